// round 1
// baseline (speedup 1.0000x reference)
#include <cuda_runtime.h>
#include <cuda_bf16.h>
#include <cstdint>

// ---------------- problem constants ----------------
#define B_TOK 8192
#define HID   4096
#define NH    32
#define NKV   8
#define HD    128
#define RBIT  128
#define QKV_C 6144
#define NC    5120   // (NH+NKV)*HD  -- v slice of proj_w is never used

// ---------------- device scratch (no cudaMalloc allowed) ----------------
__device__ __nv_bfloat16 g_Ahi[(size_t)B_TOK * HID];
__device__ __nv_bfloat16 g_Alo[(size_t)B_TOK * HID];
__device__ __nv_bfloat16 g_Bhi[(size_t)HID * NC];
__device__ __nv_bfloat16 g_Blo[(size_t)HID * NC];
__device__ float        g_C[(size_t)B_TOK * NC];

// ---------------- split kernels: fp32 -> bf16 hi + bf16 lo ----------------
__global__ void split_A_kernel(const float* __restrict__ x) {
    size_t n = (size_t)B_TOK * HID;
    for (size_t i = (size_t)blockIdx.x * blockDim.x + threadIdx.x; i < n;
         i += (size_t)gridDim.x * blockDim.x) {
        float v = x[i];
        __nv_bfloat16 h = __float2bfloat16(v);
        g_Ahi[i] = h;
        g_Alo[i] = __float2bfloat16(v - __bfloat162float(h));
    }
}

__global__ void split_B_kernel(const float* __restrict__ w) {
    size_t n = (size_t)HID * NC;
    for (size_t i = (size_t)blockIdx.x * blockDim.x + threadIdx.x; i < n;
         i += (size_t)gridDim.x * blockDim.x) {
        size_t k = i / NC;
        size_t c = i - k * NC;
        float v = w[k * QKV_C + c];   // skip unused v-projection columns
        __nv_bfloat16 h = __float2bfloat16(v);
        g_Bhi[i] = h;
        g_Blo[i] = __float2bfloat16(v - __bfloat162float(h));
    }
}

// ---------------- GEMM: C[8192,5120] = (Ahi+Alo)(Bhi+Blo) + bias ----------------
#define BM 128
#define BN 128
#define BK 32
#define LDA_S 40           // 32 + 8 pad (bf16 elems)
#define LDB_S 136          // 128 + 8 pad
#define A_ELEMS (BM * LDA_S)             // 5120
#define B_ELEMS (BK * LDB_S)             // 4352
#define STAGE_ELEMS (2 * A_ELEMS + 2 * B_ELEMS)  // 18944
#define SMEM_BYTES (2 * STAGE_ELEMS * 2)         // 75776 bytes

__device__ __forceinline__ void cp16(void* smem, const void* gmem) {
    uint32_t s = (uint32_t)__cvta_generic_to_shared(smem);
    asm volatile("cp.async.cg.shared.global [%0], [%1], 16;\n" :: "r"(s), "l"(gmem) : "memory");
}
__device__ __forceinline__ void ldm_x4(uint32_t* r, const void* p) {
    uint32_t a = (uint32_t)__cvta_generic_to_shared(p);
    asm volatile("ldmatrix.sync.aligned.m8n8.x4.shared.b16 {%0,%1,%2,%3}, [%4];\n"
        : "=r"(r[0]), "=r"(r[1]), "=r"(r[2]), "=r"(r[3]) : "r"(a));
}
__device__ __forceinline__ void ldm_x4_t(uint32_t* r, const void* p) {
    uint32_t a = (uint32_t)__cvta_generic_to_shared(p);
    asm volatile("ldmatrix.sync.aligned.m8n8.x4.trans.shared.b16 {%0,%1,%2,%3}, [%4];\n"
        : "=r"(r[0]), "=r"(r[1]), "=r"(r[2]), "=r"(r[3]) : "r"(a));
}
__device__ __forceinline__ void mma_bf16(float* d, const uint32_t* a, const uint32_t* b) {
    asm volatile("mma.sync.aligned.m16n8k16.row.col.f32.bf16.bf16.f32 "
        "{%0,%1,%2,%3}, {%4,%5,%6,%7}, {%8,%9}, {%0,%1,%2,%3};\n"
        : "+f"(d[0]), "+f"(d[1]), "+f"(d[2]), "+f"(d[3])
        : "r"(a[0]), "r"(a[1]), "r"(a[2]), "r"(a[3]), "r"(b[0]), "r"(b[1]));
}

extern __shared__ __align__(16) __nv_bfloat16 smem_buf[];

__global__ void __launch_bounds__(256, 1) gemm_split_kernel(const float* __restrict__ bias) {
    const int ti   = threadIdx.x;
    const int lane = ti & 31;
    const int warp = ti >> 5;
    const int wm = warp & 3;   // 4 warps along M -> warp tile 32 rows
    const int wn = warp >> 2;  // 2 warps along N -> warp tile 64 cols
    const int bn0 = blockIdx.x * BN;
    const int bm0 = blockIdx.y * BM;

    float acc[2][8][4];
#pragma unroll
    for (int mi = 0; mi < 2; mi++)
#pragma unroll
        for (int ni = 0; ni < 8; ni++)
#pragma unroll
            for (int r = 0; r < 4; r++) acc[mi][ni][r] = 0.f;

    auto load_stage = [&](int st, int kt) {
        __nv_bfloat16* base = smem_buf + st * STAGE_ELEMS;
        __nv_bfloat16* sAhi = base;
        __nv_bfloat16* sAlo = base + A_ELEMS;
        __nv_bfloat16* sBhi = base + 2 * A_ELEMS;
        __nv_bfloat16* sBlo = base + 2 * A_ELEMS + B_ELEMS;
#pragma unroll
        for (int j = 0; j < 2; j++) {
            int c = ti + 256 * j;
            {   // A tiles: 128 rows x 32 cols, 4 chunks/row
                int r = c >> 2, co = (c & 3) * 8;
                size_t g = (size_t)(bm0 + r) * HID + kt * BK + co;
                cp16(sAhi + r * LDA_S + co, g_Ahi + g);
                cp16(sAlo + r * LDA_S + co, g_Alo + g);
            }
            {   // B tiles: 32 rows x 128 cols, 16 chunks/row
                int r = c >> 4, co = (c & 15) * 8;
                size_t g = (size_t)(kt * BK + r) * NC + bn0 + co;
                cp16(sBhi + r * LDB_S + co, g_Bhi + g);
                cp16(sBlo + r * LDB_S + co, g_Blo + g);
            }
        }
        asm volatile("cp.async.commit_group;\n" ::: "memory");
    };

    load_stage(0, 0);
    int buf = 0;
    const int KT = HID / BK;   // 128
    for (int kt = 0; kt < KT; kt++) {
        asm volatile("cp.async.wait_group 0;\n" ::: "memory");
        __syncthreads();
        if (kt + 1 < KT) load_stage(buf ^ 1, kt + 1);

        __nv_bfloat16* base = smem_buf + buf * STAGE_ELEMS;
        __nv_bfloat16* sAhi = base;
        __nv_bfloat16* sAlo = base + A_ELEMS;
        __nv_bfloat16* sBhi = base + 2 * A_ELEMS;
        __nv_bfloat16* sBlo = base + 2 * A_ELEMS + B_ELEMS;

#pragma unroll
        for (int kk = 0; kk < 2; kk++) {
            uint32_t a_hi[2][4], a_lo[2][4], b_hi[8][2], b_lo[8][2];
#pragma unroll
            for (int mi = 0; mi < 2; mi++) {
                int row = wm * 32 + mi * 16 + (lane & 15);
                int col = kk * 16 + (lane >> 4) * 8;
                ldm_x4(a_hi[mi], sAhi + row * LDA_S + col);
                ldm_x4(a_lo[mi], sAlo + row * LDA_S + col);
            }
#pragma unroll
            for (int nj = 0; nj < 4; nj++) {
                int row = kk * 16 + (lane & 15);
                int col = wn * 64 + nj * 16 + (lane >> 4) * 8;
                ldm_x4_t(&b_hi[2 * nj][0], sBhi + row * LDB_S + col);
                ldm_x4_t(&b_lo[2 * nj][0], sBlo + row * LDB_S + col);
            }
#pragma unroll
            for (int mi = 0; mi < 2; mi++)
#pragma unroll
                for (int ni = 0; ni < 8; ni++) {
                    mma_bf16(acc[mi][ni], a_hi[mi], b_hi[ni]);
                    mma_bf16(acc[mi][ni], a_hi[mi], b_lo[ni]);
                    mma_bf16(acc[mi][ni], a_lo[mi], b_hi[ni]);
                }
        }
        buf ^= 1;
    }

    // epilogue: add bias, write fp32 C
#pragma unroll
    for (int mi = 0; mi < 2; mi++)
#pragma unroll
        for (int ni = 0; ni < 8; ni++) {
            int row = bm0 + wm * 32 + mi * 16 + (lane >> 2);
            int col = bn0 + wn * 64 + ni * 8 + (lane & 3) * 2;
            float b0 = bias[col], b1 = bias[col + 1];
            float2 v0 = make_float2(acc[mi][ni][0] + b0, acc[mi][ni][1] + b1);
            float2 v1 = make_float2(acc[mi][ni][2] + b0, acc[mi][ni][3] + b1);
            *(float2*)&g_C[(size_t)row * NC + col]       = v0;
            *(float2*)&g_C[(size_t)(row + 8) * NC + col] = v1;
        }
}

// ---------------- stage 2: attn dot, norms, tanh-hash hamming ----------------
__device__ __forceinline__ float bsum1(float v, volatile float* red) {
#pragma unroll
    for (int o = 16; o > 0; o >>= 1) v += __shfl_xor_sync(0xffffffffu, v, o);
    __syncthreads();
    if ((threadIdx.x & 31) == 0) red[threadIdx.x >> 5] = v;
    __syncthreads();
    return red[0] + red[1] + red[2] + red[3];
}
__device__ __forceinline__ void bsum3(float& a, float& b, float& c, volatile float* red) {
#pragma unroll
    for (int o = 16; o > 0; o >>= 1) {
        a += __shfl_xor_sync(0xffffffffu, a, o);
        b += __shfl_xor_sync(0xffffffffu, b, o);
        c += __shfl_xor_sync(0xffffffffu, c, o);
    }
    __syncthreads();
    int wq = threadIdx.x >> 5;
    if ((threadIdx.x & 31) == 0) { red[wq] = a; red[4 + wq] = b; red[8 + wq] = c; }
    __syncthreads();
    a = red[0] + red[1] + red[2] + red[3];
    b = red[4] + red[5] + red[6] + red[7];
    c = red[8] + red[9] + red[10] + red[11];
}

__global__ void __launch_bounds__(128) stage2_kernel(const float* __restrict__ hash_w,
                                                     float* __restrict__ out) {
    __shared__ float row[NC];
    __shared__ float kc[NKV][RBIT];
    __shared__ float kn[NKV];
    __shared__ float red[12];

    const int b = blockIdx.x;
    const int t = threadIdx.x;   // 0..127 == hash bit index

    // load full projected row for this token (5120 f32) via float4
    const float4* src = (const float4*)(g_C + (size_t)b * NC);
    float4* dst = (float4*)row;
#pragma unroll
    for (int i = 0; i < NC / 4 / 128; i++) dst[t + 128 * i] = src[t + 128 * i];

    // hash_w column t resident in registers
    float w[128];
#pragma unroll
    for (int d = 0; d < 128; d++) w[d] = hash_w[d * RBIT + t];
    __syncthreads();

    // k-head tanh codes + k norms (computed once per kv head)
#pragma unroll 1
    for (int kv = 0; kv < NKV; kv++) {
        const float* r = row + NH * HD + kv * HD;
        const float4* r4 = (const float4*)r;
        float acc = 0.f;
#pragma unroll
        for (int d4 = 0; d4 < 32; d4++) {
            float4 rv = r4[d4];
            acc = fmaf(rv.x, w[4 * d4 + 0], acc);
            acc = fmaf(rv.y, w[4 * d4 + 1], acc);
            acc = fmaf(rv.z, w[4 * d4 + 2], acc);
            acc = fmaf(rv.w, w[4 * d4 + 3], acc);
        }
        kc[kv][t] = tanhf(acc);
        float v = r[t];
        float s = bsum1(v * v, red);
        if (t == 0) kn[kv] = s;
    }
    __syncthreads();

    const float inv_sqrt_d = 0.08838834764831845f;  // 1/sqrt(128)
#pragma unroll 1
    for (int h = 0; h < NH; h++) {
        const float* q = row + h * HD;
        const float* k = row + NH * HD + (h >> 2) * HD;
        const float4* q4 = (const float4*)q;
        float acc = 0.f;
#pragma unroll
        for (int d4 = 0; d4 < 32; d4++) {
            float4 qv4 = q4[d4];
            acc = fmaf(qv4.x, w[4 * d4 + 0], acc);
            acc = fmaf(qv4.y, w[4 * d4 + 1], acc);
            acc = fmaf(qv4.z, w[4 * d4 + 2], acc);
            acc = fmaf(qv4.w, w[4 * d4 + 3], acc);
        }
        float qc  = tanhf(acc);
        float ham = fabsf(qc - kc[h >> 2][t]);   // = 2*|q_code - k_code|
        float qv  = q[t];
        float s0  = qv * k[t];    // dot partial
        float s1  = qv * qv;      // |q|^2 partial
        float s2  = ham;          // hamming partial (x0.5 folded below)
        bsum3(s0, s1, s2, red);
        if (t == 0) {
            out[(size_t)b * NH + h] = s0 * inv_sqrt_d;
            // ham_dist = 0.5*s2 ; weights = (1 - 2*ham/RBIT)*|q||k|/sqrt(D) = (1 - s2/128)*...
            float hw = (1.f - s2 * (1.f / 128.f)) * sqrtf(s1 * kn[h >> 2]) * inv_sqrt_d;
            out[(size_t)B_TOK * NH + (size_t)b * NH + h] = hw;
        }
    }
}

// ---------------- launch ----------------
extern "C" void kernel_launch(void* const* d_in, const int* in_sizes, int n_in,
                              void* d_out, int out_size) {
    const float* hidden = (const float*)d_in[0];
    const float* proj_w = (const float*)d_in[1];
    const float* proj_b = (const float*)d_in[2];
    const float* hash_w = (const float*)d_in[3];
    float* out = (float*)d_out;

    cudaFuncSetAttribute(gemm_split_kernel,
                         cudaFuncAttributeMaxDynamicSharedMemorySize, SMEM_BYTES);

    split_A_kernel<<<8192, 256>>>(hidden);
    split_B_kernel<<<8192, 256>>>(proj_w);
    gemm_split_kernel<<<dim3(NC / BN, B_TOK / BM), 256, SMEM_BYTES>>>(proj_b);
    stage2_kernel<<<B_TOK, 128>>>(hash_w, out);
}

// round 3
// speedup vs baseline: 1.0893x; 1.0893x over previous
#include <cuda_runtime.h>
#include <cuda_bf16.h>
#include <cstdint>

// ---------------- problem constants ----------------
#define B_TOK 8192
#define HID   4096
#define NH    32
#define NKV   8
#define HD    128
#define RBIT  128
#define QKV_C 6144
#define NC    5120   // (NH+NKV)*HD  -- v slice of proj_w unused

// ---------------- device scratch ----------------
__device__ __nv_bfloat16 g_Ahi[(size_t)B_TOK * HID];
__device__ __nv_bfloat16 g_Alo[(size_t)B_TOK * HID];
__device__ __nv_bfloat16 g_Bhi[(size_t)HID * NC];   // [K][N]
__device__ __nv_bfloat16 g_Blo[(size_t)HID * NC];
__device__ float        g_C[(size_t)B_TOK * NC];

// ---------------- split kernels ----------------
__global__ void split_A_kernel(const float* __restrict__ x) {
    size_t n4 = (size_t)B_TOK * HID / 4;
    for (size_t i = (size_t)blockIdx.x * blockDim.x + threadIdx.x; i < n4;
         i += (size_t)gridDim.x * blockDim.x) {
        float4 v = ((const float4*)x)[i];
        __nv_bfloat16 h0 = __float2bfloat16(v.x), h1 = __float2bfloat16(v.y);
        __nv_bfloat16 h2 = __float2bfloat16(v.z), h3 = __float2bfloat16(v.w);
        ((__nv_bfloat162*)g_Ahi)[2 * i]     = __nv_bfloat162(h0, h1);
        ((__nv_bfloat162*)g_Ahi)[2 * i + 1] = __nv_bfloat162(h2, h3);
        __nv_bfloat16 l0 = __float2bfloat16(v.x - __bfloat162float(h0));
        __nv_bfloat16 l1 = __float2bfloat16(v.y - __bfloat162float(h1));
        __nv_bfloat16 l2 = __float2bfloat16(v.z - __bfloat162float(h2));
        __nv_bfloat16 l3 = __float2bfloat16(v.w - __bfloat162float(h3));
        ((__nv_bfloat162*)g_Alo)[2 * i]     = __nv_bfloat162(l0, l1);
        ((__nv_bfloat162*)g_Alo)[2 * i + 1] = __nv_bfloat162(l2, l3);
    }
}

__global__ void split_B_kernel(const float* __restrict__ w) {
    // rows k in [0,HID), cols c in [0,NC) ; source stride QKV_C
    size_t n4 = (size_t)HID * NC / 4;
    for (size_t i = (size_t)blockIdx.x * blockDim.x + threadIdx.x; i < n4;
         i += (size_t)gridDim.x * blockDim.x) {
        size_t e = i * 4;
        size_t k = e / NC;
        size_t c = e - k * NC;
        float4 v = *(const float4*)(w + k * QKV_C + c);
        __nv_bfloat16 h0 = __float2bfloat16(v.x), h1 = __float2bfloat16(v.y);
        __nv_bfloat16 h2 = __float2bfloat16(v.z), h3 = __float2bfloat16(v.w);
        ((__nv_bfloat162*)g_Bhi)[2 * i]     = __nv_bfloat162(h0, h1);
        ((__nv_bfloat162*)g_Bhi)[2 * i + 1] = __nv_bfloat162(h2, h3);
        __nv_bfloat16 l0 = __float2bfloat16(v.x - __bfloat162float(h0));
        __nv_bfloat16 l1 = __float2bfloat16(v.y - __bfloat162float(h1));
        __nv_bfloat16 l2 = __float2bfloat16(v.z - __bfloat162float(h2));
        __nv_bfloat16 l3 = __float2bfloat16(v.w - __bfloat162float(h3));
        ((__nv_bfloat162*)g_Blo)[2 * i]     = __nv_bfloat162(l0, l1);
        ((__nv_bfloat162*)g_Blo)[2 * i + 1] = __nv_bfloat162(l2, l3);
    }
}

// ---------------- GEMM helpers ----------------
__device__ __forceinline__ void cp16(void* smem, const void* gmem) {
    uint32_t s = (uint32_t)__cvta_generic_to_shared(smem);
    asm volatile("cp.async.cg.shared.global [%0], [%1], 16;\n" :: "r"(s), "l"(gmem) : "memory");
}
__device__ __forceinline__ void ldm_x4(uint32_t* r, const void* p) {
    uint32_t a = (uint32_t)__cvta_generic_to_shared(p);
    asm volatile("ldmatrix.sync.aligned.m8n8.x4.shared.b16 {%0,%1,%2,%3}, [%4];\n"
        : "=r"(r[0]), "=r"(r[1]), "=r"(r[2]), "=r"(r[3]) : "r"(a));
}
__device__ __forceinline__ void ldm_x4_t(uint32_t* r, const void* p) {
    uint32_t a = (uint32_t)__cvta_generic_to_shared(p);
    asm volatile("ldmatrix.sync.aligned.m8n8.x4.trans.shared.b16 {%0,%1,%2,%3}, [%4];\n"
        : "=r"(r[0]), "=r"(r[1]), "=r"(r[2]), "=r"(r[3]) : "r"(a));
}
__device__ __forceinline__ void mma_bf16(float* d, const uint32_t* a, const uint32_t* b) {
    asm volatile("mma.sync.aligned.m16n8k16.row.col.f32.bf16.bf16.f32 "
        "{%0,%1,%2,%3}, {%4,%5,%6,%7}, {%8,%9}, {%0,%1,%2,%3};\n"
        : "+f"(d[0]), "+f"(d[1]), "+f"(d[2]), "+f"(d[3])
        : "r"(a[0]), "r"(a[1]), "r"(a[2]), "r"(a[3]), "r"(b[0]), "r"(b[1]));
}

// ---------------- GEMM: C[8192,5120] = (Ahi+Alo)(Bhi+Blo) + bias ----------------
#define BM 128
#define BN 128
#define BK 64
#define STAGES 3
#define LDA_E 72           // A smem row stride in bf16 elems (64 + 8 pad)
#define LDB_E 136          // B smem row stride (128 + 8 pad)
#define A_BYTES (BM * LDA_E * 2)            // 18432
#define B_BYTES (BK * LDB_E * 2)            // 17408
#define STAGE_BYTES (2 * A_BYTES + 2 * B_BYTES)  // 71680
#define SMEM_BYTES (STAGES * STAGE_BYTES)        // 215040

extern __shared__ __align__(16) char smem_raw[];

__global__ void __launch_bounds__(256, 1) gemm_split_kernel(const float* __restrict__ bias) {
    const int ti   = threadIdx.x;
    const int lane = ti & 31;
    const int warp = ti >> 5;
    const int wm = warp & 3;   // 4 warps along M, 32 rows each
    const int wn = warp >> 2;  // 2 warps along N, 64 cols each
    const int bn0 = blockIdx.x * BN;
    const int bm0 = blockIdx.y * BM;

    __shared__ float s_bias[BN];
    for (int i = ti; i < BN; i += 256) s_bias[i] = bias[bn0 + i];

    float acc[2][8][4];
#pragma unroll
    for (int mi = 0; mi < 2; mi++)
#pragma unroll
        for (int ni = 0; ni < 8; ni++)
#pragma unroll
            for (int r = 0; r < 4; r++) acc[mi][ni][r] = 0.f;

    auto load_stage = [&](int st, int kt) {
        char* base = smem_raw + st * STAGE_BYTES;
        char* sAhi = base;
        char* sAlo = base + A_BYTES;
        char* sBhi = base + 2 * A_BYTES;
        char* sBlo = base + 2 * A_BYTES + B_BYTES;
#pragma unroll
        for (int i = 0; i < 4; i++) {     // A: 128 rows x 64 cols -> 1024 chunks
            int c = ti + 256 * i;
            int r = c >> 3, cc = c & 7;
            size_t g = (size_t)(bm0 + r) * HID + (size_t)kt * BK + cc * 8;
            int so = r * (LDA_E * 2) + cc * 16;
            cp16(sAhi + so, g_Ahi + g);
            cp16(sAlo + so, g_Alo + g);
        }
#pragma unroll
        for (int i = 0; i < 4; i++) {     // B: 64 rows x 128 cols -> 1024 chunks
            int c = ti + 256 * i;
            int r = c >> 4, cc = c & 15;
            size_t g = (size_t)(kt * BK + r) * NC + bn0 + cc * 8;
            int so = r * (LDB_E * 2) + cc * 16;
            cp16(sBhi + so, g_Bhi + g);
            cp16(sBlo + so, g_Blo + g);
        }
        asm volatile("cp.async.commit_group;\n" ::: "memory");
    };

    const int KT = HID / BK;   // 64
    load_stage(0, 0);
    load_stage(1, 1);

    for (int kt = 0; kt < KT; kt++) {
        asm volatile("cp.async.wait_group 1;\n" ::: "memory");
        __syncthreads();
        if (kt + 2 < KT) load_stage((kt + 2) % STAGES, kt + 2);

        char* base = smem_raw + (kt % STAGES) * STAGE_BYTES;
        char* sAhi = base;
        char* sAlo = base + A_BYTES;
        char* sBhi = base + 2 * A_BYTES;
        char* sBlo = base + 2 * A_BYTES + B_BYTES;

#pragma unroll
        for (int kk = 0; kk < 4; kk++) {   // BK=64 -> 4 k16 steps
            uint32_t a_hi[2][4], a_lo[2][4], b_hi[8][2], b_lo[8][2];
#pragma unroll
            for (int mi = 0; mi < 2; mi++) {
                int row = wm * 32 + mi * 16 + (lane & 15);
                int col = kk * 16 + (lane >> 4) * 8;
                ldm_x4(a_hi[mi], sAhi + row * (LDA_E * 2) + col * 2);
                ldm_x4(a_lo[mi], sAlo + row * (LDA_E * 2) + col * 2);
            }
#pragma unroll
            for (int nj = 0; nj < 4; nj++) {
                int row = kk * 16 + (lane & 15);
                int col = wn * 64 + nj * 16 + (lane >> 4) * 8;
                ldm_x4_t(&b_hi[2 * nj][0], sBhi + row * (LDB_E * 2) + col * 2);
                ldm_x4_t(&b_lo[2 * nj][0], sBlo + row * (LDB_E * 2) + col * 2);
            }
#pragma unroll
            for (int mi = 0; mi < 2; mi++)
#pragma unroll
                for (int ni = 0; ni < 8; ni++) {
                    mma_bf16(acc[mi][ni], a_hi[mi], b_hi[ni]);
                    mma_bf16(acc[mi][ni], a_hi[mi], b_lo[ni]);
                    mma_bf16(acc[mi][ni], a_lo[mi], b_hi[ni]);
                }
        }
    }

    // epilogue: add bias, write fp32 C
#pragma unroll
    for (int mi = 0; mi < 2; mi++)
#pragma unroll
        for (int ni = 0; ni < 8; ni++) {
            int row = bm0 + wm * 32 + mi * 16 + (lane >> 2);
            int col = bn0 + wn * 64 + ni * 8 + (lane & 3) * 2;
            float b0 = s_bias[col - bn0], b1 = s_bias[col - bn0 + 1];
            float2 v0 = make_float2(acc[mi][ni][0] + b0, acc[mi][ni][1] + b1);
            float2 v1 = make_float2(acc[mi][ni][2] + b0, acc[mi][ni][3] + b1);
            *(float2*)&g_C[(size_t)row * NC + col]       = v0;
            *(float2*)&g_C[(size_t)(row + 8) * NC + col] = v1;
        }
}

// ---------------- stage 2: attn dot, norms, tanh-hash hamming ----------------
#define G2 4   // tokens per block, processed in pairs

__device__ __forceinline__ float wsum(float v) {
#pragma unroll
    for (int o = 16; o > 0; o >>= 1) v += __shfl_xor_sync(0xffffffffu, v, o);
    return v;
}

__global__ void __launch_bounds__(128) stage2_kernel(const float* __restrict__ hash_w,
                                                     float* __restrict__ out) {
    __shared__ float row[2][NC];
    __shared__ float kc[2][NKV][RBIT];
    __shared__ float kn[2][NKV];
    __shared__ float red[96];

    const int t = threadIdx.x;       // hash bit index 0..127
    const int lane = t & 31;
    const int wq = t >> 5;
    const float inv_sqrt_d = 0.08838834764831845f;

    float w[128];
#pragma unroll
    for (int d = 0; d < 128; d++) w[d] = hash_w[d * RBIT + t];

#pragma unroll 1
    for (int g = 0; g < G2; g += 2) {
        const int b0 = blockIdx.x * G2 + g;
        __syncthreads();   // protect smem reuse across pairs
        {
            const float4* s0 = (const float4*)(g_C + (size_t)b0 * NC);
            const float4* s1 = (const float4*)(g_C + (size_t)(b0 + 1) * NC);
            float4* d0 = (float4*)row[0];
            float4* d1 = (float4*)row[1];
#pragma unroll
            for (int i = 0; i < NC / 4 / 128; i++) {
                d0[t + 128 * i] = s0[t + 128 * i];
                d1[t + 128 * i] = s1[t + 128 * i];
            }
        }
        __syncthreads();

        // ---- k codes + k norms ----
#pragma unroll 1
        for (int kv = 0; kv < NKV; kv++) {
            const float* r0 = row[0] + NH * HD + kv * HD;
            const float* r1 = row[1] + NH * HD + kv * HD;
            const float4* r40 = (const float4*)r0;
            const float4* r41 = (const float4*)r1;
            float a0 = 0.f, a1 = 0.f;
#pragma unroll
            for (int d4 = 0; d4 < 32; d4++) {
                float4 u = r40[d4], v = r41[d4];
                a0 = fmaf(u.x, w[4 * d4 + 0], a0); a1 = fmaf(v.x, w[4 * d4 + 0], a1);
                a0 = fmaf(u.y, w[4 * d4 + 1], a0); a1 = fmaf(v.y, w[4 * d4 + 1], a1);
                a0 = fmaf(u.z, w[4 * d4 + 2], a0); a1 = fmaf(v.z, w[4 * d4 + 2], a1);
                a0 = fmaf(u.w, w[4 * d4 + 3], a0); a1 = fmaf(v.w, w[4 * d4 + 3], a1);
            }
            kc[0][kv][t] = tanhf(a0);
            kc[1][kv][t] = tanhf(a1);
            float x0 = r0[t], x1 = r1[t];
            float p0 = wsum(x0 * x0), p1 = wsum(x1 * x1);
            if (lane == 0) {
                red[(2 * kv + 0) * 4 + wq] = p0;
                red[(2 * kv + 1) * 4 + wq] = p1;
            }
        }
        __syncthreads();
        if (t < 16) {
            int kv = t >> 1, tok = t & 1;
            int s = (2 * kv + tok) * 4;
            kn[tok][kv] = red[s] + red[s + 1] + red[s + 2] + red[s + 3];
        }
        __syncthreads();

        // ---- q heads, 4 per sync round ----
#pragma unroll 1
        for (int hg = 0; hg < 8; hg++) {
#pragma unroll
            for (int i = 0; i < 4; i++) {
                const int h = hg * 4 + i;
                const float* q0 = row[0] + h * HD;
                const float* q1 = row[1] + h * HD;
                const float* k0 = row[0] + NH * HD + (h >> 2) * HD;
                const float* k1 = row[1] + NH * HD + (h >> 2) * HD;
                const float4* q40 = (const float4*)q0;
                const float4* q41 = (const float4*)q1;
                float a0 = 0.f, a1 = 0.f;
#pragma unroll
                for (int d4 = 0; d4 < 32; d4++) {
                    float4 u = q40[d4], v = q41[d4];
                    a0 = fmaf(u.x, w[4 * d4 + 0], a0); a1 = fmaf(v.x, w[4 * d4 + 0], a1);
                    a0 = fmaf(u.y, w[4 * d4 + 1], a0); a1 = fmaf(v.y, w[4 * d4 + 1], a1);
                    a0 = fmaf(u.z, w[4 * d4 + 2], a0); a1 = fmaf(v.z, w[4 * d4 + 2], a1);
                    a0 = fmaf(u.w, w[4 * d4 + 3], a0); a1 = fmaf(v.w, w[4 * d4 + 3], a1);
                }
                float ham0 = fabsf(tanhf(a0) - kc[0][h >> 2][t]);
                float ham1 = fabsf(tanhf(a1) - kc[1][h >> 2][t]);
                float qv0 = q0[t], qv1 = q1[t];
                float d0 = wsum(qv0 * k0[t]);
                float n0 = wsum(qv0 * qv0);
                float m0 = wsum(ham0);
                float d1 = wsum(qv1 * k1[t]);
                float n1 = wsum(qv1 * qv1);
                float m1 = wsum(ham1);
                if (lane == 0) {
                    int s0 = (i * 2 + 0) * 3, s1 = (i * 2 + 1) * 3;
                    red[(s0 + 0) * 4 + wq] = d0;
                    red[(s0 + 1) * 4 + wq] = n0;
                    red[(s0 + 2) * 4 + wq] = m0;
                    red[(s1 + 0) * 4 + wq] = d1;
                    red[(s1 + 1) * 4 + wq] = n1;
                    red[(s1 + 2) * 4 + wq] = m1;
                }
            }
            __syncthreads();
            if (t < 8) {
                int i = t >> 1, tok = t & 1;
                int h = hg * 4 + i;
                int bb = b0 + tok;
                int base = (i * 2 + tok) * 3;
                float dot = red[(base + 0) * 4] + red[(base + 0) * 4 + 1] +
                            red[(base + 0) * 4 + 2] + red[(base + 0) * 4 + 3];
                float qn  = red[(base + 1) * 4] + red[(base + 1) * 4 + 1] +
                            red[(base + 1) * 4 + 2] + red[(base + 1) * 4 + 3];
                float hm  = red[(base + 2) * 4] + red[(base + 2) * 4 + 1] +
                            red[(base + 2) * 4 + 2] + red[(base + 2) * 4 + 3];
                out[(size_t)bb * NH + h] = dot * inv_sqrt_d;
                float hw = (1.f - hm * (1.f / 128.f)) *
                           sqrtf(qn * kn[tok][h >> 2]) * inv_sqrt_d;
                out[(size_t)B_TOK * NH + (size_t)bb * NH + h] = hw;
            }
            __syncthreads();
        }
    }
}

// ---------------- launch ----------------
extern "C" void kernel_launch(void* const* d_in, const int* in_sizes, int n_in,
                              void* d_out, int out_size) {
    const float* hidden = (const float*)d_in[0];
    const float* proj_w = (const float*)d_in[1];
    const float* proj_b = (const float*)d_in[2];
    const float* hash_w = (const float*)d_in[3];
    float* out = (float*)d_out;

    cudaFuncSetAttribute(gemm_split_kernel,
                         cudaFuncAttributeMaxDynamicSharedMemorySize, SMEM_BYTES);

    split_A_kernel<<<4096, 256>>>(hidden);
    split_B_kernel<<<4096, 256>>>(proj_w);
    gemm_split_kernel<<<dim3(NC / BN, B_TOK / BM), 256, SMEM_BYTES>>>(proj_b);
    stage2_kernel<<<B_TOK / G2, 128>>>(hash_w, out);
}

// round 4
// speedup vs baseline: 1.4471x; 1.3285x over previous
#include <cuda_runtime.h>
#include <cuda_fp16.h>
#include <cstdint>

// ---------------- problem constants ----------------
#define B_TOK 8192
#define HID   4096
#define NH    32
#define NKV   8
#define HD    128
#define RBIT  128
#define QKV_C 6144
#define NC    5120   // (NH+NKV)*HD  -- v slice of proj_w unused

// ---------------- device scratch ----------------
__device__ __half g_A16[(size_t)B_TOK * HID];
__device__ __half g_Bhi[(size_t)HID * NC];   // [K][N]
__device__ __half g_Blo[(size_t)HID * NC];
__device__ float  g_C[(size_t)B_TOK * NC];

// ---------------- split kernels ----------------
__global__ void split_A_kernel(const float* __restrict__ x) {
    size_t n4 = (size_t)B_TOK * HID / 4;
    for (size_t i = (size_t)blockIdx.x * blockDim.x + threadIdx.x; i < n4;
         i += (size_t)gridDim.x * blockDim.x) {
        float4 v = ((const float4*)x)[i];
        __half2* dst = (__half2*)g_A16;
        dst[2 * i]     = __floats2half2_rn(v.x, v.y);
        dst[2 * i + 1] = __floats2half2_rn(v.z, v.w);
    }
}

__global__ void split_B_kernel(const float* __restrict__ w) {
    size_t n4 = (size_t)HID * NC / 4;
    for (size_t i = (size_t)blockIdx.x * blockDim.x + threadIdx.x; i < n4;
         i += (size_t)gridDim.x * blockDim.x) {
        size_t e = i * 4;
        size_t k = e / NC;
        size_t c = e - k * NC;
        float4 v = *(const float4*)(w + k * QKV_C + c);
        __half h0 = __float2half_rn(v.x), h1 = __float2half_rn(v.y);
        __half h2 = __float2half_rn(v.z), h3 = __float2half_rn(v.w);
        ((__half2*)g_Bhi)[2 * i]     = __half2(h0, h1);
        ((__half2*)g_Bhi)[2 * i + 1] = __half2(h2, h3);
        __half l0 = __float2half_rn(v.x - __half2float(h0));
        __half l1 = __float2half_rn(v.y - __half2float(h1));
        __half l2 = __float2half_rn(v.z - __half2float(h2));
        __half l3 = __float2half_rn(v.w - __half2float(h3));
        ((__half2*)g_Blo)[2 * i]     = __half2(l0, l1);
        ((__half2*)g_Blo)[2 * i + 1] = __half2(l2, l3);
    }
}

// ---------------- GEMM helpers ----------------
__device__ __forceinline__ void cp16(void* smem, const void* gmem) {
    uint32_t s = (uint32_t)__cvta_generic_to_shared(smem);
    asm volatile("cp.async.cg.shared.global [%0], [%1], 16;\n" :: "r"(s), "l"(gmem) : "memory");
}
__device__ __forceinline__ void ldm_x4(uint32_t* r, const void* p) {
    uint32_t a = (uint32_t)__cvta_generic_to_shared(p);
    asm volatile("ldmatrix.sync.aligned.m8n8.x4.shared.b16 {%0,%1,%2,%3}, [%4];\n"
        : "=r"(r[0]), "=r"(r[1]), "=r"(r[2]), "=r"(r[3]) : "r"(a));
}
__device__ __forceinline__ void ldm_x4_t(uint32_t* r, const void* p) {
    uint32_t a = (uint32_t)__cvta_generic_to_shared(p);
    asm volatile("ldmatrix.sync.aligned.m8n8.x4.trans.shared.b16 {%0,%1,%2,%3}, [%4];\n"
        : "=r"(r[0]), "=r"(r[1]), "=r"(r[2]), "=r"(r[3]) : "r"(a));
}
__device__ __forceinline__ void mma_f16(float* d, const uint32_t* a, const uint32_t* b) {
    asm volatile("mma.sync.aligned.m16n8k16.row.col.f32.f16.f16.f32 "
        "{%0,%1,%2,%3}, {%4,%5,%6,%7}, {%8,%9}, {%0,%1,%2,%3};\n"
        : "+f"(d[0]), "+f"(d[1]), "+f"(d[2]), "+f"(d[3])
        : "r"(a[0]), "r"(a[1]), "r"(a[2]), "r"(a[3]), "r"(b[0]), "r"(b[1]));
}

// ---------------- GEMM: C[8192,5120] = A16 * (Bhi+Blo) + bias ----------------
#define BM 128
#define BN 256
#define BK 32
#define STAGES 5
#define LDA_H 40            // fp16 elems per A smem row (32 + 8 pad)
#define LDB_H 264           // fp16 elems per B smem row (256 + 8 pad)
#define A_BYTES (BM * LDA_H * 2)            // 10240
#define B_BYTES (BK * LDB_H * 2)            // 16896
#define STAGE_BYTES (A_BYTES + 2 * B_BYTES) // 44032
#define SMEM_BYTES (STAGES * STAGE_BYTES)   // 220160

extern __shared__ __align__(16) char smem_raw[];

__global__ void __launch_bounds__(256, 1) gemm_f16_kernel(const float* __restrict__ bias) {
    const int ti   = threadIdx.x;
    const int lane = ti & 31;
    const int warp = ti >> 5;
    const int wm = warp >> 2;   // 2 warps along M, 64 rows each
    const int wn = warp & 3;    // 4 warps along N, 64 cols each
    const int bn0 = blockIdx.x * BN;
    const int bm0 = blockIdx.y * BM;

    __shared__ float s_bias[BN];
    for (int i = ti; i < BN; i += 256) s_bias[i] = bias[bn0 + i];

    float acc[4][8][4];
#pragma unroll
    for (int mi = 0; mi < 4; mi++)
#pragma unroll
        for (int ni = 0; ni < 8; ni++)
#pragma unroll
            for (int r = 0; r < 4; r++) acc[mi][ni][r] = 0.f;

    auto load_stage = [&](int st, int kt) {
        char* base = smem_raw + st * STAGE_BYTES;
        char* sA   = base;
        char* sBhi = base + A_BYTES;
        char* sBlo = base + A_BYTES + B_BYTES;
#pragma unroll
        for (int i = 0; i < 2; i++) {     // A: 128 rows x 32 cols = 512 chunks
            int c = ti + 256 * i;
            int r = c >> 2, cc = c & 3;
            size_t g = (size_t)(bm0 + r) * HID + (size_t)kt * BK + cc * 8;
            cp16(sA + r * (LDA_H * 2) + cc * 16, g_A16 + g);
        }
#pragma unroll
        for (int i = 0; i < 4; i++) {     // B: 32 rows x 256 cols = 1024 chunks each
            int c = ti + 256 * i;
            int r = c >> 5, cc = c & 31;
            size_t g = (size_t)(kt * BK + r) * NC + bn0 + cc * 8;
            int so = r * (LDB_H * 2) + cc * 16;
            cp16(sBhi + so, g_Bhi + g);
            cp16(sBlo + so, g_Blo + g);
        }
        asm volatile("cp.async.commit_group;\n" ::: "memory");
    };

    const int KT = HID / BK;   // 128
    load_stage(0, 0);
    load_stage(1, 1);
    load_stage(2, 2);
    load_stage(3, 3);

    for (int kt = 0; kt < KT; kt++) {
        asm volatile("cp.async.wait_group 3;\n" ::: "memory");
        __syncthreads();
        if (kt + 4 < KT) load_stage((kt + 4) % STAGES, kt + 4);
        else asm volatile("cp.async.commit_group;\n" ::: "memory");  // keep count uniform

        char* base = smem_raw + (kt % STAGES) * STAGE_BYTES;
        char* sA   = base;
        char* sBhi = base + A_BYTES;
        char* sBlo = base + A_BYTES + B_BYTES;

#pragma unroll
        for (int kk = 0; kk < 2; kk++) {   // BK=32 -> 2 k16 steps
            uint32_t a[4][4], bh[8][2], bl[8][2];
#pragma unroll
            for (int mi = 0; mi < 4; mi++) {
                int row = wm * 64 + mi * 16 + (lane & 15);
                int col = kk * 16 + (lane >> 4) * 8;
                ldm_x4(a[mi], sA + row * (LDA_H * 2) + col * 2);
            }
#pragma unroll
            for (int nj = 0; nj < 4; nj++) {
                int row = kk * 16 + (lane & 15);
                int col = wn * 64 + nj * 16 + (lane >> 4) * 8;
                ldm_x4_t(&bh[2 * nj][0], sBhi + row * (LDB_H * 2) + col * 2);
                ldm_x4_t(&bl[2 * nj][0], sBlo + row * (LDB_H * 2) + col * 2);
            }
#pragma unroll
            for (int mi = 0; mi < 4; mi++)
#pragma unroll
                for (int ni = 0; ni < 8; ni++) {
                    mma_f16(acc[mi][ni], a[mi], bh[ni]);
                    mma_f16(acc[mi][ni], a[mi], bl[ni]);
                }
        }
    }

    // epilogue: add bias, write fp32 C
#pragma unroll
    for (int mi = 0; mi < 4; mi++)
#pragma unroll
        for (int ni = 0; ni < 8; ni++) {
            int row = bm0 + wm * 64 + mi * 16 + (lane >> 2);
            int col = bn0 + wn * 64 + ni * 8 + (lane & 3) * 2;
            float b0 = s_bias[col - bn0], b1 = s_bias[col - bn0 + 1];
            float2 v0 = make_float2(acc[mi][ni][0] + b0, acc[mi][ni][1] + b1);
            float2 v1 = make_float2(acc[mi][ni][2] + b0, acc[mi][ni][3] + b1);
            *(float2*)&g_C[(size_t)row * NC + col]       = v0;
            *(float2*)&g_C[(size_t)(row + 8) * NC + col] = v1;
        }
}

// ---------------- stage 2: attn dot, norms, tanh-hash hamming ----------------
#define G2 4   // tokens per block, processed in pairs

__device__ __forceinline__ float wsum(float v) {
#pragma unroll
    for (int o = 16; o > 0; o >>= 1) v += __shfl_xor_sync(0xffffffffu, v, o);
    return v;
}

__global__ void __launch_bounds__(128) stage2_kernel(const float* __restrict__ hash_w,
                                                     float* __restrict__ out) {
    __shared__ float row[2][NC];
    __shared__ float kc[2][NKV][RBIT];
    __shared__ float kn[2][NKV];
    __shared__ float red[96];

    const int t = threadIdx.x;       // hash bit index 0..127
    const int lane = t & 31;
    const int wq = t >> 5;
    const float inv_sqrt_d = 0.08838834764831845f;

    float w[128];
#pragma unroll
    for (int d = 0; d < 128; d++) w[d] = hash_w[d * RBIT + t];

#pragma unroll 1
    for (int g = 0; g < G2; g += 2) {
        const int b0 = blockIdx.x * G2 + g;
        __syncthreads();   // protect smem reuse across pairs
        {
            const float4* s0 = (const float4*)(g_C + (size_t)b0 * NC);
            const float4* s1 = (const float4*)(g_C + (size_t)(b0 + 1) * NC);
            float4* d0 = (float4*)row[0];
            float4* d1 = (float4*)row[1];
#pragma unroll
            for (int i = 0; i < NC / 4 / 128; i++) {
                d0[t + 128 * i] = s0[t + 128 * i];
                d1[t + 128 * i] = s1[t + 128 * i];
            }
        }
        __syncthreads();

        // ---- k codes + k norms ----
#pragma unroll 1
        for (int kv = 0; kv < NKV; kv++) {
            const float* r0 = row[0] + NH * HD + kv * HD;
            const float* r1 = row[1] + NH * HD + kv * HD;
            const float4* r40 = (const float4*)r0;
            const float4* r41 = (const float4*)r1;
            float a0 = 0.f, a1 = 0.f;
#pragma unroll
            for (int d4 = 0; d4 < 32; d4++) {
                float4 u = r40[d4], v = r41[d4];
                a0 = fmaf(u.x, w[4 * d4 + 0], a0); a1 = fmaf(v.x, w[4 * d4 + 0], a1);
                a0 = fmaf(u.y, w[4 * d4 + 1], a0); a1 = fmaf(v.y, w[4 * d4 + 1], a1);
                a0 = fmaf(u.z, w[4 * d4 + 2], a0); a1 = fmaf(v.z, w[4 * d4 + 2], a1);
                a0 = fmaf(u.w, w[4 * d4 + 3], a0); a1 = fmaf(v.w, w[4 * d4 + 3], a1);
            }
            kc[0][kv][t] = tanhf(a0);
            kc[1][kv][t] = tanhf(a1);
            float x0 = r0[t], x1 = r1[t];
            float p0 = wsum(x0 * x0), p1 = wsum(x1 * x1);
            if (lane == 0) {
                red[(2 * kv + 0) * 4 + wq] = p0;
                red[(2 * kv + 1) * 4 + wq] = p1;
            }
        }
        __syncthreads();
        if (t < 16) {
            int kv = t >> 1, tok = t & 1;
            int s = (2 * kv + tok) * 4;
            kn[tok][kv] = red[s] + red[s + 1] + red[s + 2] + red[s + 3];
        }
        __syncthreads();

        // ---- q heads, 4 per sync round ----
#pragma unroll 1
        for (int hg = 0; hg < 8; hg++) {
#pragma unroll
            for (int i = 0; i < 4; i++) {
                const int h = hg * 4 + i;
                const float* q0 = row[0] + h * HD;
                const float* q1 = row[1] + h * HD;
                const float* k0 = row[0] + NH * HD + (h >> 2) * HD;
                const float* k1 = row[1] + NH * HD + (h >> 2) * HD;
                const float4* q40 = (const float4*)q0;
                const float4* q41 = (const float4*)q1;
                float a0 = 0.f, a1 = 0.f;
#pragma unroll
                for (int d4 = 0; d4 < 32; d4++) {
                    float4 u = q40[d4], v = q41[d4];
                    a0 = fmaf(u.x, w[4 * d4 + 0], a0); a1 = fmaf(v.x, w[4 * d4 + 0], a1);
                    a0 = fmaf(u.y, w[4 * d4 + 1], a0); a1 = fmaf(v.y, w[4 * d4 + 1], a1);
                    a0 = fmaf(u.z, w[4 * d4 + 2], a0); a1 = fmaf(v.z, w[4 * d4 + 2], a1);
                    a0 = fmaf(u.w, w[4 * d4 + 3], a0); a1 = fmaf(v.w, w[4 * d4 + 3], a1);
                }
                float ham0 = fabsf(tanhf(a0) - kc[0][h >> 2][t]);
                float ham1 = fabsf(tanhf(a1) - kc[1][h >> 2][t]);
                float qv0 = q0[t], qv1 = q1[t];
                float d0 = wsum(qv0 * k0[t]);
                float n0 = wsum(qv0 * qv0);
                float m0 = wsum(ham0);
                float d1 = wsum(qv1 * k1[t]);
                float n1 = wsum(qv1 * qv1);
                float m1 = wsum(ham1);
                if (lane == 0) {
                    int s0 = (i * 2 + 0) * 3, s1 = (i * 2 + 1) * 3;
                    red[(s0 + 0) * 4 + wq] = d0;
                    red[(s0 + 1) * 4 + wq] = n0;
                    red[(s0 + 2) * 4 + wq] = m0;
                    red[(s1 + 0) * 4 + wq] = d1;
                    red[(s1 + 1) * 4 + wq] = n1;
                    red[(s1 + 2) * 4 + wq] = m1;
                }
            }
            __syncthreads();
            if (t < 8) {
                int i = t >> 1, tok = t & 1;
                int h = hg * 4 + i;
                int bb = b0 + tok;
                int base = (i * 2 + tok) * 3;
                float dot = red[(base + 0) * 4] + red[(base + 0) * 4 + 1] +
                            red[(base + 0) * 4 + 2] + red[(base + 0) * 4 + 3];
                float qn  = red[(base + 1) * 4] + red[(base + 1) * 4 + 1] +
                            red[(base + 1) * 4 + 2] + red[(base + 1) * 4 + 3];
                float hm  = red[(base + 2) * 4] + red[(base + 2) * 4 + 1] +
                            red[(base + 2) * 4 + 2] + red[(base + 2) * 4 + 3];
                out[(size_t)bb * NH + h] = dot * inv_sqrt_d;
                float hw = (1.f - hm * (1.f / 128.f)) *
                           sqrtf(qn * kn[tok][h >> 2]) * inv_sqrt_d;
                out[(size_t)B_TOK * NH + (size_t)bb * NH + h] = hw;
            }
            __syncthreads();
        }
    }
}

// ---------------- launch ----------------
extern "C" void kernel_launch(void* const* d_in, const int* in_sizes, int n_in,
                              void* d_out, int out_size) {
    const float* hidden = (const float*)d_in[0];
    const float* proj_w = (const float*)d_in[1];
    const float* proj_b = (const float*)d_in[2];
    const float* hash_w = (const float*)d_in[3];
    float* out = (float*)d_out;

    cudaFuncSetAttribute(gemm_f16_kernel,
                         cudaFuncAttributeMaxDynamicSharedMemorySize, SMEM_BYTES);

    split_A_kernel<<<2048, 256>>>(hidden);
    split_B_kernel<<<2048, 256>>>(proj_w);
    gemm_f16_kernel<<<dim3(NC / BN, B_TOK / BM), 256, SMEM_BYTES>>>(proj_b);
    stage2_kernel<<<B_TOK / G2, 128>>>(hash_w, out);
}

// round 5
// speedup vs baseline: 2.2733x; 1.5709x over previous
#include <cuda_runtime.h>
#include <cuda_fp16.h>
#include <cstdint>

// ---------------- problem constants ----------------
#define B_TOK 8192
#define HID   4096
#define NH    32
#define NKV   8
#define HD    128
#define RBIT  128
#define QKV_C 6144
#define NC    5120   // (NH+NKV)*HD  -- v slice of proj_w unused

// ---------------- device scratch ----------------
__device__ __half g_A16[(size_t)B_TOK * HID];
__device__ __half g_B16[(size_t)HID * NC];   // [K][N]
__device__ float  g_C[(size_t)B_TOK * NC];

// ---------------- convert kernels ----------------
__global__ void split_A_kernel(const float* __restrict__ x) {
    size_t n4 = (size_t)B_TOK * HID / 4;
    for (size_t i = (size_t)blockIdx.x * blockDim.x + threadIdx.x; i < n4;
         i += (size_t)gridDim.x * blockDim.x) {
        float4 v = ((const float4*)x)[i];
        __half2* dst = (__half2*)g_A16;
        dst[2 * i]     = __floats2half2_rn(v.x, v.y);
        dst[2 * i + 1] = __floats2half2_rn(v.z, v.w);
    }
}

__global__ void split_B_kernel(const float* __restrict__ w) {
    size_t n4 = (size_t)HID * NC / 4;
    for (size_t i = (size_t)blockIdx.x * blockDim.x + threadIdx.x; i < n4;
         i += (size_t)gridDim.x * blockDim.x) {
        size_t e = i * 4;
        size_t k = e / NC;
        size_t c = e - k * NC;
        float4 v = *(const float4*)(w + k * QKV_C + c);
        __half2* dst = (__half2*)g_B16;
        dst[2 * i]     = __floats2half2_rn(v.x, v.y);
        dst[2 * i + 1] = __floats2half2_rn(v.z, v.w);
    }
}

// ---------------- GEMM helpers ----------------
__device__ __forceinline__ void cp16(void* smem, const void* gmem) {
    uint32_t s = (uint32_t)__cvta_generic_to_shared(smem);
    asm volatile("cp.async.cg.shared.global [%0], [%1], 16;\n" :: "r"(s), "l"(gmem) : "memory");
}
__device__ __forceinline__ void ldm_x4(uint32_t* r, const void* p) {
    uint32_t a = (uint32_t)__cvta_generic_to_shared(p);
    asm volatile("ldmatrix.sync.aligned.m8n8.x4.shared.b16 {%0,%1,%2,%3}, [%4];\n"
        : "=r"(r[0]), "=r"(r[1]), "=r"(r[2]), "=r"(r[3]) : "r"(a));
}
__device__ __forceinline__ void ldm_x4_t(uint32_t* r, const void* p) {
    uint32_t a = (uint32_t)__cvta_generic_to_shared(p);
    asm volatile("ldmatrix.sync.aligned.m8n8.x4.trans.shared.b16 {%0,%1,%2,%3}, [%4];\n"
        : "=r"(r[0]), "=r"(r[1]), "=r"(r[2]), "=r"(r[3]) : "r"(a));
}
__device__ __forceinline__ void mma_f16(float* d, const uint32_t* a, const uint32_t* b) {
    asm volatile("mma.sync.aligned.m16n8k16.row.col.f32.f16.f16.f32 "
        "{%0,%1,%2,%3}, {%4,%5,%6,%7}, {%8,%9}, {%0,%1,%2,%3};\n"
        : "+f"(d[0]), "+f"(d[1]), "+f"(d[2]), "+f"(d[3])
        : "r"(a[0]), "r"(a[1]), "r"(a[2]), "r"(a[3]), "r"(b[0]), "r"(b[1]));
}

// ---------------- GEMM: C[8192,5120] = A16 * B16 + bias ----------------
#define BM 128
#define BN 256
#define BK 64
#define STAGES 4
#define LDA_H 72            // fp16 elems per A smem row (64 + 8 pad)
#define LDB_H 264           // fp16 elems per B smem row (256 + 8 pad)
#define A_BYTES (BM * LDA_H * 2)            // 18432
#define B_BYTES (BK * LDB_H * 2)            // 33792
#define STAGE_BYTES (A_BYTES + B_BYTES)     // 52224
#define SMEM_BYTES (STAGES * STAGE_BYTES)   // 208896

extern __shared__ __align__(16) char smem_raw[];

__global__ void __launch_bounds__(256, 1) gemm_f16_kernel(const float* __restrict__ bias) {
    const int ti   = threadIdx.x;
    const int lane = ti & 31;
    const int warp = ti >> 5;
    const int wm = warp >> 2;   // 2 warps along M, 64 rows each
    const int wn = warp & 3;    // 4 warps along N, 64 cols each
    const int bn0 = blockIdx.x * BN;
    const int bm0 = blockIdx.y * BM;

    __shared__ float s_bias[BN];
    for (int i = ti; i < BN; i += 256) s_bias[i] = bias[bn0 + i];

    float acc[4][8][4];
#pragma unroll
    for (int mi = 0; mi < 4; mi++)
#pragma unroll
        for (int ni = 0; ni < 8; ni++)
#pragma unroll
            for (int r = 0; r < 4; r++) acc[mi][ni][r] = 0.f;

    auto load_stage = [&](int st, int kt) {
        char* base = smem_raw + st * STAGE_BYTES;
        char* sA   = base;
        char* sB   = base + A_BYTES;
#pragma unroll
        for (int i = 0; i < 4; i++) {     // A: 128 rows x 64 cols = 1024 chunks
            int c = ti + 256 * i;
            int r = c >> 3, cc = c & 7;
            size_t g = (size_t)(bm0 + r) * HID + (size_t)kt * BK + cc * 8;
            cp16(sA + r * (LDA_H * 2) + cc * 16, g_A16 + g);
        }
#pragma unroll
        for (int i = 0; i < 8; i++) {     // B: 64 rows x 256 cols = 2048 chunks
            int c = ti + 256 * i;
            int r = c >> 5, cc = c & 31;
            size_t g = (size_t)(kt * BK + r) * NC + bn0 + cc * 8;
            cp16(sB + r * (LDB_H * 2) + cc * 16, g_B16 + g);
        }
        asm volatile("cp.async.commit_group;\n" ::: "memory");
    };

    const int KT = HID / BK;   // 64
    load_stage(0, 0);
    load_stage(1, 1);
    load_stage(2, 2);

    for (int kt = 0; kt < KT; kt++) {
        asm volatile("cp.async.wait_group 2;\n" ::: "memory");
        __syncthreads();
        if (kt + 3 < KT) load_stage((kt + 3) % STAGES, kt + 3);
        else asm volatile("cp.async.commit_group;\n" ::: "memory");  // keep count uniform

        char* base = smem_raw + (kt % STAGES) * STAGE_BYTES;
        char* sA   = base;
        char* sB   = base + A_BYTES;

#pragma unroll
        for (int kk = 0; kk < 4; kk++) {   // BK=64 -> 4 k16 steps
            uint32_t a[4][4], b[8][2];
#pragma unroll
            for (int mi = 0; mi < 4; mi++) {
                int row = wm * 64 + mi * 16 + (lane & 15);
                int col = kk * 16 + (lane >> 4) * 8;
                ldm_x4(a[mi], sA + row * (LDA_H * 2) + col * 2);
            }
#pragma unroll
            for (int nj = 0; nj < 4; nj++) {
                int row = kk * 16 + (lane & 15);
                int col = wn * 64 + nj * 16 + (lane >> 4) * 8;
                ldm_x4_t(&b[2 * nj][0], sB + row * (LDB_H * 2) + col * 2);
            }
#pragma unroll
            for (int mi = 0; mi < 4; mi++)
#pragma unroll
                for (int ni = 0; ni < 8; ni++)
                    mma_f16(acc[mi][ni], a[mi], b[ni]);
        }
    }

    // epilogue: add bias, write fp32 C
#pragma unroll
    for (int mi = 0; mi < 4; mi++)
#pragma unroll
        for (int ni = 0; ni < 8; ni++) {
            int row = bm0 + wm * 64 + mi * 16 + (lane >> 2);
            int col = bn0 + wn * 64 + ni * 8 + (lane & 3) * 2;
            float b0 = s_bias[col - bn0], b1 = s_bias[col - bn0 + 1];
            float2 v0 = make_float2(acc[mi][ni][0] + b0, acc[mi][ni][1] + b1);
            float2 v1 = make_float2(acc[mi][ni][2] + b0, acc[mi][ni][3] + b1);
            *(float2*)&g_C[(size_t)row * NC + col]       = v0;
            *(float2*)&g_C[(size_t)(row + 8) * NC + col] = v1;
        }
}

// ---------------- stage 2: attn dot, norms, tanh-hash hamming ----------------
#define G2 4   // tokens per block, processed in pairs

__device__ __forceinline__ float wsum(float v) {
#pragma unroll
    for (int o = 16; o > 0; o >>= 1) v += __shfl_xor_sync(0xffffffffu, v, o);
    return v;
}

__global__ void __launch_bounds__(128) stage2_kernel(const float* __restrict__ hash_w,
                                                     float* __restrict__ out) {
    __shared__ float row[2][NC];
    __shared__ float kc[2][NKV][RBIT];
    __shared__ float kn[2][NKV];
    __shared__ float red[96];

    const int t = threadIdx.x;       // hash bit index 0..127
    const int lane = t & 31;
    const int wq = t >> 5;
    const float inv_sqrt_d = 0.08838834764831845f;

    float w[128];
#pragma unroll
    for (int d = 0; d < 128; d++) w[d] = hash_w[d * RBIT + t];

#pragma unroll 1
    for (int g = 0; g < G2; g += 2) {
        const int b0 = blockIdx.x * G2 + g;
        __syncthreads();   // protect smem reuse across pairs
        {
            const float4* s0 = (const float4*)(g_C + (size_t)b0 * NC);
            const float4* s1 = (const float4*)(g_C + (size_t)(b0 + 1) * NC);
            float4* d0 = (float4*)row[0];
            float4* d1 = (float4*)row[1];
#pragma unroll
            for (int i = 0; i < NC / 4 / 128; i++) {
                d0[t + 128 * i] = s0[t + 128 * i];
                d1[t + 128 * i] = s1[t + 128 * i];
            }
        }
        __syncthreads();

        // ---- k codes + k norms ----
#pragma unroll 1
        for (int kv = 0; kv < NKV; kv++) {
            const float* r0 = row[0] + NH * HD + kv * HD;
            const float* r1 = row[1] + NH * HD + kv * HD;
            const float4* r40 = (const float4*)r0;
            const float4* r41 = (const float4*)r1;
            float a0 = 0.f, a1 = 0.f;
#pragma unroll
            for (int d4 = 0; d4 < 32; d4++) {
                float4 u = r40[d4], v = r41[d4];
                a0 = fmaf(u.x, w[4 * d4 + 0], a0); a1 = fmaf(v.x, w[4 * d4 + 0], a1);
                a0 = fmaf(u.y, w[4 * d4 + 1], a0); a1 = fmaf(v.y, w[4 * d4 + 1], a1);
                a0 = fmaf(u.z, w[4 * d4 + 2], a0); a1 = fmaf(v.z, w[4 * d4 + 2], a1);
                a0 = fmaf(u.w, w[4 * d4 + 3], a0); a1 = fmaf(v.w, w[4 * d4 + 3], a1);
            }
            kc[0][kv][t] = tanhf(a0);
            kc[1][kv][t] = tanhf(a1);
            float x0 = r0[t], x1 = r1[t];
            float p0 = wsum(x0 * x0), p1 = wsum(x1 * x1);
            if (lane == 0) {
                red[(2 * kv + 0) * 4 + wq] = p0;
                red[(2 * kv + 1) * 4 + wq] = p1;
            }
        }
        __syncthreads();
        if (t < 16) {
            int kv = t >> 1, tok = t & 1;
            int s = (2 * kv + tok) * 4;
            kn[tok][kv] = red[s] + red[s + 1] + red[s + 2] + red[s + 3];
        }
        __syncthreads();

        // ---- q heads, 4 per sync round ----
#pragma unroll 1
        for (int hg = 0; hg < 8; hg++) {
#pragma unroll
            for (int i = 0; i < 4; i++) {
                const int h = hg * 4 + i;
                const float* q0 = row[0] + h * HD;
                const float* q1 = row[1] + h * HD;
                const float* k0 = row[0] + NH * HD + (h >> 2) * HD;
                const float* k1 = row[1] + NH * HD + (h >> 2) * HD;
                const float4* q40 = (const float4*)q0;
                const float4* q41 = (const float4*)q1;
                float a0 = 0.f, a1 = 0.f;
#pragma unroll
                for (int d4 = 0; d4 < 32; d4++) {
                    float4 u = q40[d4], v = q41[d4];
                    a0 = fmaf(u.x, w[4 * d4 + 0], a0); a1 = fmaf(v.x, w[4 * d4 + 0], a1);
                    a0 = fmaf(u.y, w[4 * d4 + 1], a0); a1 = fmaf(v.y, w[4 * d4 + 1], a1);
                    a0 = fmaf(u.z, w[4 * d4 + 2], a0); a1 = fmaf(v.z, w[4 * d4 + 2], a1);
                    a0 = fmaf(u.w, w[4 * d4 + 3], a0); a1 = fmaf(v.w, w[4 * d4 + 3], a1);
                }
                float ham0 = fabsf(tanhf(a0) - kc[0][h >> 2][t]);
                float ham1 = fabsf(tanhf(a1) - kc[1][h >> 2][t]);
                float qv0 = q0[t], qv1 = q1[t];
                float d0 = wsum(qv0 * k0[t]);
                float n0 = wsum(qv0 * qv0);
                float m0 = wsum(ham0);
                float d1 = wsum(qv1 * k1[t]);
                float n1 = wsum(qv1 * qv1);
                float m1 = wsum(ham1);
                if (lane == 0) {
                    int s0 = (i * 2 + 0) * 3, s1 = (i * 2 + 1) * 3;
                    red[(s0 + 0) * 4 + wq] = d0;
                    red[(s0 + 1) * 4 + wq] = n0;
                    red[(s0 + 2) * 4 + wq] = m0;
                    red[(s1 + 0) * 4 + wq] = d1;
                    red[(s1 + 1) * 4 + wq] = n1;
                    red[(s1 + 2) * 4 + wq] = m1;
                }
            }
            __syncthreads();
            if (t < 8) {
                int i = t >> 1, tok = t & 1;
                int h = hg * 4 + i;
                int bb = b0 + tok;
                int base = (i * 2 + tok) * 3;
                float dot = red[(base + 0) * 4] + red[(base + 0) * 4 + 1] +
                            red[(base + 0) * 4 + 2] + red[(base + 0) * 4 + 3];
                float qn  = red[(base + 1) * 4] + red[(base + 1) * 4 + 1] +
                            red[(base + 1) * 4 + 2] + red[(base + 1) * 4 + 3];
                float hm  = red[(base + 2) * 4] + red[(base + 2) * 4 + 1] +
                            red[(base + 2) * 4 + 2] + red[(base + 2) * 4 + 3];
                out[(size_t)bb * NH + h] = dot * inv_sqrt_d;
                float hw = (1.f - hm * (1.f / 128.f)) *
                           sqrtf(qn * kn[tok][h >> 2]) * inv_sqrt_d;
                out[(size_t)B_TOK * NH + (size_t)bb * NH + h] = hw;
            }
            __syncthreads();
        }
    }
}

// ---------------- launch ----------------
extern "C" void kernel_launch(void* const* d_in, const int* in_sizes, int n_in,
                              void* d_out, int out_size) {
    const float* hidden = (const float*)d_in[0];
    const float* proj_w = (const float*)d_in[1];
    const float* proj_b = (const float*)d_in[2];
    const float* hash_w = (const float*)d_in[3];
    float* out = (float*)d_out;

    cudaFuncSetAttribute(gemm_f16_kernel,
                         cudaFuncAttributeMaxDynamicSharedMemorySize, SMEM_BYTES);

    split_A_kernel<<<2048, 256>>>(hidden);
    split_B_kernel<<<2048, 256>>>(proj_w);
    gemm_f16_kernel<<<dim3(NC / BN, B_TOK / BM), 256, SMEM_BYTES>>>(proj_b);
    stage2_kernel<<<B_TOK / G2, 128>>>(hash_w, out);
}

// round 7
// speedup vs baseline: 2.4944x; 1.0973x over previous
#include <cuda_runtime.h>
#include <cuda_fp16.h>
#include <cstdint>

// ---------------- problem constants ----------------
#define B_TOK 8192
#define HID   4096
#define NH    32
#define NKV   8
#define HD    128
#define RBIT  128
#define QKV_C 6144
#define NC    5120   // (NH+NKV)*HD  -- v slice of proj_w unused
#define NHEADS 40    // 32 q + 8 k head-vectors per token

// ---------------- device scratch ----------------
__device__ __half g_A16[(size_t)B_TOK * HID];
__device__ __half g_B16[(size_t)HID * NC];          // [K][N]
__device__ float  g_C[(size_t)B_TOK * NC];
__device__ __half g_Chalf[(size_t)B_TOK * NC];      // fp16 copy of C (+bias)
__device__ __half g_Whi[RBIT * RBIT];               // hash_w hi [d][bit]
__device__ __half g_Wlo[RBIT * RBIT];               // hash_w lo
__device__ __half g_codes[(size_t)B_TOK * NHEADS * RBIT];  // tanh codes

// ---------------- convert kernels ----------------
__global__ void split_A_kernel(const float* __restrict__ x) {
    size_t n4 = (size_t)B_TOK * HID / 4;
    for (size_t i = (size_t)blockIdx.x * blockDim.x + threadIdx.x; i < n4;
         i += (size_t)gridDim.x * blockDim.x) {
        float4 v = ((const float4*)x)[i];
        __half2* dst = (__half2*)g_A16;
        dst[2 * i]     = __floats2half2_rn(v.x, v.y);
        dst[2 * i + 1] = __floats2half2_rn(v.z, v.w);
    }
}

__global__ void split_B_kernel(const float* __restrict__ w) {
    size_t n4 = (size_t)HID * NC / 4;
    for (size_t i = (size_t)blockIdx.x * blockDim.x + threadIdx.x; i < n4;
         i += (size_t)gridDim.x * blockDim.x) {
        size_t e = i * 4;
        size_t k = e / NC;
        size_t c = e - k * NC;
        float4 v = *(const float4*)(w + k * QKV_C + c);
        __half2* dst = (__half2*)g_B16;
        dst[2 * i]     = __floats2half2_rn(v.x, v.y);
        dst[2 * i + 1] = __floats2half2_rn(v.z, v.w);
    }
}

__global__ void conv_W_kernel(const float* __restrict__ hw) {
    int i = blockIdx.x * 256 + threadIdx.x;   // 16384 total
    float v = hw[i];
    __half h = __float2half_rn(v);
    g_Whi[i] = h;
    g_Wlo[i] = __float2half_rn(v - __half2float(h));
}

// ---------------- GEMM helpers ----------------
__device__ __forceinline__ void cp16(void* smem, const void* gmem) {
    uint32_t s = (uint32_t)__cvta_generic_to_shared(smem);
    asm volatile("cp.async.cg.shared.global [%0], [%1], 16;\n" :: "r"(s), "l"(gmem) : "memory");
}
__device__ __forceinline__ void ldm_x4(uint32_t* r, const void* p) {
    uint32_t a = (uint32_t)__cvta_generic_to_shared(p);
    asm volatile("ldmatrix.sync.aligned.m8n8.x4.shared.b16 {%0,%1,%2,%3}, [%4];\n"
        : "=r"(r[0]), "=r"(r[1]), "=r"(r[2]), "=r"(r[3]) : "r"(a));
}
__device__ __forceinline__ void ldm_x4_t(uint32_t* r, const void* p) {
    uint32_t a = (uint32_t)__cvta_generic_to_shared(p);
    asm volatile("ldmatrix.sync.aligned.m8n8.x4.trans.shared.b16 {%0,%1,%2,%3}, [%4];\n"
        : "=r"(r[0]), "=r"(r[1]), "=r"(r[2]), "=r"(r[3]) : "r"(a));
}
__device__ __forceinline__ void mma_f16(float* d, const uint32_t* a, const uint32_t* b) {
    asm volatile("mma.sync.aligned.m16n8k16.row.col.f32.f16.f16.f32 "
        "{%0,%1,%2,%3}, {%4,%5,%6,%7}, {%8,%9}, {%0,%1,%2,%3};\n"
        : "+f"(d[0]), "+f"(d[1]), "+f"(d[2]), "+f"(d[3])
        : "r"(a[0]), "r"(a[1]), "r"(a[2]), "r"(a[3]), "r"(b[0]), "r"(b[1]));
}
__device__ __forceinline__ float ftanh(float x) {
    float e = __expf(2.f * x);
    return 1.f - 2.f / (e + 1.f);
}

// ---------------- GEMM: C[8192,5120] = A16 * B16 + bias (fp32 + fp16 out) ----------------
#define BM 128
#define BN 256
#define BK 64
#define STAGES 4
#define LDA_H 72
#define LDB_H 264
#define A_BYTES (BM * LDA_H * 2)
#define B_BYTES (BK * LDB_H * 2)
#define STAGE_BYTES (A_BYTES + B_BYTES)
#define SMEM_BYTES (STAGES * STAGE_BYTES)   // 208896

extern __shared__ __align__(16) char smem_raw[];

__global__ void __launch_bounds__(256, 1) gemm_f16_kernel(const float* __restrict__ bias) {
    const int ti   = threadIdx.x;
    const int lane = ti & 31;
    const int warp = ti >> 5;
    const int wm = warp >> 2;
    const int wn = warp & 3;
    const int bn0 = blockIdx.x * BN;
    const int bm0 = blockIdx.y * BM;

    __shared__ float s_bias[BN];
    for (int i = ti; i < BN; i += 256) s_bias[i] = bias[bn0 + i];

    float acc[4][8][4];
#pragma unroll
    for (int mi = 0; mi < 4; mi++)
#pragma unroll
        for (int ni = 0; ni < 8; ni++)
#pragma unroll
            for (int r = 0; r < 4; r++) acc[mi][ni][r] = 0.f;

    auto load_stage = [&](int st, int kt) {
        char* base = smem_raw + st * STAGE_BYTES;
        char* sA   = base;
        char* sB   = base + A_BYTES;
#pragma unroll
        for (int i = 0; i < 4; i++) {
            int c = ti + 256 * i;
            int r = c >> 3, cc = c & 7;
            size_t g = (size_t)(bm0 + r) * HID + (size_t)kt * BK + cc * 8;
            cp16(sA + r * (LDA_H * 2) + cc * 16, g_A16 + g);
        }
#pragma unroll
        for (int i = 0; i < 8; i++) {
            int c = ti + 256 * i;
            int r = c >> 5, cc = c & 31;
            size_t g = (size_t)(kt * BK + r) * NC + bn0 + cc * 8;
            cp16(sB + r * (LDB_H * 2) + cc * 16, g_B16 + g);
        }
        asm volatile("cp.async.commit_group;\n" ::: "memory");
    };

    const int KT = HID / BK;
    load_stage(0, 0);
    load_stage(1, 1);
    load_stage(2, 2);

    for (int kt = 0; kt < KT; kt++) {
        asm volatile("cp.async.wait_group 2;\n" ::: "memory");
        __syncthreads();
        if (kt + 3 < KT) load_stage((kt + 3) % STAGES, kt + 3);
        else asm volatile("cp.async.commit_group;\n" ::: "memory");

        char* base = smem_raw + (kt % STAGES) * STAGE_BYTES;
        char* sA   = base;
        char* sB   = base + A_BYTES;

#pragma unroll
        for (int kk = 0; kk < 4; kk++) {
            uint32_t a[4][4], b[8][2];
#pragma unroll
            for (int mi = 0; mi < 4; mi++) {
                int row = wm * 64 + mi * 16 + (lane & 15);
                int col = kk * 16 + (lane >> 4) * 8;
                ldm_x4(a[mi], sA + row * (LDA_H * 2) + col * 2);
            }
#pragma unroll
            for (int nj = 0; nj < 4; nj++) {
                int row = kk * 16 + (lane & 15);
                int col = wn * 64 + nj * 16 + (lane >> 4) * 8;
                ldm_x4_t(&b[2 * nj][0], sB + row * (LDB_H * 2) + col * 2);
            }
#pragma unroll
            for (int mi = 0; mi < 4; mi++)
#pragma unroll
                for (int ni = 0; ni < 8; ni++)
                    mma_f16(acc[mi][ni], a[mi], b[ni]);
        }
    }

    // epilogue: add bias, write fp32 + fp16 C
#pragma unroll
    for (int mi = 0; mi < 4; mi++)
#pragma unroll
        for (int ni = 0; ni < 8; ni++) {
            int row = bm0 + wm * 64 + mi * 16 + (lane >> 2);
            int col = bn0 + wn * 64 + ni * 8 + (lane & 3) * 2;
            float b0 = s_bias[col - bn0], b1 = s_bias[col - bn0 + 1];
            float2 v0 = make_float2(acc[mi][ni][0] + b0, acc[mi][ni][1] + b1);
            float2 v1 = make_float2(acc[mi][ni][2] + b0, acc[mi][ni][3] + b1);
            *(float2*)&g_C[(size_t)row * NC + col]       = v0;
            *(float2*)&g_C[(size_t)(row + 8) * NC + col] = v1;
            *(__half2*)&g_Chalf[(size_t)row * NC + col]       = __floats2half2_rn(v0.x, v0.y);
            *(__half2*)&g_Chalf[(size_t)(row + 8) * NC + col] = __floats2half2_rn(v1.x, v1.y);
        }
}

// ---------------- hash GEMM: codes = tanh(Chalf[B*40,128] @ (Whi+Wlo)) ----------------
#define HW_LD 136
#define HSMEM_BYTES (3 * 128 * HW_LD * 2)   // 104448

__global__ void __launch_bounds__(256, 1) hash_gemm_kernel() {
    extern __shared__ __align__(16) char hsm[];
    __half* sA  = (__half*)hsm;                    // [128][136]
    __half* sWh = sA + 128 * HW_LD;
    __half* sWl = sWh + 128 * HW_LD;
    const int ti = threadIdx.x;
    const int lane = ti & 31;
    const int warp = ti >> 5;
    const int wm = warp >> 2;   // 2 warps along M, 64 rows
    const int wn = warp & 3;    // 4 warps along N, 32 cols
    const size_t m0 = (size_t)blockIdx.x * 128;

#pragma unroll
    for (int i = 0; i < 8; i++) {
        int c = ti + 256 * i;
        int r = c >> 4, cc = c & 15;
        cp16(sA + r * HW_LD + cc * 8, g_Chalf + (m0 + r) * RBIT + cc * 8);
        cp16(sWh + r * HW_LD + cc * 8, g_Whi + r * RBIT + cc * 8);
        cp16(sWl + r * HW_LD + cc * 8, g_Wlo + r * RBIT + cc * 8);
    }
    asm volatile("cp.async.commit_group;\n" ::: "memory");
    asm volatile("cp.async.wait_group 0;\n" ::: "memory");
    __syncthreads();

    float acc[4][4][4];
#pragma unroll
    for (int mi = 0; mi < 4; mi++)
#pragma unroll
        for (int ni = 0; ni < 4; ni++)
#pragma unroll
            for (int r = 0; r < 4; r++) acc[mi][ni][r] = 0.f;

#pragma unroll
    for (int kk = 0; kk < 8; kk++) {
        uint32_t a[4][4], bh[4][2], bl[4][2];
#pragma unroll
        for (int mi = 0; mi < 4; mi++) {
            int row = wm * 64 + mi * 16 + (lane & 15);
            int col = kk * 16 + (lane >> 4) * 8;
            ldm_x4(a[mi], sA + row * HW_LD + col);
        }
#pragma unroll
        for (int nj = 0; nj < 2; nj++) {
            int row = kk * 16 + (lane & 15);
            int col = wn * 32 + nj * 16 + (lane >> 4) * 8;
            ldm_x4_t(&bh[2 * nj][0], sWh + row * HW_LD + col);
            ldm_x4_t(&bl[2 * nj][0], sWl + row * HW_LD + col);
        }
#pragma unroll
        for (int mi = 0; mi < 4; mi++)
#pragma unroll
            for (int ni = 0; ni < 4; ni++) {
                mma_f16(acc[mi][ni], a[mi], bh[ni]);
                mma_f16(acc[mi][ni], a[mi], bl[ni]);
            }
    }

#pragma unroll
    for (int mi = 0; mi < 4; mi++)
#pragma unroll
        for (int ni = 0; ni < 4; ni++) {
            size_t row = m0 + wm * 64 + mi * 16 + (lane >> 2);
            int col = wn * 32 + ni * 8 + (lane & 3) * 2;
            *(__half2*)&g_codes[row * RBIT + col] =
                __floats2half2_rn(ftanh(acc[mi][ni][0]), ftanh(acc[mi][ni][1]));
            *(__half2*)&g_codes[(row + 8) * RBIT + col] =
                __floats2half2_rn(ftanh(acc[mi][ni][2]), ftanh(acc[mi][ni][3]));
        }
}

// ---------------- stage 2: dots, norms, hamming from precomputed codes ----------------
#define G2 4
#define QC_LD 136   // halfs per code row (128 + 8 pad)
// dynamic smem layout:
//   float row[2][5120]           @ 0       (40960 B)
//   half  qc [2][40][QC_LD]      @ 40960   (21760 B)
//   float kn [2][8]              @ 62720   (64 B)
//   float red[96]                @ 62784   (384 B)
#define S2_SMEM 63168

__device__ __forceinline__ float wsum(float v) {
#pragma unroll
    for (int o = 16; o > 0; o >>= 1) v += __shfl_xor_sync(0xffffffffu, v, o);
    return v;
}

__global__ void __launch_bounds__(128) stage2_kernel(float* __restrict__ out) {
    extern __shared__ __align__(16) char s2s[];
    float* rowb = (float*)s2s;                        // [2][5120]
    __half* qcs = (__half*)(s2s + 40960);             // [2][40][QC_LD]
    float* kn   = (float*)(s2s + 62720);              // [2][8]
    float* red  = (float*)(s2s + 62784);              // [96]

    const int t = threadIdx.x;
    const int lane = t & 31;
    const int wq = t >> 5;
    const float inv_sqrt_d = 0.08838834764831845f;

#pragma unroll 1
    for (int g = 0; g < G2; g += 2) {
        const int b0 = blockIdx.x * G2 + g;
        __syncthreads();
        {
            const float4* s0 = (const float4*)(g_C + (size_t)b0 * NC);
            const float4* s1 = (const float4*)(g_C + (size_t)(b0 + 1) * NC);
            float4* d0 = (float4*)rowb;
            float4* d1 = (float4*)(rowb + NC);
#pragma unroll
            for (int i = 0; i < NC / 4 / 128; i++) {
                d0[t + 128 * i] = s0[t + 128 * i];
                d1[t + 128 * i] = s1[t + 128 * i];
            }
            // codes: 40 rows x 16 uint4 = 640 uint4 per token, 5 iters x 128 threads
#pragma unroll
            for (int i = 0; i < 5; i++) {
                int idx = t + 128 * i;          // 0..639
                int h = idx >> 4, cc = idx & 15;
                *(uint4*)&qcs[(size_t)h * QC_LD + cc * 8] =
                    *(const uint4*)&g_codes[((size_t)b0 * NHEADS + h) * RBIT + cc * 8];
                *(uint4*)&qcs[(size_t)(NHEADS + h) * QC_LD + cc * 8] =
                    *(const uint4*)&g_codes[((size_t)(b0 + 1) * NHEADS + h) * RBIT + cc * 8];
            }
        }
        __syncthreads();

        // ---- k norms ----
#pragma unroll
        for (int kv = 0; kv < NKV; kv++) {
            float x0 = rowb[NH * HD + kv * HD + t];
            float x1 = rowb[NC + NH * HD + kv * HD + t];
            float p0 = wsum(x0 * x0), p1 = wsum(x1 * x1);
            if (lane == 0) {
                red[(2 * kv + 0) * 4 + wq] = p0;
                red[(2 * kv + 1) * 4 + wq] = p1;
            }
        }
        __syncthreads();
        if (t < 16) {
            int kv = t >> 1, tok = t & 1;
            int s = (2 * kv + tok) * 4;
            kn[tok * 8 + kv] = red[s] + red[s + 1] + red[s + 2] + red[s + 3];
        }
        __syncthreads();

        // ---- q heads, 4 per sync round ----
#pragma unroll 1
        for (int hg = 0; hg < 8; hg++) {
#pragma unroll
            for (int i = 0; i < 4; i++) {
                const int h = hg * 4 + i;
                const int kv = h >> 2;
                float qc0 = __half2float(qcs[(size_t)h * QC_LD + t]);
                float kc0 = __half2float(qcs[(size_t)(NH + kv) * QC_LD + t]);
                float qc1 = __half2float(qcs[(size_t)(NHEADS + h) * QC_LD + t]);
                float kc1 = __half2float(qcs[(size_t)(NHEADS + NH + kv) * QC_LD + t]);
                float ham0 = fabsf(qc0 - kc0);
                float ham1 = fabsf(qc1 - kc1);
                float qv0 = rowb[h * HD + t];
                float kv0 = rowb[NH * HD + kv * HD + t];
                float qv1 = rowb[NC + h * HD + t];
                float kv1 = rowb[NC + NH * HD + kv * HD + t];
                float d0 = wsum(qv0 * kv0);
                float n0 = wsum(qv0 * qv0);
                float m0 = wsum(ham0);
                float d1 = wsum(qv1 * kv1);
                float n1 = wsum(qv1 * qv1);
                float m1 = wsum(ham1);
                if (lane == 0) {
                    int s0 = (i * 2 + 0) * 3, s1 = (i * 2 + 1) * 3;
                    red[(s0 + 0) * 4 + wq] = d0;
                    red[(s0 + 1) * 4 + wq] = n0;
                    red[(s0 + 2) * 4 + wq] = m0;
                    red[(s1 + 0) * 4 + wq] = d1;
                    red[(s1 + 1) * 4 + wq] = n1;
                    red[(s1 + 2) * 4 + wq] = m1;
                }
            }
            __syncthreads();
            if (t < 8) {
                int i = t >> 1, tok = t & 1;
                int h = hg * 4 + i;
                int bb = b0 + tok;
                int base = (i * 2 + tok) * 3;
                float dot = red[(base + 0) * 4] + red[(base + 0) * 4 + 1] +
                            red[(base + 0) * 4 + 2] + red[(base + 0) * 4 + 3];
                float qn  = red[(base + 1) * 4] + red[(base + 1) * 4 + 1] +
                            red[(base + 1) * 4 + 2] + red[(base + 1) * 4 + 3];
                float hm  = red[(base + 2) * 4] + red[(base + 2) * 4 + 1] +
                            red[(base + 2) * 4 + 2] + red[(base + 2) * 4 + 3];
                out[(size_t)bb * NH + h] = dot * inv_sqrt_d;
                float hw = (1.f - hm * (1.f / 128.f)) *
                           sqrtf(qn * kn[tok * 8 + (h >> 2)]) * inv_sqrt_d;
                out[(size_t)B_TOK * NH + (size_t)bb * NH + h] = hw;
            }
            __syncthreads();
        }
    }
}

// ---------------- launch ----------------
extern "C" void kernel_launch(void* const* d_in, const int* in_sizes, int n_in,
                              void* d_out, int out_size) {
    const float* hidden = (const float*)d_in[0];
    const float* proj_w = (const float*)d_in[1];
    const float* proj_b = (const float*)d_in[2];
    const float* hash_w = (const float*)d_in[3];
    float* out = (float*)d_out;

    cudaFuncSetAttribute(gemm_f16_kernel,
                         cudaFuncAttributeMaxDynamicSharedMemorySize, SMEM_BYTES);
    cudaFuncSetAttribute(hash_gemm_kernel,
                         cudaFuncAttributeMaxDynamicSharedMemorySize, HSMEM_BYTES);
    cudaFuncSetAttribute(stage2_kernel,
                         cudaFuncAttributeMaxDynamicSharedMemorySize, S2_SMEM);

    split_A_kernel<<<2048, 256>>>(hidden);
    split_B_kernel<<<2048, 256>>>(proj_w);
    conv_W_kernel<<<64, 256>>>(hash_w);
    gemm_f16_kernel<<<dim3(NC / BN, B_TOK / BM), 256, SMEM_BYTES>>>(proj_b);
    hash_gemm_kernel<<<(B_TOK * NHEADS) / 128, 256, HSMEM_BYTES>>>();
    stage2_kernel<<<B_TOK / G2, 128, S2_SMEM>>>(out);
}

// round 8
// speedup vs baseline: 2.6303x; 1.0545x over previous
#include <cuda_runtime.h>
#include <cuda_fp16.h>
#include <cstdint>

// ---------------- problem constants ----------------
#define B_TOK 8192
#define HID   4096
#define NH    32
#define NKV   8
#define HD    128
#define RBIT  128
#define QKV_C 6144
#define NC    5120   // (NH+NKV)*HD  -- v slice of proj_w unused
#define NHEADS 40    // 32 q + 8 k head-vectors per token

// ---------------- device scratch ----------------
__device__ __half g_A16[(size_t)B_TOK * HID];
__device__ __half g_B16[(size_t)HID * NC];          // [K][N]
__device__ float  g_C[(size_t)B_TOK * NC];
__device__ __half g_Chalf[(size_t)B_TOK * NC];      // fp16 copy of C (+bias)
__device__ __half g_Whi[RBIT * RBIT];               // hash_w hi [d][bit]
__device__ __half g_Wlo[RBIT * RBIT];               // hash_w lo
__device__ __half g_codes[(size_t)B_TOK * NHEADS * RBIT];  // tanh codes

// ---------------- convert kernels ----------------
__global__ void split_A_kernel(const float* __restrict__ x) {
    size_t n4 = (size_t)B_TOK * HID / 4;
    for (size_t i = (size_t)blockIdx.x * blockDim.x + threadIdx.x; i < n4;
         i += (size_t)gridDim.x * blockDim.x) {
        float4 v = ((const float4*)x)[i];
        __half2* dst = (__half2*)g_A16;
        dst[2 * i]     = __floats2half2_rn(v.x, v.y);
        dst[2 * i + 1] = __floats2half2_rn(v.z, v.w);
    }
}

__global__ void split_B_kernel(const float* __restrict__ w) {
    size_t n4 = (size_t)HID * NC / 4;
    for (size_t i = (size_t)blockIdx.x * blockDim.x + threadIdx.x; i < n4;
         i += (size_t)gridDim.x * blockDim.x) {
        size_t e = i * 4;
        size_t k = e / NC;
        size_t c = e - k * NC;
        float4 v = *(const float4*)(w + k * QKV_C + c);
        __half2* dst = (__half2*)g_B16;
        dst[2 * i]     = __floats2half2_rn(v.x, v.y);
        dst[2 * i + 1] = __floats2half2_rn(v.z, v.w);
    }
}

__global__ void conv_W_kernel(const float* __restrict__ hw) {
    int i = blockIdx.x * 256 + threadIdx.x;   // 16384 total
    float v = hw[i];
    __half h = __float2half_rn(v);
    g_Whi[i] = h;
    g_Wlo[i] = __float2half_rn(v - __half2float(h));
}

// ---------------- GEMM helpers ----------------
__device__ __forceinline__ void cp16(void* smem, const void* gmem) {
    uint32_t s = (uint32_t)__cvta_generic_to_shared(smem);
    asm volatile("cp.async.cg.shared.global [%0], [%1], 16;\n" :: "r"(s), "l"(gmem) : "memory");
}
__device__ __forceinline__ void ldm_x4(uint32_t* r, const void* p) {
    uint32_t a = (uint32_t)__cvta_generic_to_shared(p);
    asm volatile("ldmatrix.sync.aligned.m8n8.x4.shared.b16 {%0,%1,%2,%3}, [%4];\n"
        : "=r"(r[0]), "=r"(r[1]), "=r"(r[2]), "=r"(r[3]) : "r"(a));
}
__device__ __forceinline__ void ldm_x4_t(uint32_t* r, const void* p) {
    uint32_t a = (uint32_t)__cvta_generic_to_shared(p);
    asm volatile("ldmatrix.sync.aligned.m8n8.x4.trans.shared.b16 {%0,%1,%2,%3}, [%4];\n"
        : "=r"(r[0]), "=r"(r[1]), "=r"(r[2]), "=r"(r[3]) : "r"(a));
}
__device__ __forceinline__ void mma_f16(float* d, const uint32_t* a, const uint32_t* b) {
    asm volatile("mma.sync.aligned.m16n8k16.row.col.f32.f16.f16.f32 "
        "{%0,%1,%2,%3}, {%4,%5,%6,%7}, {%8,%9}, {%0,%1,%2,%3};\n"
        : "+f"(d[0]), "+f"(d[1]), "+f"(d[2]), "+f"(d[3])
        : "r"(a[0]), "r"(a[1]), "r"(a[2]), "r"(a[3]), "r"(b[0]), "r"(b[1]));
}
__device__ __forceinline__ float ftanh(float x) {
    float e = __expf(2.f * x);
    return 1.f - 2.f / (e + 1.f);
}

// ---------------- GEMM: C[8192,5120] = A16 * B16 + bias (fp32 + fp16 out) ----------------
#define BM 128
#define BN 256
#define BK 64
#define NT 512
#define STAGES 4
#define LDA_H 72
#define LDB_H 264
#define A_BYTES (BM * LDA_H * 2)
#define B_BYTES (BK * LDB_H * 2)
#define STAGE_BYTES (A_BYTES + B_BYTES)
#define SMEM_BYTES (STAGES * STAGE_BYTES)   // 208896

extern __shared__ __align__(16) char smem_raw[];

__global__ void __launch_bounds__(NT, 1) gemm_f16_kernel(const float* __restrict__ bias) {
    const int ti   = threadIdx.x;
    const int lane = ti & 31;
    const int warp = ti >> 5;
    const int wm = warp >> 2;   // 4 warps along M, 32 rows each
    const int wn = warp & 3;    // 4 warps along N, 64 cols each
    const int bn0 = blockIdx.x * BN;
    const int bm0 = blockIdx.y * BM;

    __shared__ float s_bias[BN];
    for (int i = ti; i < BN; i += NT) s_bias[i] = bias[bn0 + i];

    float acc[2][8][4];
#pragma unroll
    for (int mi = 0; mi < 2; mi++)
#pragma unroll
        for (int ni = 0; ni < 8; ni++)
#pragma unroll
            for (int r = 0; r < 4; r++) acc[mi][ni][r] = 0.f;

    auto load_stage = [&](int st, int kt) {
        char* base = smem_raw + st * STAGE_BYTES;
        char* sA   = base;
        char* sB   = base + A_BYTES;
#pragma unroll
        for (int i = 0; i < 2; i++) {        // A: 1024 chunks / 512 threads
            int c = ti + NT * i;
            int r = c >> 3, cc = c & 7;
            size_t g = (size_t)(bm0 + r) * HID + (size_t)kt * BK + cc * 8;
            cp16(sA + r * (LDA_H * 2) + cc * 16, g_A16 + g);
        }
#pragma unroll
        for (int i = 0; i < 4; i++) {        // B: 2048 chunks / 512 threads
            int c = ti + NT * i;
            int r = c >> 5, cc = c & 31;
            size_t g = (size_t)(kt * BK + r) * NC + bn0 + cc * 8;
            cp16(sB + r * (LDB_H * 2) + cc * 16, g_B16 + g);
        }
        asm volatile("cp.async.commit_group;\n" ::: "memory");
    };

    const int KT = HID / BK;
    load_stage(0, 0);
    load_stage(1, 1);
    load_stage(2, 2);

    for (int kt = 0; kt < KT; kt++) {
        asm volatile("cp.async.wait_group 2;\n" ::: "memory");
        __syncthreads();
        if (kt + 3 < KT) load_stage((kt + 3) % STAGES, kt + 3);
        else asm volatile("cp.async.commit_group;\n" ::: "memory");

        char* base = smem_raw + (kt % STAGES) * STAGE_BYTES;
        char* sA   = base;
        char* sB   = base + A_BYTES;

#pragma unroll
        for (int kk = 0; kk < 4; kk++) {
            uint32_t a[2][4], b[8][2];
#pragma unroll
            for (int mi = 0; mi < 2; mi++) {
                int row = wm * 32 + mi * 16 + (lane & 15);
                int col = kk * 16 + (lane >> 4) * 8;
                ldm_x4(a[mi], sA + row * (LDA_H * 2) + col * 2);
            }
#pragma unroll
            for (int nj = 0; nj < 4; nj++) {
                int row = kk * 16 + (lane & 15);
                int col = wn * 64 + nj * 16 + (lane >> 4) * 8;
                ldm_x4_t(&b[2 * nj][0], sB + row * (LDB_H * 2) + col * 2);
            }
#pragma unroll
            for (int mi = 0; mi < 2; mi++)
#pragma unroll
                for (int ni = 0; ni < 8; ni++)
                    mma_f16(acc[mi][ni], a[mi], b[ni]);
        }
    }

    // epilogue: add bias, write fp32 + fp16 C
#pragma unroll
    for (int mi = 0; mi < 2; mi++)
#pragma unroll
        for (int ni = 0; ni < 8; ni++) {
            int row = bm0 + wm * 32 + mi * 16 + (lane >> 2);
            int col = bn0 + wn * 64 + ni * 8 + (lane & 3) * 2;
            float b0 = s_bias[col - bn0], b1 = s_bias[col - bn0 + 1];
            float2 v0 = make_float2(acc[mi][ni][0] + b0, acc[mi][ni][1] + b1);
            float2 v1 = make_float2(acc[mi][ni][2] + b0, acc[mi][ni][3] + b1);
            *(float2*)&g_C[(size_t)row * NC + col]       = v0;
            *(float2*)&g_C[(size_t)(row + 8) * NC + col] = v1;
            *(__half2*)&g_Chalf[(size_t)row * NC + col]       = __floats2half2_rn(v0.x, v0.y);
            *(__half2*)&g_Chalf[(size_t)(row + 8) * NC + col] = __floats2half2_rn(v1.x, v1.y);
        }
}

// ---------------- hash GEMM: codes = tanh(Chalf[B*40,128] @ (Whi+Wlo)) ----------------
#define HW_LD 136
#define HSMEM_BYTES (3 * 128 * HW_LD * 2)   // 104448

__global__ void __launch_bounds__(256, 1) hash_gemm_kernel() {
    extern __shared__ __align__(16) char hsm[];
    __half* sA  = (__half*)hsm;                    // [128][136]
    __half* sWh = sA + 128 * HW_LD;
    __half* sWl = sWh + 128 * HW_LD;
    const int ti = threadIdx.x;
    const int lane = ti & 31;
    const int warp = ti >> 5;
    const int wm = warp >> 2;   // 2 warps along M, 64 rows
    const int wn = warp & 3;    // 4 warps along N, 32 cols
    const size_t m0 = (size_t)blockIdx.x * 128;

#pragma unroll
    for (int i = 0; i < 8; i++) {
        int c = ti + 256 * i;
        int r = c >> 4, cc = c & 15;
        cp16(sA + r * HW_LD + cc * 8, g_Chalf + (m0 + r) * RBIT + cc * 8);
        cp16(sWh + r * HW_LD + cc * 8, g_Whi + r * RBIT + cc * 8);
        cp16(sWl + r * HW_LD + cc * 8, g_Wlo + r * RBIT + cc * 8);
    }
    asm volatile("cp.async.commit_group;\n" ::: "memory");
    asm volatile("cp.async.wait_group 0;\n" ::: "memory");
    __syncthreads();

    float acc[4][4][4];
#pragma unroll
    for (int mi = 0; mi < 4; mi++)
#pragma unroll
        for (int ni = 0; ni < 4; ni++)
#pragma unroll
            for (int r = 0; r < 4; r++) acc[mi][ni][r] = 0.f;

#pragma unroll
    for (int kk = 0; kk < 8; kk++) {
        uint32_t a[4][4], bh[4][2], bl[4][2];
#pragma unroll
        for (int mi = 0; mi < 4; mi++) {
            int row = wm * 64 + mi * 16 + (lane & 15);
            int col = kk * 16 + (lane >> 4) * 8;
            ldm_x4(a[mi], sA + row * HW_LD + col);
        }
#pragma unroll
        for (int nj = 0; nj < 2; nj++) {
            int row = kk * 16 + (lane & 15);
            int col = wn * 32 + nj * 16 + (lane >> 4) * 8;
            ldm_x4_t(&bh[2 * nj][0], sWh + row * HW_LD + col);
            ldm_x4_t(&bl[2 * nj][0], sWl + row * HW_LD + col);
        }
#pragma unroll
        for (int mi = 0; mi < 4; mi++)
#pragma unroll
            for (int ni = 0; ni < 4; ni++) {
                mma_f16(acc[mi][ni], a[mi], bh[ni]);
                mma_f16(acc[mi][ni], a[mi], bl[ni]);
            }
    }

#pragma unroll
    for (int mi = 0; mi < 4; mi++)
#pragma unroll
        for (int ni = 0; ni < 4; ni++) {
            size_t row = m0 + wm * 64 + mi * 16 + (lane >> 2);
            int col = wn * 32 + ni * 8 + (lane & 3) * 2;
            *(__half2*)&g_codes[row * RBIT + col] =
                __floats2half2_rn(ftanh(acc[mi][ni][0]), ftanh(acc[mi][ni][1]));
            *(__half2*)&g_codes[(row + 8) * RBIT + col] =
                __floats2half2_rn(ftanh(acc[mi][ni][2]), ftanh(acc[mi][ni][3]));
        }
}

// ---------------- stage 2: dots, norms, hamming from precomputed codes ----------------
#define G2 4
#define QC_LD 136   // halfs per code row (128 + 8 pad)
#define S2_SMEM 63168

__device__ __forceinline__ float wsum(float v) {
#pragma unroll
    for (int o = 16; o > 0; o >>= 1) v += __shfl_xor_sync(0xffffffffu, v, o);
    return v;
}

__global__ void __launch_bounds__(128) stage2_kernel(float* __restrict__ out) {
    extern __shared__ __align__(16) char s2s[];
    float* rowb = (float*)s2s;                        // [2][5120]
    __half* qcs = (__half*)(s2s + 40960);             // [2][40][QC_LD]
    float* kn   = (float*)(s2s + 62720);              // [2][8]
    float* red  = (float*)(s2s + 62784);              // [96]

    const int t = threadIdx.x;
    const int lane = t & 31;
    const int wq = t >> 5;
    const float inv_sqrt_d = 0.08838834764831845f;

#pragma unroll 1
    for (int g = 0; g < G2; g += 2) {
        const int b0 = blockIdx.x * G2 + g;
        __syncthreads();
        {
            const float4* s0 = (const float4*)(g_C + (size_t)b0 * NC);
            const float4* s1 = (const float4*)(g_C + (size_t)(b0 + 1) * NC);
            float4* d0 = (float4*)rowb;
            float4* d1 = (float4*)(rowb + NC);
#pragma unroll
            for (int i = 0; i < NC / 4 / 128; i++) {
                d0[t + 128 * i] = s0[t + 128 * i];
                d1[t + 128 * i] = s1[t + 128 * i];
            }
#pragma unroll
            for (int i = 0; i < 5; i++) {
                int idx = t + 128 * i;          // 0..639
                int h = idx >> 4, cc = idx & 15;
                *(uint4*)&qcs[(size_t)h * QC_LD + cc * 8] =
                    *(const uint4*)&g_codes[((size_t)b0 * NHEADS + h) * RBIT + cc * 8];
                *(uint4*)&qcs[(size_t)(NHEADS + h) * QC_LD + cc * 8] =
                    *(const uint4*)&g_codes[((size_t)(b0 + 1) * NHEADS + h) * RBIT + cc * 8];
            }
        }
        __syncthreads();

        // ---- k norms ----
#pragma unroll
        for (int kv = 0; kv < NKV; kv++) {
            float x0 = rowb[NH * HD + kv * HD + t];
            float x1 = rowb[NC + NH * HD + kv * HD + t];
            float p0 = wsum(x0 * x0), p1 = wsum(x1 * x1);
            if (lane == 0) {
                red[(2 * kv + 0) * 4 + wq] = p0;
                red[(2 * kv + 1) * 4 + wq] = p1;
            }
        }
        __syncthreads();
        if (t < 16) {
            int kv = t >> 1, tok = t & 1;
            int s = (2 * kv + tok) * 4;
            kn[tok * 8 + kv] = red[s] + red[s + 1] + red[s + 2] + red[s + 3];
        }
        __syncthreads();

        // ---- q heads, 4 per sync round ----
#pragma unroll 1
        for (int hg = 0; hg < 8; hg++) {
#pragma unroll
            for (int i = 0; i < 4; i++) {
                const int h = hg * 4 + i;
                const int kv = h >> 2;
                float qc0 = __half2float(qcs[(size_t)h * QC_LD + t]);
                float kc0 = __half2float(qcs[(size_t)(NH + kv) * QC_LD + t]);
                float qc1 = __half2float(qcs[(size_t)(NHEADS + h) * QC_LD + t]);
                float kc1 = __half2float(qcs[(size_t)(NHEADS + NH + kv) * QC_LD + t]);
                float ham0 = fabsf(qc0 - kc0);
                float ham1 = fabsf(qc1 - kc1);
                float qv0 = rowb[h * HD + t];
                float kv0 = rowb[NH * HD + kv * HD + t];
                float qv1 = rowb[NC + h * HD + t];
                float kv1 = rowb[NC + NH * HD + kv * HD + t];
                float d0 = wsum(qv0 * kv0);
                float n0 = wsum(qv0 * qv0);
                float m0 = wsum(ham0);
                float d1 = wsum(qv1 * kv1);
                float n1 = wsum(qv1 * qv1);
                float m1 = wsum(ham1);
                if (lane == 0) {
                    int s0 = (i * 2 + 0) * 3, s1 = (i * 2 + 1) * 3;
                    red[(s0 + 0) * 4 + wq] = d0;
                    red[(s0 + 1) * 4 + wq] = n0;
                    red[(s0 + 2) * 4 + wq] = m0;
                    red[(s1 + 0) * 4 + wq] = d1;
                    red[(s1 + 1) * 4 + wq] = n1;
                    red[(s1 + 2) * 4 + wq] = m1;
                }
            }
            __syncthreads();
            if (t < 8) {
                int i = t >> 1, tok = t & 1;
                int h = hg * 4 + i;
                int bb = b0 + tok;
                int base = (i * 2 + tok) * 3;
                float dot = red[(base + 0) * 4] + red[(base + 0) * 4 + 1] +
                            red[(base + 0) * 4 + 2] + red[(base + 0) * 4 + 3];
                float qn  = red[(base + 1) * 4] + red[(base + 1) * 4 + 1] +
                            red[(base + 1) * 4 + 2] + red[(base + 1) * 4 + 3];
                float hm  = red[(base + 2) * 4] + red[(base + 2) * 4 + 1] +
                            red[(base + 2) * 4 + 2] + red[(base + 2) * 4 + 3];
                out[(size_t)bb * NH + h] = dot * inv_sqrt_d;
                float hw = (1.f - hm * (1.f / 128.f)) *
                           sqrtf(qn * kn[tok * 8 + (h >> 2)]) * inv_sqrt_d;
                out[(size_t)B_TOK * NH + (size_t)bb * NH + h] = hw;
            }
            __syncthreads();
        }
    }
}

// ---------------- launch ----------------
extern "C" void kernel_launch(void* const* d_in, const int* in_sizes, int n_in,
                              void* d_out, int out_size) {
    const float* hidden = (const float*)d_in[0];
    const float* proj_w = (const float*)d_in[1];
    const float* proj_b = (const float*)d_in[2];
    const float* hash_w = (const float*)d_in[3];
    float* out = (float*)d_out;

    cudaFuncSetAttribute(gemm_f16_kernel,
                         cudaFuncAttributeMaxDynamicSharedMemorySize, SMEM_BYTES);
    cudaFuncSetAttribute(hash_gemm_kernel,
                         cudaFuncAttributeMaxDynamicSharedMemorySize, HSMEM_BYTES);
    cudaFuncSetAttribute(stage2_kernel,
                         cudaFuncAttributeMaxDynamicSharedMemorySize, S2_SMEM);

    split_A_kernel<<<2048, 256>>>(hidden);
    split_B_kernel<<<2048, 256>>>(proj_w);
    conv_W_kernel<<<64, 256>>>(hash_w);
    gemm_f16_kernel<<<dim3(NC / BN, B_TOK / BM), NT, SMEM_BYTES>>>(proj_b);
    hash_gemm_kernel<<<(B_TOK * NHEADS) / 128, 256, HSMEM_BYTES>>>();
    stage2_kernel<<<B_TOK / G2, 128, S2_SMEM>>>(out);
}

// round 9
// speedup vs baseline: 2.7808x; 1.0572x over previous
#include <cuda_runtime.h>
#include <cuda_fp16.h>
#include <cstdint>

// ---------------- problem constants ----------------
#define B_TOK 8192
#define HID   4096
#define NH    32
#define NKV   8
#define HD    128
#define RBIT  128
#define QKV_C 6144
#define NC    5120   // (NH+NKV)*HD  -- v slice of proj_w unused
#define NHEADS 40    // 32 q + 8 k head-vectors per token

// ---------------- device scratch ----------------
__device__ __half g_A16[(size_t)B_TOK * HID];
__device__ __half g_B16[(size_t)HID * NC];          // [K][N]
__device__ float  g_C[(size_t)B_TOK * NC];
__device__ __half g_Chalf[(size_t)B_TOK * NC];      // fp16 copy of C (+bias)
__device__ __half g_Whi[RBIT * RBIT];               // hash_w hi [d][bit]
__device__ __half g_Wlo[RBIT * RBIT];               // hash_w lo
__device__ __half g_codes[(size_t)B_TOK * NHEADS * RBIT];  // tanh codes

// ---------------- convert kernels ----------------
__global__ void split_A_kernel(const float* __restrict__ x) {
    size_t n4 = (size_t)B_TOK * HID / 4;
    for (size_t i = (size_t)blockIdx.x * blockDim.x + threadIdx.x; i < n4;
         i += (size_t)gridDim.x * blockDim.x) {
        float4 v = ((const float4*)x)[i];
        __half2* dst = (__half2*)g_A16;
        dst[2 * i]     = __floats2half2_rn(v.x, v.y);
        dst[2 * i + 1] = __floats2half2_rn(v.z, v.w);
    }
}

__global__ void split_B_kernel(const float* __restrict__ w) {
    size_t n4 = (size_t)HID * NC / 4;
    for (size_t i = (size_t)blockIdx.x * blockDim.x + threadIdx.x; i < n4;
         i += (size_t)gridDim.x * blockDim.x) {
        size_t e = i * 4;
        size_t k = e / NC;
        size_t c = e - k * NC;
        float4 v = *(const float4*)(w + k * QKV_C + c);
        __half2* dst = (__half2*)g_B16;
        dst[2 * i]     = __floats2half2_rn(v.x, v.y);
        dst[2 * i + 1] = __floats2half2_rn(v.z, v.w);
    }
}

__global__ void conv_W_kernel(const float* __restrict__ hw) {
    int i = blockIdx.x * 256 + threadIdx.x;   // 16384 total
    float v = hw[i];
    __half h = __float2half_rn(v);
    g_Whi[i] = h;
    g_Wlo[i] = __float2half_rn(v - __half2float(h));
}

// ---------------- GEMM helpers ----------------
__device__ __forceinline__ void cp16(void* smem, const void* gmem) {
    uint32_t s = (uint32_t)__cvta_generic_to_shared(smem);
    asm volatile("cp.async.cg.shared.global [%0], [%1], 16;\n" :: "r"(s), "l"(gmem) : "memory");
}
__device__ __forceinline__ void ldm_x4(uint32_t* r, const void* p) {
    uint32_t a = (uint32_t)__cvta_generic_to_shared(p);
    asm volatile("ldmatrix.sync.aligned.m8n8.x4.shared.b16 {%0,%1,%2,%3}, [%4];\n"
        : "=r"(r[0]), "=r"(r[1]), "=r"(r[2]), "=r"(r[3]) : "r"(a));
}
__device__ __forceinline__ void ldm_x4_t(uint32_t* r, const void* p) {
    uint32_t a = (uint32_t)__cvta_generic_to_shared(p);
    asm volatile("ldmatrix.sync.aligned.m8n8.x4.trans.shared.b16 {%0,%1,%2,%3}, [%4];\n"
        : "=r"(r[0]), "=r"(r[1]), "=r"(r[2]), "=r"(r[3]) : "r"(a));
}
__device__ __forceinline__ void mma_f16(float* d, const uint32_t* a, const uint32_t* b) {
    asm volatile("mma.sync.aligned.m16n8k16.row.col.f32.f16.f16.f32 "
        "{%0,%1,%2,%3}, {%4,%5,%6,%7}, {%8,%9}, {%0,%1,%2,%3};\n"
        : "+f"(d[0]), "+f"(d[1]), "+f"(d[2]), "+f"(d[3])
        : "r"(a[0]), "r"(a[1]), "r"(a[2]), "r"(a[3]), "r"(b[0]), "r"(b[1]));
}
__device__ __forceinline__ float ftanh(float x) {
    float e = __expf(2.f * x);
    return 1.f - 2.f / (e + 1.f);
}

// ---------------- GEMM: C[8192,5120] = A16 * B16 + bias (fp32 + fp16 out) ----------------
#define BM 128
#define BN 128
#define BK 64
#define NT 256
#define STAGES 3
#define LDA_H 72            // 64 + 8 pad
#define LDB_H 136           // 128 + 8 pad
#define A_BYTES (BM * LDA_H * 2)            // 18432
#define B_BYTES (BK * LDB_H * 2)            // 17408
#define STAGE_BYTES (A_BYTES + B_BYTES)     // 35840
#define SMEM_BYTES (STAGES * STAGE_BYTES)   // 107520 -> 2 CTAs/SM

extern __shared__ __align__(16) char smem_raw[];

__global__ void __launch_bounds__(NT, 2) gemm_f16_kernel(const float* __restrict__ bias) {
    const int ti   = threadIdx.x;
    const int lane = ti & 31;
    const int warp = ti >> 5;
    const int wm = warp & 1;    // 2 warps along M, 64 rows each
    const int wn = warp >> 1;   // 4 warps along N, 32 cols each
    const int bn0 = blockIdx.x * BN;
    const int bm0 = blockIdx.y * BM;

    __shared__ float s_bias[BN];
    for (int i = ti; i < BN; i += NT) s_bias[i] = bias[bn0 + i];

    float acc[4][4][4];
#pragma unroll
    for (int mi = 0; mi < 4; mi++)
#pragma unroll
        for (int ni = 0; ni < 4; ni++)
#pragma unroll
            for (int r = 0; r < 4; r++) acc[mi][ni][r] = 0.f;

    auto load_stage = [&](int st, int kt) {
        char* base = smem_raw + st * STAGE_BYTES;
        char* sA   = base;
        char* sB   = base + A_BYTES;
#pragma unroll
        for (int i = 0; i < 4; i++) {        // A: 128x64 = 1024 chunks / 256 thr
            int c = ti + NT * i;
            int r = c >> 3, cc = c & 7;
            size_t g = (size_t)(bm0 + r) * HID + (size_t)kt * BK + cc * 8;
            cp16(sA + r * (LDA_H * 2) + cc * 16, g_A16 + g);
        }
#pragma unroll
        for (int i = 0; i < 4; i++) {        // B: 64x128 = 1024 chunks / 256 thr
            int c = ti + NT * i;
            int r = c >> 4, cc = c & 15;
            size_t g = (size_t)(kt * BK + r) * NC + bn0 + cc * 8;
            cp16(sB + r * (LDB_H * 2) + cc * 16, g_B16 + g);
        }
        asm volatile("cp.async.commit_group;\n" ::: "memory");
    };

    const int KT = HID / BK;   // 64
    load_stage(0, 0);
    load_stage(1, 1);

    for (int kt = 0; kt < KT; kt++) {
        asm volatile("cp.async.wait_group 1;\n" ::: "memory");
        __syncthreads();
        if (kt + 2 < KT) load_stage((kt + 2) % STAGES, kt + 2);
        else asm volatile("cp.async.commit_group;\n" ::: "memory");

        char* base = smem_raw + (kt % STAGES) * STAGE_BYTES;
        char* sA   = base;
        char* sB   = base + A_BYTES;

#pragma unroll
        for (int kk = 0; kk < 4; kk++) {
            uint32_t a[4][4], b[4][2];
#pragma unroll
            for (int mi = 0; mi < 4; mi++) {
                int row = wm * 64 + mi * 16 + (lane & 15);
                int col = kk * 16 + (lane >> 4) * 8;
                ldm_x4(a[mi], sA + row * (LDA_H * 2) + col * 2);
            }
#pragma unroll
            for (int nj = 0; nj < 2; nj++) {
                int row = kk * 16 + (lane & 15);
                int col = wn * 32 + nj * 16 + (lane >> 4) * 8;
                ldm_x4_t(&b[2 * nj][0], sB + row * (LDB_H * 2) + col * 2);
            }
#pragma unroll
            for (int mi = 0; mi < 4; mi++)
#pragma unroll
                for (int ni = 0; ni < 4; ni++)
                    mma_f16(acc[mi][ni], a[mi], b[ni]);
        }
    }

    // epilogue: add bias, write fp32 + fp16 C
#pragma unroll
    for (int mi = 0; mi < 4; mi++)
#pragma unroll
        for (int ni = 0; ni < 4; ni++) {
            int row = bm0 + wm * 64 + mi * 16 + (lane >> 2);
            int col = bn0 + wn * 32 + ni * 8 + (lane & 3) * 2;
            float b0 = s_bias[col - bn0], b1 = s_bias[col - bn0 + 1];
            float2 v0 = make_float2(acc[mi][ni][0] + b0, acc[mi][ni][1] + b1);
            float2 v1 = make_float2(acc[mi][ni][2] + b0, acc[mi][ni][3] + b1);
            *(float2*)&g_C[(size_t)row * NC + col]       = v0;
            *(float2*)&g_C[(size_t)(row + 8) * NC + col] = v1;
            *(__half2*)&g_Chalf[(size_t)row * NC + col]       = __floats2half2_rn(v0.x, v0.y);
            *(__half2*)&g_Chalf[(size_t)(row + 8) * NC + col] = __floats2half2_rn(v1.x, v1.y);
        }
}

// ---------------- hash GEMM: codes = tanh(Chalf[B*40,128] @ (Whi+Wlo)) ----------------
#define HW_LD 136
#define HSMEM_BYTES (3 * 128 * HW_LD * 2)   // 104448

__global__ void __launch_bounds__(256, 1) hash_gemm_kernel() {
    extern __shared__ __align__(16) char hsm[];
    __half* sA  = (__half*)hsm;                    // [128][136]
    __half* sWh = sA + 128 * HW_LD;
    __half* sWl = sWh + 128 * HW_LD;
    const int ti = threadIdx.x;
    const int lane = ti & 31;
    const int warp = ti >> 5;
    const int wm = warp >> 2;   // 2 warps along M, 64 rows
    const int wn = warp & 3;    // 4 warps along N, 32 cols
    const size_t m0 = (size_t)blockIdx.x * 128;

#pragma unroll
    for (int i = 0; i < 8; i++) {
        int c = ti + 256 * i;
        int r = c >> 4, cc = c & 15;
        cp16(sA + r * HW_LD + cc * 8, g_Chalf + (m0 + r) * RBIT + cc * 8);
        cp16(sWh + r * HW_LD + cc * 8, g_Whi + r * RBIT + cc * 8);
        cp16(sWl + r * HW_LD + cc * 8, g_Wlo + r * RBIT + cc * 8);
    }
    asm volatile("cp.async.commit_group;\n" ::: "memory");
    asm volatile("cp.async.wait_group 0;\n" ::: "memory");
    __syncthreads();

    float acc[4][4][4];
#pragma unroll
    for (int mi = 0; mi < 4; mi++)
#pragma unroll
        for (int ni = 0; ni < 4; ni++)
#pragma unroll
            for (int r = 0; r < 4; r++) acc[mi][ni][r] = 0.f;

#pragma unroll
    for (int kk = 0; kk < 8; kk++) {
        uint32_t a[4][4], bh[4][2], bl[4][2];
#pragma unroll
        for (int mi = 0; mi < 4; mi++) {
            int row = wm * 64 + mi * 16 + (lane & 15);
            int col = kk * 16 + (lane >> 4) * 8;
            ldm_x4(a[mi], sA + row * HW_LD + col);
        }
#pragma unroll
        for (int nj = 0; nj < 2; nj++) {
            int row = kk * 16 + (lane & 15);
            int col = wn * 32 + nj * 16 + (lane >> 4) * 8;
            ldm_x4_t(&bh[2 * nj][0], sWh + row * HW_LD + col);
            ldm_x4_t(&bl[2 * nj][0], sWl + row * HW_LD + col);
        }
#pragma unroll
        for (int mi = 0; mi < 4; mi++)
#pragma unroll
            for (int ni = 0; ni < 4; ni++) {
                mma_f16(acc[mi][ni], a[mi], bh[ni]);
                mma_f16(acc[mi][ni], a[mi], bl[ni]);
            }
    }

#pragma unroll
    for (int mi = 0; mi < 4; mi++)
#pragma unroll
        for (int ni = 0; ni < 4; ni++) {
            size_t row = m0 + wm * 64 + mi * 16 + (lane >> 2);
            int col = wn * 32 + ni * 8 + (lane & 3) * 2;
            *(__half2*)&g_codes[row * RBIT + col] =
                __floats2half2_rn(ftanh(acc[mi][ni][0]), ftanh(acc[mi][ni][1]));
            *(__half2*)&g_codes[(row + 8) * RBIT + col] =
                __floats2half2_rn(ftanh(acc[mi][ni][2]), ftanh(acc[mi][ni][3]));
        }
}

// ---------------- stage 2: dots, norms, hamming from precomputed codes ----------------
#define G2 4
#define QC_LD 136   // halfs per code row (128 + 8 pad)
#define S2_SMEM 63168

__device__ __forceinline__ float wsum(float v) {
#pragma unroll
    for (int o = 16; o > 0; o >>= 1) v += __shfl_xor_sync(0xffffffffu, v, o);
    return v;
}

__global__ void __launch_bounds__(128) stage2_kernel(float* __restrict__ out) {
    extern __shared__ __align__(16) char s2s[];
    float* rowb = (float*)s2s;                        // [2][5120]
    __half* qcs = (__half*)(s2s + 40960);             // [2][40][QC_LD]
    float* kn   = (float*)(s2s + 62720);              // [2][8]
    float* red  = (float*)(s2s + 62784);              // [96]

    const int t = threadIdx.x;
    const int lane = t & 31;
    const int wq = t >> 5;
    const float inv_sqrt_d = 0.08838834764831845f;

#pragma unroll 1
    for (int g = 0; g < G2; g += 2) {
        const int b0 = blockIdx.x * G2 + g;
        __syncthreads();
        {
            const float4* s0 = (const float4*)(g_C + (size_t)b0 * NC);
            const float4* s1 = (const float4*)(g_C + (size_t)(b0 + 1) * NC);
            float4* d0 = (float4*)rowb;
            float4* d1 = (float4*)(rowb + NC);
#pragma unroll
            for (int i = 0; i < NC / 4 / 128; i++) {
                d0[t + 128 * i] = s0[t + 128 * i];
                d1[t + 128 * i] = s1[t + 128 * i];
            }
#pragma unroll
            for (int i = 0; i < 5; i++) {
                int idx = t + 128 * i;          // 0..639
                int h = idx >> 4, cc = idx & 15;
                *(uint4*)&qcs[(size_t)h * QC_LD + cc * 8] =
                    *(const uint4*)&g_codes[((size_t)b0 * NHEADS + h) * RBIT + cc * 8];
                *(uint4*)&qcs[(size_t)(NHEADS + h) * QC_LD + cc * 8] =
                    *(const uint4*)&g_codes[((size_t)(b0 + 1) * NHEADS + h) * RBIT + cc * 8];
            }
        }
        __syncthreads();

        // ---- k norms ----
#pragma unroll
        for (int kv = 0; kv < NKV; kv++) {
            float x0 = rowb[NH * HD + kv * HD + t];
            float x1 = rowb[NC + NH * HD + kv * HD + t];
            float p0 = wsum(x0 * x0), p1 = wsum(x1 * x1);
            if (lane == 0) {
                red[(2 * kv + 0) * 4 + wq] = p0;
                red[(2 * kv + 1) * 4 + wq] = p1;
            }
        }
        __syncthreads();
        if (t < 16) {
            int kv = t >> 1, tok = t & 1;
            int s = (2 * kv + tok) * 4;
            kn[tok * 8 + kv] = red[s] + red[s + 1] + red[s + 2] + red[s + 3];
        }
        __syncthreads();

        // ---- q heads, 4 per sync round ----
#pragma unroll 1
        for (int hg = 0; hg < 8; hg++) {
#pragma unroll
            for (int i = 0; i < 4; i++) {
                const int h = hg * 4 + i;
                const int kv = h >> 2;
                float qc0 = __half2float(qcs[(size_t)h * QC_LD + t]);
                float kc0 = __half2float(qcs[(size_t)(NH + kv) * QC_LD + t]);
                float qc1 = __half2float(qcs[(size_t)(NHEADS + h) * QC_LD + t]);
                float kc1 = __half2float(qcs[(size_t)(NHEADS + NH + kv) * QC_LD + t]);
                float ham0 = fabsf(qc0 - kc0);
                float ham1 = fabsf(qc1 - kc1);
                float qv0 = rowb[h * HD + t];
                float kv0 = rowb[NH * HD + kv * HD + t];
                float qv1 = rowb[NC + h * HD + t];
                float kv1 = rowb[NC + NH * HD + kv * HD + t];
                float d0 = wsum(qv0 * kv0);
                float n0 = wsum(qv0 * qv0);
                float m0 = wsum(ham0);
                float d1 = wsum(qv1 * kv1);
                float n1 = wsum(qv1 * qv1);
                float m1 = wsum(ham1);
                if (lane == 0) {
                    int s0 = (i * 2 + 0) * 3, s1 = (i * 2 + 1) * 3;
                    red[(s0 + 0) * 4 + wq] = d0;
                    red[(s0 + 1) * 4 + wq] = n0;
                    red[(s0 + 2) * 4 + wq] = m0;
                    red[(s1 + 0) * 4 + wq] = d1;
                    red[(s1 + 1) * 4 + wq] = n1;
                    red[(s1 + 2) * 4 + wq] = m1;
                }
            }
            __syncthreads();
            if (t < 8) {
                int i = t >> 1, tok = t & 1;
                int h = hg * 4 + i;
                int bb = b0 + tok;
                int base = (i * 2 + tok) * 3;
                float dot = red[(base + 0) * 4] + red[(base + 0) * 4 + 1] +
                            red[(base + 0) * 4 + 2] + red[(base + 0) * 4 + 3];
                float qn  = red[(base + 1) * 4] + red[(base + 1) * 4 + 1] +
                            red[(base + 1) * 4 + 2] + red[(base + 1) * 4 + 3];
                float hm  = red[(base + 2) * 4] + red[(base + 2) * 4 + 1] +
                            red[(base + 2) * 4 + 2] + red[(base + 2) * 4 + 3];
                out[(size_t)bb * NH + h] = dot * inv_sqrt_d;
                float hw = (1.f - hm * (1.f / 128.f)) *
                           sqrtf(qn * kn[tok * 8 + (h >> 2)]) * inv_sqrt_d;
                out[(size_t)B_TOK * NH + (size_t)bb * NH + h] = hw;
            }
            __syncthreads();
        }
    }
}

// ---------------- launch ----------------
extern "C" void kernel_launch(void* const* d_in, const int* in_sizes, int n_in,
                              void* d_out, int out_size) {
    const float* hidden = (const float*)d_in[0];
    const float* proj_w = (const float*)d_in[1];
    const float* proj_b = (const float*)d_in[2];
    const float* hash_w = (const float*)d_in[3];
    float* out = (float*)d_out;

    cudaFuncSetAttribute(gemm_f16_kernel,
                         cudaFuncAttributeMaxDynamicSharedMemorySize, SMEM_BYTES);
    cudaFuncSetAttribute(hash_gemm_kernel,
                         cudaFuncAttributeMaxDynamicSharedMemorySize, HSMEM_BYTES);
    cudaFuncSetAttribute(stage2_kernel,
                         cudaFuncAttributeMaxDynamicSharedMemorySize, S2_SMEM);

    split_A_kernel<<<2048, 256>>>(hidden);
    split_B_kernel<<<2048, 256>>>(proj_w);
    conv_W_kernel<<<64, 256>>>(hash_w);
    gemm_f16_kernel<<<dim3(NC / BN, B_TOK / BM), NT, SMEM_BYTES>>>(proj_b);
    hash_gemm_kernel<<<(B_TOK * NHEADS) / 128, 256, HSMEM_BYTES>>>();
    stage2_kernel<<<B_TOK / G2, 128, S2_SMEM>>>(out);
}

// round 10
// speedup vs baseline: 2.9791x; 1.0713x over previous
#include <cuda_runtime.h>
#include <cuda_fp16.h>
#include <cstdint>

// ---------------- problem constants ----------------
#define B_TOK 8192
#define HID   4096
#define NH    32
#define NKV   8
#define HD    128
#define RBIT  128
#define QKV_C 6144
#define NC    5120   // (NH+NKV)*HD  -- v slice of proj_w unused
#define NHEADS 40    // 32 q + 8 k head-vectors per token

// ---------------- device scratch ----------------
__device__ __half g_A16[(size_t)B_TOK * HID];
__device__ __half g_B16[(size_t)HID * NC];          // [K][N]
__device__ __half g_Chalf[(size_t)B_TOK * NC];      // fp16 C (+bias)
__device__ __half g_Whi[RBIT * RBIT];               // hash_w hi [d][bit]
__device__ __half g_Wlo[RBIT * RBIT];               // hash_w lo
__device__ __half g_codes[(size_t)B_TOK * NHEADS * RBIT];  // tanh codes

// ---------------- fused convert kernel: W | A | B ----------------
#define WBLK 64
#define ABLK 2048
#define BBLK 1280
__global__ void __launch_bounds__(256) convert_all(const float* __restrict__ x,
                                                   const float* __restrict__ w,
                                                   const float* __restrict__ hw) {
    const int b = blockIdx.x;
    const int t = threadIdx.x;
    if (b < WBLK) {                       // hash_w split hi/lo (16384 elems)
        int i = b * 256 + t;
        float v = hw[i];
        __half h = __float2half_rn(v);
        g_Whi[i] = h;
        g_Wlo[i] = __float2half_rn(v - __half2float(h));
    } else if (b < WBLK + ABLK) {         // hidden -> fp16
        size_t base = (size_t)(b - WBLK) * 256 + t;
        __half2* dst = (__half2*)g_A16;
#pragma unroll 4
        for (int it = 0; it < 16; it++) {
            size_t i = base + (size_t)it * (ABLK * 256);
            float4 v = ((const float4*)x)[i];
            dst[2 * i]     = __floats2half2_rn(v.x, v.y);
            dst[2 * i + 1] = __floats2half2_rn(v.z, v.w);
        }
    } else {                              // proj_w[:, :NC] -> fp16
        size_t base = (size_t)(b - WBLK - ABLK) * 256 + t;
        __half2* dst = (__half2*)g_B16;
#pragma unroll 4
        for (int it = 0; it < 16; it++) {
            size_t i = base + (size_t)it * (BBLK * 256);
            size_t e = i * 4;
            size_t k = e / NC;
            size_t c = e - k * NC;
            float4 v = *(const float4*)(w + k * QKV_C + c);
            dst[2 * i]     = __floats2half2_rn(v.x, v.y);
            dst[2 * i + 1] = __floats2half2_rn(v.z, v.w);
        }
    }
}

// ---------------- GEMM helpers ----------------
__device__ __forceinline__ void cp16(void* smem, const void* gmem) {
    uint32_t s = (uint32_t)__cvta_generic_to_shared(smem);
    asm volatile("cp.async.cg.shared.global [%0], [%1], 16;\n" :: "r"(s), "l"(gmem) : "memory");
}
__device__ __forceinline__ void ldm_x4(uint32_t* r, const void* p) {
    uint32_t a = (uint32_t)__cvta_generic_to_shared(p);
    asm volatile("ldmatrix.sync.aligned.m8n8.x4.shared.b16 {%0,%1,%2,%3}, [%4];\n"
        : "=r"(r[0]), "=r"(r[1]), "=r"(r[2]), "=r"(r[3]) : "r"(a));
}
__device__ __forceinline__ void ldm_x4_t(uint32_t* r, const void* p) {
    uint32_t a = (uint32_t)__cvta_generic_to_shared(p);
    asm volatile("ldmatrix.sync.aligned.m8n8.x4.trans.shared.b16 {%0,%1,%2,%3}, [%4];\n"
        : "=r"(r[0]), "=r"(r[1]), "=r"(r[2]), "=r"(r[3]) : "r"(a));
}
__device__ __forceinline__ void mma_f16(float* d, const uint32_t* a, const uint32_t* b) {
    asm volatile("mma.sync.aligned.m16n8k16.row.col.f32.f16.f16.f32 "
        "{%0,%1,%2,%3}, {%4,%5,%6,%7}, {%8,%9}, {%0,%1,%2,%3};\n"
        : "+f"(d[0]), "+f"(d[1]), "+f"(d[2]), "+f"(d[3])
        : "r"(a[0]), "r"(a[1]), "r"(a[2]), "r"(a[3]), "r"(b[0]), "r"(b[1]));
}
__device__ __forceinline__ float ftanh(float x) {
    float e = __expf(2.f * x);
    return 1.f - 2.f / (e + 1.f);
}

// ---------------- GEMM: Chalf[8192,5120] = A16 * B16 + bias ----------------
#define BM 128
#define BN 128
#define BK 64
#define NT 256
#define STAGES 3
#define LDA_H 72            // 64 + 8 pad
#define LDB_H 136           // 128 + 8 pad
#define A_BYTES (BM * LDA_H * 2)            // 18432
#define B_BYTES (BK * LDB_H * 2)            // 17408
#define STAGE_BYTES (A_BYTES + B_BYTES)     // 35840
#define SMEM_BYTES (STAGES * STAGE_BYTES)   // 107520 -> 2 CTAs/SM

extern __shared__ __align__(16) char smem_raw[];

__global__ void __launch_bounds__(NT, 2) gemm_f16_kernel(const float* __restrict__ bias) {
    const int ti   = threadIdx.x;
    const int lane = ti & 31;
    const int warp = ti >> 5;
    const int wm = warp & 1;    // 2 warps along M, 64 rows each
    const int wn = warp >> 1;   // 4 warps along N, 32 cols each
    const int bn0 = blockIdx.x * BN;
    const int bm0 = blockIdx.y * BM;

    __shared__ float s_bias[BN];
    for (int i = ti; i < BN; i += NT) s_bias[i] = bias[bn0 + i];

    float acc[4][4][4];
#pragma unroll
    for (int mi = 0; mi < 4; mi++)
#pragma unroll
        for (int ni = 0; ni < 4; ni++)
#pragma unroll
            for (int r = 0; r < 4; r++) acc[mi][ni][r] = 0.f;

    auto load_stage = [&](int st, int kt) {
        char* base = smem_raw + st * STAGE_BYTES;
        char* sA   = base;
        char* sB   = base + A_BYTES;
#pragma unroll
        for (int i = 0; i < 4; i++) {        // A: 128x64 = 1024 chunks / 256 thr
            int c = ti + NT * i;
            int r = c >> 3, cc = c & 7;
            size_t g = (size_t)(bm0 + r) * HID + (size_t)kt * BK + cc * 8;
            cp16(sA + r * (LDA_H * 2) + cc * 16, g_A16 + g);
        }
#pragma unroll
        for (int i = 0; i < 4; i++) {        // B: 64x128 = 1024 chunks / 256 thr
            int c = ti + NT * i;
            int r = c >> 4, cc = c & 15;
            size_t g = (size_t)(kt * BK + r) * NC + bn0 + cc * 8;
            cp16(sB + r * (LDB_H * 2) + cc * 16, g_B16 + g);
        }
        asm volatile("cp.async.commit_group;\n" ::: "memory");
    };

    const int KT = HID / BK;   // 64
    load_stage(0, 0);
    load_stage(1, 1);

    for (int kt = 0; kt < KT; kt++) {
        asm volatile("cp.async.wait_group 1;\n" ::: "memory");
        __syncthreads();
        if (kt + 2 < KT) load_stage((kt + 2) % STAGES, kt + 2);
        else asm volatile("cp.async.commit_group;\n" ::: "memory");

        char* base = smem_raw + (kt % STAGES) * STAGE_BYTES;
        char* sA   = base;
        char* sB   = base + A_BYTES;

#pragma unroll
        for (int kk = 0; kk < 4; kk++) {
            uint32_t a[4][4], b[4][2];
#pragma unroll
            for (int mi = 0; mi < 4; mi++) {
                int row = wm * 64 + mi * 16 + (lane & 15);
                int col = kk * 16 + (lane >> 4) * 8;
                ldm_x4(a[mi], sA + row * (LDA_H * 2) + col * 2);
            }
#pragma unroll
            for (int nj = 0; nj < 2; nj++) {
                int row = kk * 16 + (lane & 15);
                int col = wn * 32 + nj * 16 + (lane >> 4) * 8;
                ldm_x4_t(&b[2 * nj][0], sB + row * (LDB_H * 2) + col * 2);
            }
#pragma unroll
            for (int mi = 0; mi < 4; mi++)
#pragma unroll
                for (int ni = 0; ni < 4; ni++)
                    mma_f16(acc[mi][ni], a[mi], b[ni]);
        }
    }

    // epilogue: add bias, write fp16 C only
#pragma unroll
    for (int mi = 0; mi < 4; mi++)
#pragma unroll
        for (int ni = 0; ni < 4; ni++) {
            int row = bm0 + wm * 64 + mi * 16 + (lane >> 2);
            int col = bn0 + wn * 32 + ni * 8 + (lane & 3) * 2;
            float b0 = s_bias[col - bn0], b1 = s_bias[col - bn0 + 1];
            *(__half2*)&g_Chalf[(size_t)row * NC + col] =
                __floats2half2_rn(acc[mi][ni][0] + b0, acc[mi][ni][1] + b1);
            *(__half2*)&g_Chalf[(size_t)(row + 8) * NC + col] =
                __floats2half2_rn(acc[mi][ni][2] + b0, acc[mi][ni][3] + b1);
        }
}

// ---------------- hash GEMM: codes = tanh(Chalf[B*40,128] @ (Whi+Wlo)) ----------------
#define HW_LD 136
#define HSMEM_BYTES (3 * 128 * HW_LD * 2)   // 104448

__global__ void __launch_bounds__(256, 1) hash_gemm_kernel() {
    extern __shared__ __align__(16) char hsm[];
    __half* sA  = (__half*)hsm;                    // [128][136]
    __half* sWh = sA + 128 * HW_LD;
    __half* sWl = sWh + 128 * HW_LD;
    const int ti = threadIdx.x;
    const int lane = ti & 31;
    const int warp = ti >> 5;
    const int wm = warp >> 2;   // 2 warps along M, 64 rows
    const int wn = warp & 3;    // 4 warps along N, 32 cols
    const size_t m0 = (size_t)blockIdx.x * 128;

#pragma unroll
    for (int i = 0; i < 8; i++) {
        int c = ti + 256 * i;
        int r = c >> 4, cc = c & 15;
        cp16(sA + r * HW_LD + cc * 8, g_Chalf + (m0 + r) * RBIT + cc * 8);
        cp16(sWh + r * HW_LD + cc * 8, g_Whi + r * RBIT + cc * 8);
        cp16(sWl + r * HW_LD + cc * 8, g_Wlo + r * RBIT + cc * 8);
    }
    asm volatile("cp.async.commit_group;\n" ::: "memory");
    asm volatile("cp.async.wait_group 0;\n" ::: "memory");
    __syncthreads();

    float acc[4][4][4];
#pragma unroll
    for (int mi = 0; mi < 4; mi++)
#pragma unroll
        for (int ni = 0; ni < 4; ni++)
#pragma unroll
            for (int r = 0; r < 4; r++) acc[mi][ni][r] = 0.f;

#pragma unroll
    for (int kk = 0; kk < 8; kk++) {
        uint32_t a[4][4], bh[4][2], bl[4][2];
#pragma unroll
        for (int mi = 0; mi < 4; mi++) {
            int row = wm * 64 + mi * 16 + (lane & 15);
            int col = kk * 16 + (lane >> 4) * 8;
            ldm_x4(a[mi], sA + row * HW_LD + col);
        }
#pragma unroll
        for (int nj = 0; nj < 2; nj++) {
            int row = kk * 16 + (lane & 15);
            int col = wn * 32 + nj * 16 + (lane >> 4) * 8;
            ldm_x4_t(&bh[2 * nj][0], sWh + row * HW_LD + col);
            ldm_x4_t(&bl[2 * nj][0], sWl + row * HW_LD + col);
        }
#pragma unroll
        for (int mi = 0; mi < 4; mi++)
#pragma unroll
            for (int ni = 0; ni < 4; ni++) {
                mma_f16(acc[mi][ni], a[mi], bh[ni]);
                mma_f16(acc[mi][ni], a[mi], bl[ni]);
            }
    }

#pragma unroll
    for (int mi = 0; mi < 4; mi++)
#pragma unroll
        for (int ni = 0; ni < 4; ni++) {
            size_t row = m0 + wm * 64 + mi * 16 + (lane >> 2);
            int col = wn * 32 + ni * 8 + (lane & 3) * 2;
            *(__half2*)&g_codes[row * RBIT + col] =
                __floats2half2_rn(ftanh(acc[mi][ni][0]), ftanh(acc[mi][ni][1]));
            *(__half2*)&g_codes[(row + 8) * RBIT + col] =
                __floats2half2_rn(ftanh(acc[mi][ni][2]), ftanh(acc[mi][ni][3]));
        }
}

// ---------------- stage 2: dots, norms, hamming (fp16 rows + codes) ----------------
#define G2 4
#define QC_LD 136
// smem layout (bytes):
//   half  rowb[2][5120]     @ 0       (20480)
//   half  qcs [2][40][136]  @ 20480   (21760)
//   float kn  [2][8]        @ 42240   (64)
//   float red [96]          @ 42304   (384)
#define S2_SMEM 42688

__device__ __forceinline__ float wsum(float v) {
#pragma unroll
    for (int o = 16; o > 0; o >>= 1) v += __shfl_xor_sync(0xffffffffu, v, o);
    return v;
}

__global__ void __launch_bounds__(128) stage2_kernel(float* __restrict__ out) {
    extern __shared__ __align__(16) char s2s[];
    __half* rowb = (__half*)s2s;                      // [2][5120]
    __half* qcs  = (__half*)(s2s + 20480);            // [2][40][QC_LD]
    float* kn    = (float*)(s2s + 42240);             // [2][8]
    float* red   = (float*)(s2s + 42304);             // [96]

    const int t = threadIdx.x;
    const int lane = t & 31;
    const int wq = t >> 5;
    const float inv_sqrt_d = 0.08838834764831845f;

#pragma unroll 1
    for (int g = 0; g < G2; g += 2) {
        const int b0 = blockIdx.x * G2 + g;
        __syncthreads();
        {
            const uint4* s0 = (const uint4*)(g_Chalf + (size_t)b0 * NC);
            const uint4* s1 = (const uint4*)(g_Chalf + (size_t)(b0 + 1) * NC);
            uint4* d0 = (uint4*)rowb;
            uint4* d1 = (uint4*)(rowb + NC);
#pragma unroll
            for (int i = 0; i < 5; i++) {     // 640 uint4 per token
                d0[t + 128 * i] = s0[t + 128 * i];
                d1[t + 128 * i] = s1[t + 128 * i];
            }
#pragma unroll
            for (int i = 0; i < 5; i++) {
                int idx = t + 128 * i;        // 0..639
                int h = idx >> 4, cc = idx & 15;
                *(uint4*)&qcs[(size_t)h * QC_LD + cc * 8] =
                    *(const uint4*)&g_codes[((size_t)b0 * NHEADS + h) * RBIT + cc * 8];
                *(uint4*)&qcs[(size_t)(NHEADS + h) * QC_LD + cc * 8] =
                    *(const uint4*)&g_codes[((size_t)(b0 + 1) * NHEADS + h) * RBIT + cc * 8];
            }
        }
        __syncthreads();

        // ---- k norms ----
#pragma unroll
        for (int kv = 0; kv < NKV; kv++) {
            float x0 = __half2float(rowb[NH * HD + kv * HD + t]);
            float x1 = __half2float(rowb[NC + NH * HD + kv * HD + t]);
            float p0 = wsum(x0 * x0), p1 = wsum(x1 * x1);
            if (lane == 0) {
                red[(2 * kv + 0) * 4 + wq] = p0;
                red[(2 * kv + 1) * 4 + wq] = p1;
            }
        }
        __syncthreads();
        if (t < 16) {
            int kv = t >> 1, tok = t & 1;
            int s = (2 * kv + tok) * 4;
            kn[tok * 8 + kv] = red[s] + red[s + 1] + red[s + 2] + red[s + 3];
        }
        __syncthreads();

        // ---- q heads, 4 per sync round ----
#pragma unroll 1
        for (int hg = 0; hg < 8; hg++) {
#pragma unroll
            for (int i = 0; i < 4; i++) {
                const int h = hg * 4 + i;
                const int kv = h >> 2;
                float qc0 = __half2float(qcs[(size_t)h * QC_LD + t]);
                float kc0 = __half2float(qcs[(size_t)(NH + kv) * QC_LD + t]);
                float qc1 = __half2float(qcs[(size_t)(NHEADS + h) * QC_LD + t]);
                float kc1 = __half2float(qcs[(size_t)(NHEADS + NH + kv) * QC_LD + t]);
                float ham0 = fabsf(qc0 - kc0);
                float ham1 = fabsf(qc1 - kc1);
                float qv0 = __half2float(rowb[h * HD + t]);
                float kv0 = __half2float(rowb[NH * HD + kv * HD + t]);
                float qv1 = __half2float(rowb[NC + h * HD + t]);
                float kv1 = __half2float(rowb[NC + NH * HD + kv * HD + t]);
                float d0 = wsum(qv0 * kv0);
                float n0 = wsum(qv0 * qv0);
                float m0 = wsum(ham0);
                float d1 = wsum(qv1 * kv1);
                float n1 = wsum(qv1 * qv1);
                float m1 = wsum(ham1);
                if (lane == 0) {
                    int s0 = (i * 2 + 0) * 3, s1 = (i * 2 + 1) * 3;
                    red[(s0 + 0) * 4 + wq] = d0;
                    red[(s0 + 1) * 4 + wq] = n0;
                    red[(s0 + 2) * 4 + wq] = m0;
                    red[(s1 + 0) * 4 + wq] = d1;
                    red[(s1 + 1) * 4 + wq] = n1;
                    red[(s1 + 2) * 4 + wq] = m1;
                }
            }
            __syncthreads();
            if (t < 8) {
                int i = t >> 1, tok = t & 1;
                int h = hg * 4 + i;
                int bb = b0 + tok;
                int base = (i * 2 + tok) * 3;
                float dot = red[(base + 0) * 4] + red[(base + 0) * 4 + 1] +
                            red[(base + 0) * 4 + 2] + red[(base + 0) * 4 + 3];
                float qn  = red[(base + 1) * 4] + red[(base + 1) * 4 + 1] +
                            red[(base + 1) * 4 + 2] + red[(base + 1) * 4 + 3];
                float hm  = red[(base + 2) * 4] + red[(base + 2) * 4 + 1] +
                            red[(base + 2) * 4 + 2] + red[(base + 2) * 4 + 3];
                out[(size_t)bb * NH + h] = dot * inv_sqrt_d;
                float hw = (1.f - hm * (1.f / 128.f)) *
                           sqrtf(qn * kn[tok * 8 + (h >> 2)]) * inv_sqrt_d;
                out[(size_t)B_TOK * NH + (size_t)bb * NH + h] = hw;
            }
            __syncthreads();
        }
    }
}

// ---------------- launch ----------------
extern "C" void kernel_launch(void* const* d_in, const int* in_sizes, int n_in,
                              void* d_out, int out_size) {
    const float* hidden = (const float*)d_in[0];
    const float* proj_w = (const float*)d_in[1];
    const float* proj_b = (const float*)d_in[2];
    const float* hash_w = (const float*)d_in[3];
    float* out = (float*)d_out;

    cudaFuncSetAttribute(gemm_f16_kernel,
                         cudaFuncAttributeMaxDynamicSharedMemorySize, SMEM_BYTES);
    cudaFuncSetAttribute(hash_gemm_kernel,
                         cudaFuncAttributeMaxDynamicSharedMemorySize, HSMEM_BYTES);
    cudaFuncSetAttribute(stage2_kernel,
                         cudaFuncAttributeMaxDynamicSharedMemorySize, S2_SMEM);

    convert_all<<<WBLK + ABLK + BBLK, 256>>>(hidden, proj_w, hash_w);
    gemm_f16_kernel<<<dim3(NC / BN, B_TOK / BM), NT, SMEM_BYTES>>>(proj_b);
    hash_gemm_kernel<<<(B_TOK * NHEADS) / 128, 256, HSMEM_BYTES>>>();
    stage2_kernel<<<B_TOK / G2, 128, S2_SMEM>>>(out);
}

// round 11
// speedup vs baseline: 3.0163x; 1.0125x over previous
#include <cuda_runtime.h>
#include <cuda_fp16.h>
#include <cstdint>

// ---------------- problem constants ----------------
#define B_TOK 8192
#define HID   4096
#define NH    32
#define NKV   8
#define HD    128
#define RBIT  128
#define QKV_C 6144
#define NC    5120   // (NH+NKV)*HD  -- v slice of proj_w unused
#define NHEADS 40    // 32 q + 8 k head-vectors per token

// ---------------- device scratch ----------------
__device__ __half g_A16[(size_t)B_TOK * HID];
__device__ __half g_B16[(size_t)HID * NC];          // [K][N]
__device__ __half g_Chalf[(size_t)B_TOK * NC];      // fp16 C (+bias)
__device__ __half g_Whi[RBIT * RBIT];               // hash_w hi [d][bit]
__device__ __half g_Wlo[RBIT * RBIT];               // hash_w lo
__device__ __half g_codes[(size_t)B_TOK * NHEADS * RBIT];  // tanh codes

// ---------------- fused convert kernel: W | A | B ----------------
#define WBLK 64
#define ABLK 2048
#define BBLK 1280
__global__ void __launch_bounds__(256) convert_all(const float* __restrict__ x,
                                                   const float* __restrict__ w,
                                                   const float* __restrict__ hw) {
    const int b = blockIdx.x;
    const int t = threadIdx.x;
    if (b < WBLK) {                       // hash_w split hi/lo (16384 elems)
        int i = b * 256 + t;
        float v = hw[i];
        __half h = __float2half_rn(v);
        g_Whi[i] = h;
        g_Wlo[i] = __float2half_rn(v - __half2float(h));
    } else if (b < WBLK + ABLK) {         // hidden -> fp16
        size_t base = (size_t)(b - WBLK) * 256 + t;
        __half2* dst = (__half2*)g_A16;
#pragma unroll 4
        for (int it = 0; it < 16; it++) {
            size_t i = base + (size_t)it * (ABLK * 256);
            float4 v = ((const float4*)x)[i];
            dst[2 * i]     = __floats2half2_rn(v.x, v.y);
            dst[2 * i + 1] = __floats2half2_rn(v.z, v.w);
        }
    } else {                              // proj_w[:, :NC] -> fp16
        size_t base = (size_t)(b - WBLK - ABLK) * 256 + t;
        __half2* dst = (__half2*)g_B16;
#pragma unroll 4
        for (int it = 0; it < 16; it++) {
            size_t i = base + (size_t)it * (BBLK * 256);
            size_t e = i * 4;
            size_t k = e / NC;
            size_t c = e - k * NC;
            float4 v = *(const float4*)(w + k * QKV_C + c);
            dst[2 * i]     = __floats2half2_rn(v.x, v.y);
            dst[2 * i + 1] = __floats2half2_rn(v.z, v.w);
        }
    }
}

// ---------------- GEMM helpers ----------------
__device__ __forceinline__ void cp16(void* smem, const void* gmem) {
    uint32_t s = (uint32_t)__cvta_generic_to_shared(smem);
    asm volatile("cp.async.cg.shared.global [%0], [%1], 16;\n" :: "r"(s), "l"(gmem) : "memory");
}
__device__ __forceinline__ void ldm_x4(uint32_t* r, const void* p) {
    uint32_t a = (uint32_t)__cvta_generic_to_shared(p);
    asm volatile("ldmatrix.sync.aligned.m8n8.x4.shared.b16 {%0,%1,%2,%3}, [%4];\n"
        : "=r"(r[0]), "=r"(r[1]), "=r"(r[2]), "=r"(r[3]) : "r"(a));
}
__device__ __forceinline__ void ldm_x4_t(uint32_t* r, const void* p) {
    uint32_t a = (uint32_t)__cvta_generic_to_shared(p);
    asm volatile("ldmatrix.sync.aligned.m8n8.x4.trans.shared.b16 {%0,%1,%2,%3}, [%4];\n"
        : "=r"(r[0]), "=r"(r[1]), "=r"(r[2]), "=r"(r[3]) : "r"(a));
}
__device__ __forceinline__ void mma_f16(float* d, const uint32_t* a, const uint32_t* b) {
    asm volatile("mma.sync.aligned.m16n8k16.row.col.f32.f16.f16.f32 "
        "{%0,%1,%2,%3}, {%4,%5,%6,%7}, {%8,%9}, {%0,%1,%2,%3};\n"
        : "+f"(d[0]), "+f"(d[1]), "+f"(d[2]), "+f"(d[3])
        : "r"(a[0]), "r"(a[1]), "r"(a[2]), "r"(a[3]), "r"(b[0]), "r"(b[1]));
}
__device__ __forceinline__ float ftanh(float x) {
    float e = __expf(2.f * x);
    return 1.f - 2.f / (e + 1.f);
}

// ---------------- GEMM: Chalf[8192,5120] = A16 * B16 + bias ----------------
#define BM 128
#define BN 128
#define BK 64
#define NT 128
#define STAGES 3
#define LDA_H 72            // 64 + 8 pad
#define LDB_H 136           // 128 + 8 pad
#define A_BYTES (BM * LDA_H * 2)            // 18432
#define B_BYTES (BK * LDB_H * 2)            // 17408
#define STAGE_BYTES (A_BYTES + B_BYTES)     // 35840
#define SMEM_BYTES (STAGES * STAGE_BYTES)   // 107520 -> 2 CTAs/SM

extern __shared__ __align__(16) char smem_raw[];

__global__ void __launch_bounds__(NT, 2) gemm_f16_kernel(const float* __restrict__ bias) {
    const int ti   = threadIdx.x;
    const int lane = ti & 31;
    const int warp = ti >> 5;
    const int wm = warp >> 1;   // 2 warps along M, 64 rows each
    const int wn = warp & 1;    // 2 warps along N, 64 cols each
    const int bn0 = blockIdx.x * BN;
    const int bm0 = blockIdx.y * BM;

    __shared__ float s_bias[BN];
    for (int i = ti; i < BN; i += NT) s_bias[i] = bias[bn0 + i];

    float acc[4][8][4];
#pragma unroll
    for (int mi = 0; mi < 4; mi++)
#pragma unroll
        for (int ni = 0; ni < 8; ni++)
#pragma unroll
            for (int r = 0; r < 4; r++) acc[mi][ni][r] = 0.f;

    auto load_stage = [&](int st, int kt) {
        char* base = smem_raw + st * STAGE_BYTES;
        char* sA   = base;
        char* sB   = base + A_BYTES;
#pragma unroll
        for (int i = 0; i < 8; i++) {        // A: 128x64 = 1024 chunks / 128 thr
            int c = ti + NT * i;
            int r = c >> 3, cc = c & 7;
            size_t g = (size_t)(bm0 + r) * HID + (size_t)kt * BK + cc * 8;
            cp16(sA + r * (LDA_H * 2) + cc * 16, g_A16 + g);
        }
#pragma unroll
        for (int i = 0; i < 8; i++) {        // B: 64x128 = 1024 chunks / 128 thr
            int c = ti + NT * i;
            int r = c >> 4, cc = c & 15;
            size_t g = (size_t)(kt * BK + r) * NC + bn0 + cc * 8;
            cp16(sB + r * (LDB_H * 2) + cc * 16, g_B16 + g);
        }
        asm volatile("cp.async.commit_group;\n" ::: "memory");
    };

    const int KT = HID / BK;   // 64
    load_stage(0, 0);
    load_stage(1, 1);

    for (int kt = 0; kt < KT; kt++) {
        asm volatile("cp.async.wait_group 1;\n" ::: "memory");
        __syncthreads();
        if (kt + 2 < KT) load_stage((kt + 2) % STAGES, kt + 2);
        else asm volatile("cp.async.commit_group;\n" ::: "memory");

        char* base = smem_raw + (kt % STAGES) * STAGE_BYTES;
        char* sA   = base;
        char* sB   = base + A_BYTES;

#pragma unroll
        for (int kk = 0; kk < 4; kk++) {
            uint32_t a[4][4], b[8][2];
#pragma unroll
            for (int mi = 0; mi < 4; mi++) {
                int row = wm * 64 + mi * 16 + (lane & 15);
                int col = kk * 16 + (lane >> 4) * 8;
                ldm_x4(a[mi], sA + row * (LDA_H * 2) + col * 2);
            }
#pragma unroll
            for (int nj = 0; nj < 4; nj++) {
                int row = kk * 16 + (lane & 15);
                int col = wn * 64 + nj * 16 + (lane >> 4) * 8;
                ldm_x4_t(&b[2 * nj][0], sB + row * (LDB_H * 2) + col * 2);
            }
#pragma unroll
            for (int mi = 0; mi < 4; mi++)
#pragma unroll
                for (int ni = 0; ni < 8; ni++)
                    mma_f16(acc[mi][ni], a[mi], b[ni]);
        }
    }

    // epilogue: add bias, write fp16 C only
#pragma unroll
    for (int mi = 0; mi < 4; mi++)
#pragma unroll
        for (int ni = 0; ni < 8; ni++) {
            int row = bm0 + wm * 64 + mi * 16 + (lane >> 2);
            int col = bn0 + wn * 64 + ni * 8 + (lane & 3) * 2;
            float b0 = s_bias[col - bn0], b1 = s_bias[col - bn0 + 1];
            *(__half2*)&g_Chalf[(size_t)row * NC + col] =
                __floats2half2_rn(acc[mi][ni][0] + b0, acc[mi][ni][1] + b1);
            *(__half2*)&g_Chalf[(size_t)(row + 8) * NC + col] =
                __floats2half2_rn(acc[mi][ni][2] + b0, acc[mi][ni][3] + b1);
        }
}

// ---------------- hash GEMM: codes = tanh(Chalf[B*40,128] @ (Whi+Wlo)) ----------------
#define HW_LD 136
#define HSMEM_BYTES (3 * 128 * HW_LD * 2)   // 104448

__global__ void __launch_bounds__(256, 1) hash_gemm_kernel() {
    extern __shared__ __align__(16) char hsm[];
    __half* sA  = (__half*)hsm;                    // [128][136]
    __half* sWh = sA + 128 * HW_LD;
    __half* sWl = sWh + 128 * HW_LD;
    const int ti = threadIdx.x;
    const int lane = ti & 31;
    const int warp = ti >> 5;
    const int wm = warp >> 2;   // 2 warps along M, 64 rows
    const int wn = warp & 3;    // 4 warps along N, 32 cols
    const size_t m0 = (size_t)blockIdx.x * 128;

#pragma unroll
    for (int i = 0; i < 8; i++) {
        int c = ti + 256 * i;
        int r = c >> 4, cc = c & 15;
        cp16(sA + r * HW_LD + cc * 8, g_Chalf + (m0 + r) * RBIT + cc * 8);
        cp16(sWh + r * HW_LD + cc * 8, g_Whi + r * RBIT + cc * 8);
        cp16(sWl + r * HW_LD + cc * 8, g_Wlo + r * RBIT + cc * 8);
    }
    asm volatile("cp.async.commit_group;\n" ::: "memory");
    asm volatile("cp.async.wait_group 0;\n" ::: "memory");
    __syncthreads();

    float acc[4][4][4];
#pragma unroll
    for (int mi = 0; mi < 4; mi++)
#pragma unroll
        for (int ni = 0; ni < 4; ni++)
#pragma unroll
            for (int r = 0; r < 4; r++) acc[mi][ni][r] = 0.f;

#pragma unroll
    for (int kk = 0; kk < 8; kk++) {
        uint32_t a[4][4], bh[4][2], bl[4][2];
#pragma unroll
        for (int mi = 0; mi < 4; mi++) {
            int row = wm * 64 + mi * 16 + (lane & 15);
            int col = kk * 16 + (lane >> 4) * 8;
            ldm_x4(a[mi], sA + row * HW_LD + col);
        }
#pragma unroll
        for (int nj = 0; nj < 2; nj++) {
            int row = kk * 16 + (lane & 15);
            int col = wn * 32 + nj * 16 + (lane >> 4) * 8;
            ldm_x4_t(&bh[2 * nj][0], sWh + row * HW_LD + col);
            ldm_x4_t(&bl[2 * nj][0], sWl + row * HW_LD + col);
        }
#pragma unroll
        for (int mi = 0; mi < 4; mi++)
#pragma unroll
            for (int ni = 0; ni < 4; ni++) {
                mma_f16(acc[mi][ni], a[mi], bh[ni]);
                mma_f16(acc[mi][ni], a[mi], bl[ni]);
            }
    }

#pragma unroll
    for (int mi = 0; mi < 4; mi++)
#pragma unroll
        for (int ni = 0; ni < 4; ni++) {
            size_t row = m0 + wm * 64 + mi * 16 + (lane >> 2);
            int col = wn * 32 + ni * 8 + (lane & 3) * 2;
            *(__half2*)&g_codes[row * RBIT + col] =
                __floats2half2_rn(ftanh(acc[mi][ni][0]), ftanh(acc[mi][ni][1]));
            *(__half2*)&g_codes[(row + 8) * RBIT + col] =
                __floats2half2_rn(ftanh(acc[mi][ni][2]), ftanh(acc[mi][ni][3]));
        }
}

// ---------------- stage 2: dots, norms, hamming (fp16 rows + codes) ----------------
#define G2 4
#define QC_LD 136
#define S2_SMEM 42688

__device__ __forceinline__ float wsum(float v) {
#pragma unroll
    for (int o = 16; o > 0; o >>= 1) v += __shfl_xor_sync(0xffffffffu, v, o);
    return v;
}

__global__ void __launch_bounds__(128) stage2_kernel(float* __restrict__ out) {
    extern __shared__ __align__(16) char s2s[];
    __half* rowb = (__half*)s2s;                      // [2][5120]
    __half* qcs  = (__half*)(s2s + 20480);            // [2][40][QC_LD]
    float* kn    = (float*)(s2s + 42240);             // [2][8]
    float* red   = (float*)(s2s + 42304);             // [96]

    const int t = threadIdx.x;
    const int lane = t & 31;
    const int wq = t >> 5;
    const float inv_sqrt_d = 0.08838834764831845f;

#pragma unroll 1
    for (int g = 0; g < G2; g += 2) {
        const int b0 = blockIdx.x * G2 + g;
        __syncthreads();
        {
            const uint4* s0 = (const uint4*)(g_Chalf + (size_t)b0 * NC);
            const uint4* s1 = (const uint4*)(g_Chalf + (size_t)(b0 + 1) * NC);
            uint4* d0 = (uint4*)rowb;
            uint4* d1 = (uint4*)(rowb + NC);
#pragma unroll
            for (int i = 0; i < 5; i++) {     // 640 uint4 per token
                d0[t + 128 * i] = s0[t + 128 * i];
                d1[t + 128 * i] = s1[t + 128 * i];
            }
#pragma unroll
            for (int i = 0; i < 5; i++) {
                int idx = t + 128 * i;        // 0..639
                int h = idx >> 4, cc = idx & 15;
                *(uint4*)&qcs[(size_t)h * QC_LD + cc * 8] =
                    *(const uint4*)&g_codes[((size_t)b0 * NHEADS + h) * RBIT + cc * 8];
                *(uint4*)&qcs[(size_t)(NHEADS + h) * QC_LD + cc * 8] =
                    *(const uint4*)&g_codes[((size_t)(b0 + 1) * NHEADS + h) * RBIT + cc * 8];
            }
        }
        __syncthreads();

        // ---- k norms ----
#pragma unroll
        for (int kv = 0; kv < NKV; kv++) {
            float x0 = __half2float(rowb[NH * HD + kv * HD + t]);
            float x1 = __half2float(rowb[NC + NH * HD + kv * HD + t]);
            float p0 = wsum(x0 * x0), p1 = wsum(x1 * x1);
            if (lane == 0) {
                red[(2 * kv + 0) * 4 + wq] = p0;
                red[(2 * kv + 1) * 4 + wq] = p1;
            }
        }
        __syncthreads();
        if (t < 16) {
            int kv = t >> 1, tok = t & 1;
            int s = (2 * kv + tok) * 4;
            kn[tok * 8 + kv] = red[s] + red[s + 1] + red[s + 2] + red[s + 3];
        }
        __syncthreads();

        // ---- q heads, 4 per sync round ----
#pragma unroll 1
        for (int hg = 0; hg < 8; hg++) {
#pragma unroll
            for (int i = 0; i < 4; i++) {
                const int h = hg * 4 + i;
                const int kv = h >> 2;
                float qc0 = __half2float(qcs[(size_t)h * QC_LD + t]);
                float kc0 = __half2float(qcs[(size_t)(NH + kv) * QC_LD + t]);
                float qc1 = __half2float(qcs[(size_t)(NHEADS + h) * QC_LD + t]);
                float kc1 = __half2float(qcs[(size_t)(NHEADS + NH + kv) * QC_LD + t]);
                float ham0 = fabsf(qc0 - kc0);
                float ham1 = fabsf(qc1 - kc1);
                float qv0 = __half2float(rowb[h * HD + t]);
                float kv0 = __half2float(rowb[NH * HD + kv * HD + t]);
                float qv1 = __half2float(rowb[NC + h * HD + t]);
                float kv1 = __half2float(rowb[NC + NH * HD + kv * HD + t]);
                float d0 = wsum(qv0 * kv0);
                float n0 = wsum(qv0 * qv0);
                float m0 = wsum(ham0);
                float d1 = wsum(qv1 * kv1);
                float n1 = wsum(qv1 * qv1);
                float m1 = wsum(ham1);
                if (lane == 0) {
                    int s0 = (i * 2 + 0) * 3, s1 = (i * 2 + 1) * 3;
                    red[(s0 + 0) * 4 + wq] = d0;
                    red[(s0 + 1) * 4 + wq] = n0;
                    red[(s0 + 2) * 4 + wq] = m0;
                    red[(s1 + 0) * 4 + wq] = d1;
                    red[(s1 + 1) * 4 + wq] = n1;
                    red[(s1 + 2) * 4 + wq] = m1;
                }
            }
            __syncthreads();
            if (t < 8) {
                int i = t >> 1, tok = t & 1;
                int h = hg * 4 + i;
                int bb = b0 + tok;
                int base = (i * 2 + tok) * 3;
                float dot = red[(base + 0) * 4] + red[(base + 0) * 4 + 1] +
                            red[(base + 0) * 4 + 2] + red[(base + 0) * 4 + 3];
                float qn  = red[(base + 1) * 4] + red[(base + 1) * 4 + 1] +
                            red[(base + 1) * 4 + 2] + red[(base + 1) * 4 + 3];
                float hm  = red[(base + 2) * 4] + red[(base + 2) * 4 + 1] +
                            red[(base + 2) * 4 + 2] + red[(base + 2) * 4 + 3];
                out[(size_t)bb * NH + h] = dot * inv_sqrt_d;
                float hw = (1.f - hm * (1.f / 128.f)) *
                           sqrtf(qn * kn[tok * 8 + (h >> 2)]) * inv_sqrt_d;
                out[(size_t)B_TOK * NH + (size_t)bb * NH + h] = hw;
            }
            __syncthreads();
        }
    }
}

// ---------------- launch ----------------
extern "C" void kernel_launch(void* const* d_in, const int* in_sizes, int n_in,
                              void* d_out, int out_size) {
    const float* hidden = (const float*)d_in[0];
    const float* proj_w = (const float*)d_in[1];
    const float* proj_b = (const float*)d_in[2];
    const float* hash_w = (const float*)d_in[3];
    float* out = (float*)d_out;

    cudaFuncSetAttribute(gemm_f16_kernel,
                         cudaFuncAttributeMaxDynamicSharedMemorySize, SMEM_BYTES);
    cudaFuncSetAttribute(hash_gemm_kernel,
                         cudaFuncAttributeMaxDynamicSharedMemorySize, HSMEM_BYTES);
    cudaFuncSetAttribute(stage2_kernel,
                         cudaFuncAttributeMaxDynamicSharedMemorySize, S2_SMEM);

    convert_all<<<WBLK + ABLK + BBLK, 256>>>(hidden, proj_w, hash_w);
    gemm_f16_kernel<<<dim3(NC / BN, B_TOK / BM), NT, SMEM_BYTES>>>(proj_b);
    hash_gemm_kernel<<<(B_TOK * NHEADS) / 128, 256, HSMEM_BYTES>>>();
    stage2_kernel<<<B_TOK / G2, 128, S2_SMEM>>>(out);
}

// round 12
// speedup vs baseline: 3.2529x; 1.0784x over previous
#include <cuda_runtime.h>
#include <cuda_fp16.h>
#include <cstdint>

// ---------------- problem constants ----------------
#define B_TOK 8192
#define HID   4096
#define NH    32
#define NKV   8
#define HD    128
#define RBIT  128
#define QKV_C 6144
#define NC    5120   // (NH+NKV)*HD  -- v slice of proj_w unused
#define NHEADS 40    // 32 q + 8 k head-vectors per token

// ---------------- device scratch ----------------
__device__ __half g_A16[(size_t)B_TOK * HID];
__device__ __half g_B16[(size_t)HID * NC];          // [K][N]
__device__ __half g_Chalf[(size_t)B_TOK * NC];      // fp16 C (+bias)
__device__ __half g_Whi[RBIT * RBIT];               // hash_w hi [d][bit]
__device__ __half g_Wlo[RBIT * RBIT];               // hash_w lo
__device__ __half g_codes[(size_t)B_TOK * NHEADS * RBIT];  // tanh codes

// ---------------- fused convert kernel: W | A | B ----------------
#define WBLK 64
#define ABLK 2048
#define BBLK 1280
__global__ void __launch_bounds__(256) convert_all(const float* __restrict__ x,
                                                   const float* __restrict__ w,
                                                   const float* __restrict__ hw) {
    const int b = blockIdx.x;
    const int t = threadIdx.x;
    if (b < WBLK) {                       // hash_w split hi/lo (16384 elems)
        int i = b * 256 + t;
        float v = hw[i];
        __half h = __float2half_rn(v);
        g_Whi[i] = h;
        g_Wlo[i] = __float2half_rn(v - __half2float(h));
    } else if (b < WBLK + ABLK) {         // hidden -> fp16
        size_t base = (size_t)(b - WBLK) * 256 + t;
        __half2* dst = (__half2*)g_A16;
#pragma unroll 4
        for (int it = 0; it < 16; it++) {
            size_t i = base + (size_t)it * (ABLK * 256);
            float4 v = ((const float4*)x)[i];
            dst[2 * i]     = __floats2half2_rn(v.x, v.y);
            dst[2 * i + 1] = __floats2half2_rn(v.z, v.w);
        }
    } else {                              // proj_w[:, :NC] -> fp16
        size_t base = (size_t)(b - WBLK - ABLK) * 256 + t;
        __half2* dst = (__half2*)g_B16;
#pragma unroll 4
        for (int it = 0; it < 16; it++) {
            size_t i = base + (size_t)it * (BBLK * 256);
            size_t e = i * 4;
            size_t k = e / NC;
            size_t c = e - k * NC;
            float4 v = *(const float4*)(w + k * QKV_C + c);
            dst[2 * i]     = __floats2half2_rn(v.x, v.y);
            dst[2 * i + 1] = __floats2half2_rn(v.z, v.w);
        }
    }
}

// ---------------- GEMM helpers ----------------
__device__ __forceinline__ void cp16(void* smem, const void* gmem) {
    uint32_t s = (uint32_t)__cvta_generic_to_shared(smem);
    asm volatile("cp.async.cg.shared.global [%0], [%1], 16;\n" :: "r"(s), "l"(gmem) : "memory");
}
__device__ __forceinline__ void ldm_x4(uint32_t* r, const void* p) {
    uint32_t a = (uint32_t)__cvta_generic_to_shared(p);
    asm volatile("ldmatrix.sync.aligned.m8n8.x4.shared.b16 {%0,%1,%2,%3}, [%4];\n"
        : "=r"(r[0]), "=r"(r[1]), "=r"(r[2]), "=r"(r[3]) : "r"(a));
}
__device__ __forceinline__ void ldm_x4_t(uint32_t* r, const void* p) {
    uint32_t a = (uint32_t)__cvta_generic_to_shared(p);
    asm volatile("ldmatrix.sync.aligned.m8n8.x4.trans.shared.b16 {%0,%1,%2,%3}, [%4];\n"
        : "=r"(r[0]), "=r"(r[1]), "=r"(r[2]), "=r"(r[3]) : "r"(a));
}
__device__ __forceinline__ void mma_f16(float* d, const uint32_t* a, const uint32_t* b) {
    asm volatile("mma.sync.aligned.m16n8k16.row.col.f32.f16.f16.f32 "
        "{%0,%1,%2,%3}, {%4,%5,%6,%7}, {%8,%9}, {%0,%1,%2,%3};\n"
        : "+f"(d[0]), "+f"(d[1]), "+f"(d[2]), "+f"(d[3])
        : "r"(a[0]), "r"(a[1]), "r"(a[2]), "r"(a[3]), "r"(b[0]), "r"(b[1]));
}
__device__ __forceinline__ float ftanh(float x) {
    float e = __expf(2.f * x);
    return 1.f - 2.f / (e + 1.f);
}

// ---------------- GEMM: Chalf[8192,5120] = A16 * B16 + bias ----------------
#define BM 128
#define BN 128
#define BK 64
#define NT 128
#define STAGES 3
#define LDA_H 72            // 64 + 8 pad
#define LDB_H 136           // 128 + 8 pad
#define A_BYTES (BM * LDA_H * 2)            // 18432
#define B_BYTES (BK * LDB_H * 2)            // 17408
#define STAGE_BYTES (A_BYTES + B_BYTES)     // 35840
#define SMEM_BYTES (STAGES * STAGE_BYTES)   // 107520 -> 2 CTAs/SM

extern __shared__ __align__(16) char smem_raw[];

__global__ void __launch_bounds__(NT, 2) gemm_f16_kernel(const float* __restrict__ bias) {
    const int ti   = threadIdx.x;
    const int lane = ti & 31;
    const int warp = ti >> 5;
    const int wm = warp >> 1;   // 2 warps along M, 64 rows each
    const int wn = warp & 1;    // 2 warps along N, 64 cols each
    const int bn0 = blockIdx.x * BN;
    const int bm0 = blockIdx.y * BM;

    __shared__ float s_bias[BN];
    for (int i = ti; i < BN; i += NT) s_bias[i] = bias[bn0 + i];

    float acc[4][8][4];
#pragma unroll
    for (int mi = 0; mi < 4; mi++)
#pragma unroll
        for (int ni = 0; ni < 8; ni++)
#pragma unroll
            for (int r = 0; r < 4; r++) acc[mi][ni][r] = 0.f;

    auto load_stage = [&](int st, int kt) {
        char* base = smem_raw + st * STAGE_BYTES;
        char* sA   = base;
        char* sB   = base + A_BYTES;
#pragma unroll
        for (int i = 0; i < 8; i++) {        // A: 128x64 = 1024 chunks / 128 thr
            int c = ti + NT * i;
            int r = c >> 3, cc = c & 7;
            size_t g = (size_t)(bm0 + r) * HID + (size_t)kt * BK + cc * 8;
            cp16(sA + r * (LDA_H * 2) + cc * 16, g_A16 + g);
        }
#pragma unroll
        for (int i = 0; i < 8; i++) {        // B: 64x128 = 1024 chunks / 128 thr
            int c = ti + NT * i;
            int r = c >> 4, cc = c & 15;
            size_t g = (size_t)(kt * BK + r) * NC + bn0 + cc * 8;
            cp16(sB + r * (LDB_H * 2) + cc * 16, g_B16 + g);
        }
        asm volatile("cp.async.commit_group;\n" ::: "memory");
    };

    // double-buffered fragments
    uint32_t afr[2][4][4], bfr[2][8][2];

    auto load_frag = [&](int bi, char* sA, char* sB, int kk) {
#pragma unroll
        for (int mi = 0; mi < 4; mi++) {
            int row = wm * 64 + mi * 16 + (lane & 15);
            int col = kk * 16 + (lane >> 4) * 8;
            ldm_x4(afr[bi][mi], sA + row * (LDA_H * 2) + col * 2);
        }
#pragma unroll
        for (int nj = 0; nj < 4; nj++) {
            int row = kk * 16 + (lane & 15);
            int col = wn * 64 + nj * 16 + (lane >> 4) * 8;
            ldm_x4_t(&bfr[bi][2 * nj][0], sB + row * (LDB_H * 2) + col * 2);
        }
    };

    const int KT = HID / BK;   // 64
    load_stage(0, 0);
    load_stage(1, 1);
    asm volatile("cp.async.wait_group 1;\n" ::: "memory");
    __syncthreads();
    load_frag(0, smem_raw, smem_raw + A_BYTES, 0);

    for (int kt = 0; kt < KT; kt++) {
        char* base = smem_raw + (kt % STAGES) * STAGE_BYTES;
        char* sA   = base;
        char* sB   = base + A_BYTES;

#pragma unroll
        for (int kk = 0; kk < 4; kk++) {
            const int cur = kk & 1;
            if (kk < 3) load_frag(cur ^ 1, sA, sB, kk + 1);
#pragma unroll
            for (int mi = 0; mi < 4; mi++)
#pragma unroll
                for (int ni = 0; ni < 8; ni++)
                    mma_f16(acc[mi][ni], afr[cur][mi], bfr[cur][ni]);
        }

        if (kt + 1 < KT) {
            if (kt + 2 < KT) load_stage((kt + 2) % STAGES, kt + 2);
            else asm volatile("cp.async.commit_group;\n" ::: "memory");
            asm volatile("cp.async.wait_group 1;\n" ::: "memory");
            __syncthreads();
            char* nb = smem_raw + ((kt + 1) % STAGES) * STAGE_BYTES;
            load_frag(0, nb, nb + A_BYTES, 0);
        }
    }

    // epilogue: add bias, write fp16 C only
#pragma unroll
    for (int mi = 0; mi < 4; mi++)
#pragma unroll
        for (int ni = 0; ni < 8; ni++) {
            int row = bm0 + wm * 64 + mi * 16 + (lane >> 2);
            int col = bn0 + wn * 64 + ni * 8 + (lane & 3) * 2;
            float b0 = s_bias[col - bn0], b1 = s_bias[col - bn0 + 1];
            *(__half2*)&g_Chalf[(size_t)row * NC + col] =
                __floats2half2_rn(acc[mi][ni][0] + b0, acc[mi][ni][1] + b1);
            *(__half2*)&g_Chalf[(size_t)(row + 8) * NC + col] =
                __floats2half2_rn(acc[mi][ni][2] + b0, acc[mi][ni][3] + b1);
        }
}

// ---------------- hash GEMM: codes = tanh(Chalf[B*40,128] @ (Whi+Wlo)) ----------------
#define HW_LD 136
#define HSMEM_BYTES (3 * 128 * HW_LD * 2)   // 104448

__global__ void __launch_bounds__(256, 1) hash_gemm_kernel() {
    extern __shared__ __align__(16) char hsm[];
    __half* sA  = (__half*)hsm;                    // [128][136]
    __half* sWh = sA + 128 * HW_LD;
    __half* sWl = sWh + 128 * HW_LD;
    const int ti = threadIdx.x;
    const int lane = ti & 31;
    const int warp = ti >> 5;
    const int wm = warp >> 2;   // 2 warps along M, 64 rows
    const int wn = warp & 3;    // 4 warps along N, 32 cols
    const size_t m0 = (size_t)blockIdx.x * 128;

#pragma unroll
    for (int i = 0; i < 8; i++) {
        int c = ti + 256 * i;
        int r = c >> 4, cc = c & 15;
        cp16(sA + r * HW_LD + cc * 8, g_Chalf + (m0 + r) * RBIT + cc * 8);
        cp16(sWh + r * HW_LD + cc * 8, g_Whi + r * RBIT + cc * 8);
        cp16(sWl + r * HW_LD + cc * 8, g_Wlo + r * RBIT + cc * 8);
    }
    asm volatile("cp.async.commit_group;\n" ::: "memory");
    asm volatile("cp.async.wait_group 0;\n" ::: "memory");
    __syncthreads();

    float acc[4][4][4];
#pragma unroll
    for (int mi = 0; mi < 4; mi++)
#pragma unroll
        for (int ni = 0; ni < 4; ni++)
#pragma unroll
            for (int r = 0; r < 4; r++) acc[mi][ni][r] = 0.f;

#pragma unroll
    for (int kk = 0; kk < 8; kk++) {
        uint32_t a[4][4], bh[4][2], bl[4][2];
#pragma unroll
        for (int mi = 0; mi < 4; mi++) {
            int row = wm * 64 + mi * 16 + (lane & 15);
            int col = kk * 16 + (lane >> 4) * 8;
            ldm_x4(a[mi], sA + row * HW_LD + col);
        }
#pragma unroll
        for (int nj = 0; nj < 2; nj++) {
            int row = kk * 16 + (lane & 15);
            int col = wn * 32 + nj * 16 + (lane >> 4) * 8;
            ldm_x4_t(&bh[2 * nj][0], sWh + row * HW_LD + col);
            ldm_x4_t(&bl[2 * nj][0], sWl + row * HW_LD + col);
        }
#pragma unroll
        for (int mi = 0; mi < 4; mi++)
#pragma unroll
            for (int ni = 0; ni < 4; ni++) {
                mma_f16(acc[mi][ni], a[mi], bh[ni]);
                mma_f16(acc[mi][ni], a[mi], bl[ni]);
            }
    }

#pragma unroll
    for (int mi = 0; mi < 4; mi++)
#pragma unroll
        for (int ni = 0; ni < 4; ni++) {
            size_t row = m0 + wm * 64 + mi * 16 + (lane >> 2);
            int col = wn * 32 + ni * 8 + (lane & 3) * 2;
            *(__half2*)&g_codes[row * RBIT + col] =
                __floats2half2_rn(ftanh(acc[mi][ni][0]), ftanh(acc[mi][ni][1]));
            *(__half2*)&g_codes[(row + 8) * RBIT + col] =
                __floats2half2_rn(ftanh(acc[mi][ni][2]), ftanh(acc[mi][ni][3]));
        }
}

// ---------------- stage 2: dots, norms, hamming (fp16 rows + codes) ----------------
#define G2 4
#define QC_LD 136
#define S2_SMEM 42688

__device__ __forceinline__ float wsum(float v) {
#pragma unroll
    for (int o = 16; o > 0; o >>= 1) v += __shfl_xor_sync(0xffffffffu, v, o);
    return v;
}

__global__ void __launch_bounds__(128) stage2_kernel(float* __restrict__ out) {
    extern __shared__ __align__(16) char s2s[];
    __half* rowb = (__half*)s2s;                      // [2][5120]
    __half* qcs  = (__half*)(s2s + 20480);            // [2][40][QC_LD]
    float* kn    = (float*)(s2s + 42240);             // [2][8]
    float* red   = (float*)(s2s + 42304);             // [96]

    const int t = threadIdx.x;
    const int lane = t & 31;
    const int wq = t >> 5;
    const float inv_sqrt_d = 0.08838834764831845f;

#pragma unroll 1
    for (int g = 0; g < G2; g += 2) {
        const int b0 = blockIdx.x * G2 + g;
        __syncthreads();
        {
            const uint4* s0 = (const uint4*)(g_Chalf + (size_t)b0 * NC);
            const uint4* s1 = (const uint4*)(g_Chalf + (size_t)(b0 + 1) * NC);
            uint4* d0 = (uint4*)rowb;
            uint4* d1 = (uint4*)(rowb + NC);
#pragma unroll
            for (int i = 0; i < 5; i++) {     // 640 uint4 per token
                d0[t + 128 * i] = s0[t + 128 * i];
                d1[t + 128 * i] = s1[t + 128 * i];
            }
#pragma unroll
            for (int i = 0; i < 5; i++) {
                int idx = t + 128 * i;        // 0..639
                int h = idx >> 4, cc = idx & 15;
                *(uint4*)&qcs[(size_t)h * QC_LD + cc * 8] =
                    *(const uint4*)&g_codes[((size_t)b0 * NHEADS + h) * RBIT + cc * 8];
                *(uint4*)&qcs[(size_t)(NHEADS + h) * QC_LD + cc * 8] =
                    *(const uint4*)&g_codes[((size_t)(b0 + 1) * NHEADS + h) * RBIT + cc * 8];
            }
        }
        __syncthreads();

        // ---- k norms ----
#pragma unroll
        for (int kv = 0; kv < NKV; kv++) {
            float x0 = __half2float(rowb[NH * HD + kv * HD + t]);
            float x1 = __half2float(rowb[NC + NH * HD + kv * HD + t]);
            float p0 = wsum(x0 * x0), p1 = wsum(x1 * x1);
            if (lane == 0) {
                red[(2 * kv + 0) * 4 + wq] = p0;
                red[(2 * kv + 1) * 4 + wq] = p1;
            }
        }
        __syncthreads();
        if (t < 16) {
            int kv = t >> 1, tok = t & 1;
            int s = (2 * kv + tok) * 4;
            kn[tok * 8 + kv] = red[s] + red[s + 1] + red[s + 2] + red[s + 3];
        }
        __syncthreads();

        // ---- q heads, 4 per sync round ----
#pragma unroll 1
        for (int hg = 0; hg < 8; hg++) {
#pragma unroll
            for (int i = 0; i < 4; i++) {
                const int h = hg * 4 + i;
                const int kv = h >> 2;
                float qc0 = __half2float(qcs[(size_t)h * QC_LD + t]);
                float kc0 = __half2float(qcs[(size_t)(NH + kv) * QC_LD + t]);
                float qc1 = __half2float(qcs[(size_t)(NHEADS + h) * QC_LD + t]);
                float kc1 = __half2float(qcs[(size_t)(NHEADS + NH + kv) * QC_LD + t]);
                float ham0 = fabsf(qc0 - kc0);
                float ham1 = fabsf(qc1 - kc1);
                float qv0 = __half2float(rowb[h * HD + t]);
                float kv0 = __half2float(rowb[NH * HD + kv * HD + t]);
                float qv1 = __half2float(rowb[NC + h * HD + t]);
                float kv1 = __half2float(rowb[NC + NH * HD + kv * HD + t]);
                float d0 = wsum(qv0 * kv0);
                float n0 = wsum(qv0 * qv0);
                float m0 = wsum(ham0);
                float d1 = wsum(qv1 * kv1);
                float n1 = wsum(qv1 * qv1);
                float m1 = wsum(ham1);
                if (lane == 0) {
                    int s0 = (i * 2 + 0) * 3, s1 = (i * 2 + 1) * 3;
                    red[(s0 + 0) * 4 + wq] = d0;
                    red[(s0 + 1) * 4 + wq] = n0;
                    red[(s0 + 2) * 4 + wq] = m0;
                    red[(s1 + 0) * 4 + wq] = d1;
                    red[(s1 + 1) * 4 + wq] = n1;
                    red[(s1 + 2) * 4 + wq] = m1;
                }
            }
            __syncthreads();
            if (t < 8) {
                int i = t >> 1, tok = t & 1;
                int h = hg * 4 + i;
                int bb = b0 + tok;
                int base = (i * 2 + tok) * 3;
                float dot = red[(base + 0) * 4] + red[(base + 0) * 4 + 1] +
                            red[(base + 0) * 4 + 2] + red[(base + 0) * 4 + 3];
                float qn  = red[(base + 1) * 4] + red[(base + 1) * 4 + 1] +
                            red[(base + 1) * 4 + 2] + red[(base + 1) * 4 + 3];
                float hm  = red[(base + 2) * 4] + red[(base + 2) * 4 + 1] +
                            red[(base + 2) * 4 + 2] + red[(base + 2) * 4 + 3];
                out[(size_t)bb * NH + h] = dot * inv_sqrt_d;
                float hw = (1.f - hm * (1.f / 128.f)) *
                           sqrtf(qn * kn[tok * 8 + (h >> 2)]) * inv_sqrt_d;
                out[(size_t)B_TOK * NH + (size_t)bb * NH + h] = hw;
            }
            __syncthreads();
        }
    }
}

// ---------------- launch ----------------
extern "C" void kernel_launch(void* const* d_in, const int* in_sizes, int n_in,
                              void* d_out, int out_size) {
    const float* hidden = (const float*)d_in[0];
    const float* proj_w = (const float*)d_in[1];
    const float* proj_b = (const float*)d_in[2];
    const float* hash_w = (const float*)d_in[3];
    float* out = (float*)d_out;

    cudaFuncSetAttribute(gemm_f16_kernel,
                         cudaFuncAttributeMaxDynamicSharedMemorySize, SMEM_BYTES);
    cudaFuncSetAttribute(hash_gemm_kernel,
                         cudaFuncAttributeMaxDynamicSharedMemorySize, HSMEM_BYTES);
    cudaFuncSetAttribute(stage2_kernel,
                         cudaFuncAttributeMaxDynamicSharedMemorySize, S2_SMEM);

    convert_all<<<WBLK + ABLK + BBLK, 256>>>(hidden, proj_w, hash_w);
    gemm_f16_kernel<<<dim3(NC / BN, B_TOK / BM), NT, SMEM_BYTES>>>(proj_b);
    hash_gemm_kernel<<<(B_TOK * NHEADS) / 128, 256, HSMEM_BYTES>>>();
    stage2_kernel<<<B_TOK / G2, 128, S2_SMEM>>>(out);
}

// round 14
// speedup vs baseline: 3.3710x; 1.0363x over previous
#include <cuda_runtime.h>
#include <cuda_fp16.h>
#include <cstdint>

// ---------------- problem constants ----------------
#define B_TOK 8192
#define HID   4096
#define NH    32
#define NKV   8
#define HD    128
#define RBIT  128
#define QKV_C 6144
#define NC    5120   // (NH+NKV)*HD  -- v slice of proj_w unused
#define NHEADS 40    // 32 q + 8 k head-vectors per token

// ---------------- device scratch ----------------
__device__ __half g_A16[(size_t)B_TOK * HID];
__device__ __half g_B16[(size_t)HID * NC];          // [K][N]
__device__ __half g_Chalf[(size_t)B_TOK * NC];      // fp16 C (+bias)
__device__ __half g_Whi[RBIT * RBIT];               // hash_w hi [d][bit]
__device__ __half g_Wlo[RBIT * RBIT];               // hash_w lo
__device__ __half g_codes[(size_t)B_TOK * NHEADS * RBIT];  // tanh codes

// ---------------- fused convert kernel: W | A | B ----------------
#define WBLK 64
#define ABLK 2048
#define BBLK 1280
__global__ void __launch_bounds__(256) convert_all(const float* __restrict__ x,
                                                   const float* __restrict__ w,
                                                   const float* __restrict__ hw) {
    const int b = blockIdx.x;
    const int t = threadIdx.x;
    if (b < WBLK) {                       // hash_w split hi/lo (16384 elems)
        int i = b * 256 + t;
        float v = hw[i];
        __half h = __float2half_rn(v);
        g_Whi[i] = h;
        g_Wlo[i] = __float2half_rn(v - __half2float(h));
    } else if (b < WBLK + ABLK) {         // hidden -> fp16
        size_t base = (size_t)(b - WBLK) * 256 + t;
        __half2* dst = (__half2*)g_A16;
#pragma unroll 4
        for (int it = 0; it < 16; it++) {
            size_t i = base + (size_t)it * (ABLK * 256);
            float4 v = ((const float4*)x)[i];
            dst[2 * i]     = __floats2half2_rn(v.x, v.y);
            dst[2 * i + 1] = __floats2half2_rn(v.z, v.w);
        }
    } else {                              // proj_w[:, :NC] -> fp16
        size_t base = (size_t)(b - WBLK - ABLK) * 256 + t;
        __half2* dst = (__half2*)g_B16;
#pragma unroll 4
        for (int it = 0; it < 16; it++) {
            size_t i = base + (size_t)it * (BBLK * 256);
            size_t e = i * 4;
            size_t k = e / NC;
            size_t c = e - k * NC;
            float4 v = *(const float4*)(w + k * QKV_C + c);
            dst[2 * i]     = __floats2half2_rn(v.x, v.y);
            dst[2 * i + 1] = __floats2half2_rn(v.z, v.w);
        }
    }
}

// ---------------- GEMM helpers ----------------
__device__ __forceinline__ void cp16(void* smem, const void* gmem) {
    uint32_t s = (uint32_t)__cvta_generic_to_shared(smem);
    asm volatile("cp.async.cg.shared.global [%0], [%1], 16;\n" :: "r"(s), "l"(gmem) : "memory");
}
__device__ __forceinline__ void ldm_x4(uint32_t* r, const void* p) {
    uint32_t a = (uint32_t)__cvta_generic_to_shared(p);
    asm volatile("ldmatrix.sync.aligned.m8n8.x4.shared.b16 {%0,%1,%2,%3}, [%4];\n"
        : "=r"(r[0]), "=r"(r[1]), "=r"(r[2]), "=r"(r[3]) : "r"(a));
}
__device__ __forceinline__ void ldm_x4_t(uint32_t* r, const void* p) {
    uint32_t a = (uint32_t)__cvta_generic_to_shared(p);
    asm volatile("ldmatrix.sync.aligned.m8n8.x4.trans.shared.b16 {%0,%1,%2,%3}, [%4];\n"
        : "=r"(r[0]), "=r"(r[1]), "=r"(r[2]), "=r"(r[3]) : "r"(a));
}
__device__ __forceinline__ void mma_f16(float* d, const uint32_t* a, const uint32_t* b) {
    asm volatile("mma.sync.aligned.m16n8k16.row.col.f32.f16.f16.f32 "
        "{%0,%1,%2,%3}, {%4,%5,%6,%7}, {%8,%9}, {%0,%1,%2,%3};\n"
        : "+f"(d[0]), "+f"(d[1]), "+f"(d[2]), "+f"(d[3])
        : "r"(a[0]), "r"(a[1]), "r"(a[2]), "r"(a[3]), "r"(b[0]), "r"(b[1]));
}
__device__ __forceinline__ float ftanh(float x) {
    float e = __expf(2.f * x);
    return 1.f - 2.f / (e + 1.f);
}

// ---------------- GEMM: Chalf[8192,5120] = A16 * B16 + bias ----------------
#define BM 128
#define BN 128
#define BK 64
#define NT 128
#define STAGES 3
#define LDA_H 72            // 64 + 8 pad
#define LDB_H 136           // 128 + 8 pad
#define A_BYTES (BM * LDA_H * 2)            // 18432
#define B_BYTES (BK * LDB_H * 2)            // 17408
#define STAGE_BYTES (A_BYTES + B_BYTES)     // 35840
#define SMEM_BYTES (STAGES * STAGE_BYTES)   // 107520 -> 2 CTAs/SM

extern __shared__ __align__(16) char smem_raw[];

__global__ void __launch_bounds__(NT, 2) gemm_f16_kernel(const float* __restrict__ bias) {
    const int ti   = threadIdx.x;
    const int lane = ti & 31;
    const int warp = ti >> 5;
    const int wm = warp >> 1;   // 2 warps along M, 64 rows each
    const int wn = warp & 1;    // 2 warps along N, 64 cols each
    const int bn0 = blockIdx.x * BN;
    const int bm0 = blockIdx.y * BM;

    __shared__ float s_bias[BN];
    for (int i = ti; i < BN; i += NT) s_bias[i] = bias[bn0 + i];

    float acc[4][8][4];
#pragma unroll
    for (int mi = 0; mi < 4; mi++)
#pragma unroll
        for (int ni = 0; ni < 8; ni++)
#pragma unroll
            for (int r = 0; r < 4; r++) acc[mi][ni][r] = 0.f;

    auto load_stage = [&](int st, int kt) {
        char* base = smem_raw + st * STAGE_BYTES;
        char* sA   = base;
        char* sB   = base + A_BYTES;
#pragma unroll
        for (int i = 0; i < 8; i++) {        // A: 128x64 = 1024 chunks / 128 thr
            int c = ti + NT * i;
            int r = c >> 3, cc = c & 7;
            size_t g = (size_t)(bm0 + r) * HID + (size_t)kt * BK + cc * 8;
            cp16(sA + r * (LDA_H * 2) + cc * 16, g_A16 + g);
        }
#pragma unroll
        for (int i = 0; i < 8; i++) {        // B: 64x128 = 1024 chunks / 128 thr
            int c = ti + NT * i;
            int r = c >> 4, cc = c & 15;
            size_t g = (size_t)(kt * BK + r) * NC + bn0 + cc * 8;
            cp16(sB + r * (LDB_H * 2) + cc * 16, g_B16 + g);
        }
        asm volatile("cp.async.commit_group;\n" ::: "memory");
    };

    // double-buffered fragments
    uint32_t afr[2][4][4], bfr[2][8][2];

    auto load_frag = [&](int bi, char* sA, char* sB, int kk) {
#pragma unroll
        for (int mi = 0; mi < 4; mi++) {
            int row = wm * 64 + mi * 16 + (lane & 15);
            int col = kk * 16 + (lane >> 4) * 8;
            ldm_x4(afr[bi][mi], sA + row * (LDA_H * 2) + col * 2);
        }
#pragma unroll
        for (int nj = 0; nj < 4; nj++) {
            int row = kk * 16 + (lane & 15);
            int col = wn * 64 + nj * 16 + (lane >> 4) * 8;
            ldm_x4_t(&bfr[bi][2 * nj][0], sB + row * (LDB_H * 2) + col * 2);
        }
    };

    const int KT = HID / BK;   // 64
    load_stage(0, 0);
    load_stage(1, 1);
    asm volatile("cp.async.wait_group 1;\n" ::: "memory");
    __syncthreads();
    load_frag(0, smem_raw, smem_raw + A_BYTES, 0);

    for (int kt = 0; kt < KT; kt++) {
        char* base = smem_raw + (kt % STAGES) * STAGE_BYTES;
        char* sA   = base;
        char* sB   = base + A_BYTES;

#pragma unroll
        for (int kk = 0; kk < 4; kk++) {
            const int cur = kk & 1;
            if (kk < 3) load_frag(cur ^ 1, sA, sB, kk + 1);
#pragma unroll
            for (int mi = 0; mi < 4; mi++)
#pragma unroll
                for (int ni = 0; ni < 8; ni++)
                    mma_f16(acc[mi][ni], afr[cur][mi], bfr[cur][ni]);
        }

        if (kt + 1 < KT) {
            if (kt + 2 < KT) load_stage((kt + 2) % STAGES, kt + 2);
            else asm volatile("cp.async.commit_group;\n" ::: "memory");
            asm volatile("cp.async.wait_group 1;\n" ::: "memory");
            __syncthreads();
            char* nb = smem_raw + ((kt + 1) % STAGES) * STAGE_BYTES;
            load_frag(0, nb, nb + A_BYTES, 0);
        }
    }

    // epilogue: add bias, write fp16 C only
#pragma unroll
    for (int mi = 0; mi < 4; mi++)
#pragma unroll
        for (int ni = 0; ni < 8; ni++) {
            int row = bm0 + wm * 64 + mi * 16 + (lane >> 2);
            int col = bn0 + wn * 64 + ni * 8 + (lane & 3) * 2;
            float b0 = s_bias[col - bn0], b1 = s_bias[col - bn0 + 1];
            *(__half2*)&g_Chalf[(size_t)row * NC + col] =
                __floats2half2_rn(acc[mi][ni][0] + b0, acc[mi][ni][1] + b1);
            *(__half2*)&g_Chalf[(size_t)(row + 8) * NC + col] =
                __floats2half2_rn(acc[mi][ni][2] + b0, acc[mi][ni][3] + b1);
        }
}

// ---------------- hash GEMM: codes = tanh(Chalf[B*40,128] @ (Whi+Wlo)) ----------------
#define HW_LD 136
#define HSMEM_BYTES (3 * 128 * HW_LD * 2)   // 104448

__global__ void __launch_bounds__(256, 1) hash_gemm_kernel() {
    extern __shared__ __align__(16) char hsm[];
    __half* sA  = (__half*)hsm;                    // [128][136]
    __half* sWh = sA + 128 * HW_LD;
    __half* sWl = sWh + 128 * HW_LD;
    const int ti = threadIdx.x;
    const int lane = ti & 31;
    const int warp = ti >> 5;
    const int wm = warp >> 2;   // 2 warps along M, 64 rows
    const int wn = warp & 3;    // 4 warps along N, 32 cols
    const size_t m0 = (size_t)blockIdx.x * 128;

#pragma unroll
    for (int i = 0; i < 8; i++) {
        int c = ti + 256 * i;
        int r = c >> 4, cc = c & 15;
        cp16(sA + r * HW_LD + cc * 8, g_Chalf + (m0 + r) * RBIT + cc * 8);
        cp16(sWh + r * HW_LD + cc * 8, g_Whi + r * RBIT + cc * 8);
        cp16(sWl + r * HW_LD + cc * 8, g_Wlo + r * RBIT + cc * 8);
    }
    asm volatile("cp.async.commit_group;\n" ::: "memory");
    asm volatile("cp.async.wait_group 0;\n" ::: "memory");
    __syncthreads();

    float acc[4][4][4];
#pragma unroll
    for (int mi = 0; mi < 4; mi++)
#pragma unroll
        for (int ni = 0; ni < 4; ni++)
#pragma unroll
            for (int r = 0; r < 4; r++) acc[mi][ni][r] = 0.f;

#pragma unroll
    for (int kk = 0; kk < 8; kk++) {
        uint32_t a[4][4], bh[4][2], bl[4][2];
#pragma unroll
        for (int mi = 0; mi < 4; mi++) {
            int row = wm * 64 + mi * 16 + (lane & 15);
            int col = kk * 16 + (lane >> 4) * 8;
            ldm_x4(a[mi], sA + row * HW_LD + col);
        }
#pragma unroll
        for (int nj = 0; nj < 2; nj++) {
            int row = kk * 16 + (lane & 15);
            int col = wn * 32 + nj * 16 + (lane >> 4) * 8;
            ldm_x4_t(&bh[2 * nj][0], sWh + row * HW_LD + col);
            ldm_x4_t(&bl[2 * nj][0], sWl + row * HW_LD + col);
        }
#pragma unroll
        for (int mi = 0; mi < 4; mi++)
#pragma unroll
            for (int ni = 0; ni < 4; ni++) {
                mma_f16(acc[mi][ni], a[mi], bh[ni]);
                mma_f16(acc[mi][ni], a[mi], bl[ni]);
            }
    }

#pragma unroll
    for (int mi = 0; mi < 4; mi++)
#pragma unroll
        for (int ni = 0; ni < 4; ni++) {
            size_t row = m0 + wm * 64 + mi * 16 + (lane >> 2);
            int col = wn * 32 + ni * 8 + (lane & 3) * 2;
            *(__half2*)&g_codes[row * RBIT + col] =
                __floats2half2_rn(ftanh(acc[mi][ni][0]), ftanh(acc[mi][ni][1]));
            *(__half2*)&g_codes[(row + 8) * RBIT + col] =
                __floats2half2_rn(ftanh(acc[mi][ni][2]), ftanh(acc[mi][ni][3]));
        }
}

// ---------------- stage 2: warp-per-token, no block syncs ----------------
__device__ __forceinline__ float wsum(float v) {
#pragma unroll
    for (int o = 16; o > 0; o >>= 1) v += __shfl_xor_sync(0xffffffffu, v, o);
    return v;
}
__device__ __forceinline__ void h4f(const __half* p, float* f) {
    uint2 r = *(const uint2*)p;
    __half2 a = *(__half2*)&r.x, b = *(__half2*)&r.y;
    float2 fa = __half22float2(a), fb = __half22float2(b);
    f[0] = fa.x; f[1] = fa.y; f[2] = fb.x; f[3] = fb.y;
}

__global__ void __launch_bounds__(128) stage2_kernel(float* __restrict__ out) {
    const int lane = threadIdx.x & 31;
    const int warp = threadIdx.x >> 5;
    const size_t tok = (size_t)blockIdx.x * 4 + warp;
    const float inv_sqrt_d = 0.08838834764831845f;

    const __half* crow  = g_Chalf + tok * NC;
    const __half* codes = g_codes + tok * NHEADS * RBIT;

    // k vectors + k codes in registers (lane owns dims 4*lane..4*lane+3)
    float kvr[NKV][4], kcr[NKV][4], knorm[NKV];
#pragma unroll
    for (int kv = 0; kv < NKV; kv++) {
        h4f(crow + NH * HD + kv * HD + lane * 4, kvr[kv]);
        h4f(codes + (size_t)(NH + kv) * RBIT + lane * 4, kcr[kv]);
        float s = kvr[kv][0] * kvr[kv][0] + kvr[kv][1] * kvr[kv][1] +
                  kvr[kv][2] * kvr[kv][2] + kvr[kv][3] * kvr[kv][3];
        knorm[kv] = wsum(s);
    }

#pragma unroll 4
    for (int h = 0; h < NH; h++) {
        const int kv = h >> 2;
        float q[4], qc[4];
        h4f(crow + h * HD + lane * 4, q);
        h4f(codes + (size_t)h * RBIT + lane * 4, qc);
        float dot = q[0] * kvr[kv][0] + q[1] * kvr[kv][1] +
                    q[2] * kvr[kv][2] + q[3] * kvr[kv][3];
        float qn  = q[0] * q[0] + q[1] * q[1] + q[2] * q[2] + q[3] * q[3];
        float hm  = fabsf(qc[0] - kcr[kv][0]) + fabsf(qc[1] - kcr[kv][1]) +
                    fabsf(qc[2] - kcr[kv][2]) + fabsf(qc[3] - kcr[kv][3]);
        dot = wsum(dot);
        qn  = wsum(qn);
        hm  = wsum(hm);
        if (lane == 0) {
            out[tok * NH + h] = dot * inv_sqrt_d;
            out[(size_t)B_TOK * NH + tok * NH + h] =
                (1.f - hm * (1.f / 128.f)) * sqrtf(qn * knorm[kv]) * inv_sqrt_d;
        }
    }
}

// ---------------- launch ----------------
extern "C" void kernel_launch(void* const* d_in, const int* in_sizes, int n_in,
                              void* d_out, int out_size) {
    const float* hidden = (const float*)d_in[0];
    const float* proj_w = (const float*)d_in[1];
    const float* proj_b = (const float*)d_in[2];
    const float* hash_w = (const float*)d_in[3];
    float* out = (float*)d_out;

    cudaFuncSetAttribute(gemm_f16_kernel,
                         cudaFuncAttributeMaxDynamicSharedMemorySize, SMEM_BYTES);
    cudaFuncSetAttribute(hash_gemm_kernel,
                         cudaFuncAttributeMaxDynamicSharedMemorySize, HSMEM_BYTES);

    convert_all<<<WBLK + ABLK + BBLK, 256>>>(hidden, proj_w, hash_w);
    gemm_f16_kernel<<<dim3(NC / BN, B_TOK / BM), NT, SMEM_BYTES>>>(proj_b);
    hash_gemm_kernel<<<(B_TOK * NHEADS) / 128, 256, HSMEM_BYTES>>>();
    stage2_kernel<<<B_TOK / 4, 128>>>(out);
}

// round 16
// speedup vs baseline: 3.5120x; 1.0418x over previous
#include <cuda_runtime.h>
#include <cuda_fp16.h>
#include <cstdint>

// ---------------- problem constants ----------------
#define B_TOK 8192
#define HID   4096
#define NH    32
#define NKV   8
#define HD    128
#define RBIT  128
#define QKV_C 6144
#define NC    5120   // (NH+NKV)*HD  -- v slice of proj_w unused
#define NHEADS 40    // 32 q + 8 k head-vectors per token

// ---------------- device scratch ----------------
__device__ __half g_A16[(size_t)B_TOK * HID];
__device__ __half g_B16[(size_t)HID * NC];          // [K][N]
__device__ __half g_Chalf[(size_t)B_TOK * NC];      // fp16 C (+bias)
__device__ __half g_Whi[RBIT * RBIT];               // hash_w hi [d][bit]
__device__ __half g_Wlo[RBIT * RBIT];               // hash_w lo

// ---------------- fused convert kernel: W | A | B ----------------
#define WBLK 64
#define ABLK 2048
#define BBLK 1280
__global__ void __launch_bounds__(256) convert_all(const float* __restrict__ x,
                                                   const float* __restrict__ w,
                                                   const float* __restrict__ hw) {
    const int b = blockIdx.x;
    const int t = threadIdx.x;
    if (b < WBLK) {                       // hash_w split hi/lo (16384 elems)
        int i = b * 256 + t;
        float v = hw[i];
        __half h = __float2half_rn(v);
        g_Whi[i] = h;
        g_Wlo[i] = __float2half_rn(v - __half2float(h));
    } else if (b < WBLK + ABLK) {         // hidden -> fp16
        size_t base = (size_t)(b - WBLK) * 256 + t;
        __half2* dst = (__half2*)g_A16;
#pragma unroll 4
        for (int it = 0; it < 16; it++) {
            size_t i = base + (size_t)it * (ABLK * 256);
            float4 v = ((const float4*)x)[i];
            dst[2 * i]     = __floats2half2_rn(v.x, v.y);
            dst[2 * i + 1] = __floats2half2_rn(v.z, v.w);
        }
    } else {                              // proj_w[:, :NC] -> fp16
        size_t base = (size_t)(b - WBLK - ABLK) * 256 + t;
        __half2* dst = (__half2*)g_B16;
#pragma unroll 4
        for (int it = 0; it < 16; it++) {
            size_t i = base + (size_t)it * (BBLK * 256);
            size_t e = i * 4;
            size_t k = e / NC;
            size_t c = e - k * NC;
            float4 v = *(const float4*)(w + k * QKV_C + c);
            dst[2 * i]     = __floats2half2_rn(v.x, v.y);
            dst[2 * i + 1] = __floats2half2_rn(v.z, v.w);
        }
    }
}

// ---------------- GEMM helpers ----------------
__device__ __forceinline__ void cp16(void* smem, const void* gmem) {
    uint32_t s = (uint32_t)__cvta_generic_to_shared(smem);
    asm volatile("cp.async.cg.shared.global [%0], [%1], 16;\n" :: "r"(s), "l"(gmem) : "memory");
}
__device__ __forceinline__ void ldm_x4(uint32_t* r, const void* p) {
    uint32_t a = (uint32_t)__cvta_generic_to_shared(p);
    asm volatile("ldmatrix.sync.aligned.m8n8.x4.shared.b16 {%0,%1,%2,%3}, [%4];\n"
        : "=r"(r[0]), "=r"(r[1]), "=r"(r[2]), "=r"(r[3]) : "r"(a));
}
__device__ __forceinline__ void ldm_x4_t(uint32_t* r, const void* p) {
    uint32_t a = (uint32_t)__cvta_generic_to_shared(p);
    asm volatile("ldmatrix.sync.aligned.m8n8.x4.trans.shared.b16 {%0,%1,%2,%3}, [%4];\n"
        : "=r"(r[0]), "=r"(r[1]), "=r"(r[2]), "=r"(r[3]) : "r"(a));
}
__device__ __forceinline__ void mma_f16(float* d, const uint32_t* a, const uint32_t* b) {
    asm volatile("mma.sync.aligned.m16n8k16.row.col.f32.f16.f16.f32 "
        "{%0,%1,%2,%3}, {%4,%5,%6,%7}, {%8,%9}, {%0,%1,%2,%3};\n"
        : "+f"(d[0]), "+f"(d[1]), "+f"(d[2]), "+f"(d[3])
        : "r"(a[0]), "r"(a[1]), "r"(a[2]), "r"(a[3]), "r"(b[0]), "r"(b[1]));
}
__device__ __forceinline__ float ftanh(float x) {
    float e = __expf(2.f * x);
    return 1.f - 2.f / (e + 1.f);
}
__device__ __forceinline__ float wsum(float v) {
#pragma unroll
    for (int o = 16; o > 0; o >>= 1) v += __shfl_xor_sync(0xffffffffu, v, o);
    return v;
}
__device__ __forceinline__ void h4f(const __half* p, float* f) {
    uint2 r = *(const uint2*)p;
    __half2 a = *(__half2*)&r.x, b = *(__half2*)&r.y;
    float2 fa = __half22float2(a), fb = __half22float2(b);
    f[0] = fa.x; f[1] = fa.y; f[2] = fb.x; f[3] = fb.y;
}

// ---------------- GEMM: Chalf[8192,5120] = A16 * B16 + bias ----------------
#define BM 128
#define BN 128
#define BK 64
#define NT 128
#define STAGES 3
#define LDA_H 72            // 64 + 8 pad
#define LDB_H 136           // 128 + 8 pad
#define A_BYTES (BM * LDA_H * 2)            // 18432
#define B_BYTES (BK * LDB_H * 2)            // 17408
#define STAGE_BYTES (A_BYTES + B_BYTES)     // 35840
#define SMEM_BYTES (STAGES * STAGE_BYTES)   // 107520 -> 2 CTAs/SM

extern __shared__ __align__(16) char smem_raw[];

__global__ void __launch_bounds__(NT, 2) gemm_f16_kernel(const float* __restrict__ bias) {
    const int ti   = threadIdx.x;
    const int lane = ti & 31;
    const int warp = ti >> 5;
    const int wm = warp >> 1;   // 2 warps along M, 64 rows each
    const int wn = warp & 1;    // 2 warps along N, 64 cols each
    const int bn0 = blockIdx.x * BN;
    const int bm0 = blockIdx.y * BM;

    __shared__ float s_bias[BN];
    for (int i = ti; i < BN; i += NT) s_bias[i] = bias[bn0 + i];

    float acc[4][8][4];
#pragma unroll
    for (int mi = 0; mi < 4; mi++)
#pragma unroll
        for (int ni = 0; ni < 8; ni++)
#pragma unroll
            for (int r = 0; r < 4; r++) acc[mi][ni][r] = 0.f;

    auto load_stage = [&](int st, int kt) {
        char* base = smem_raw + st * STAGE_BYTES;
        char* sA   = base;
        char* sB   = base + A_BYTES;
#pragma unroll
        for (int i = 0; i < 8; i++) {
            int c = ti + NT * i;
            int r = c >> 3, cc = c & 7;
            size_t g = (size_t)(bm0 + r) * HID + (size_t)kt * BK + cc * 8;
            cp16(sA + r * (LDA_H * 2) + cc * 16, g_A16 + g);
        }
#pragma unroll
        for (int i = 0; i < 8; i++) {
            int c = ti + NT * i;
            int r = c >> 4, cc = c & 15;
            size_t g = (size_t)(kt * BK + r) * NC + bn0 + cc * 8;
            cp16(sB + r * (LDB_H * 2) + cc * 16, g_B16 + g);
        }
        asm volatile("cp.async.commit_group;\n" ::: "memory");
    };

    uint32_t afr[2][4][4], bfr[2][8][2];

    auto load_frag = [&](int bi, char* sA, char* sB, int kk) {
#pragma unroll
        for (int mi = 0; mi < 4; mi++) {
            int row = wm * 64 + mi * 16 + (lane & 15);
            int col = kk * 16 + (lane >> 4) * 8;
            ldm_x4(afr[bi][mi], sA + row * (LDA_H * 2) + col * 2);
        }
#pragma unroll
        for (int nj = 0; nj < 4; nj++) {
            int row = kk * 16 + (lane & 15);
            int col = wn * 64 + nj * 16 + (lane >> 4) * 8;
            ldm_x4_t(&bfr[bi][2 * nj][0], sB + row * (LDB_H * 2) + col * 2);
        }
    };

    const int KT = HID / BK;   // 64
    load_stage(0, 0);
    load_stage(1, 1);
    asm volatile("cp.async.wait_group 1;\n" ::: "memory");
    __syncthreads();
    load_frag(0, smem_raw, smem_raw + A_BYTES, 0);

    for (int kt = 0; kt < KT; kt++) {
        char* base = smem_raw + (kt % STAGES) * STAGE_BYTES;
        char* sA   = base;
        char* sB   = base + A_BYTES;

#pragma unroll
        for (int kk = 0; kk < 4; kk++) {
            const int cur = kk & 1;
            if (kk < 3) load_frag(cur ^ 1, sA, sB, kk + 1);
#pragma unroll
            for (int mi = 0; mi < 4; mi++)
#pragma unroll
                for (int ni = 0; ni < 8; ni++)
                    mma_f16(acc[mi][ni], afr[cur][mi], bfr[cur][ni]);
        }

        if (kt + 1 < KT) {
            if (kt + 2 < KT) load_stage((kt + 2) % STAGES, kt + 2);
            else asm volatile("cp.async.commit_group;\n" ::: "memory");
            asm volatile("cp.async.wait_group 1;\n" ::: "memory");
            __syncthreads();
            char* nb = smem_raw + ((kt + 1) % STAGES) * STAGE_BYTES;
            load_frag(0, nb, nb + A_BYTES, 0);
        }
    }

#pragma unroll
    for (int mi = 0; mi < 4; mi++)
#pragma unroll
        for (int ni = 0; ni < 8; ni++) {
            int row = bm0 + wm * 64 + mi * 16 + (lane >> 2);
            int col = bn0 + wn * 64 + ni * 8 + (lane & 3) * 2;
            float b0 = s_bias[col - bn0], b1 = s_bias[col - bn0 + 1];
            *(__half2*)&g_Chalf[(size_t)row * NC + col] =
                __floats2half2_rn(acc[mi][ni][0] + b0, acc[mi][ni][1] + b1);
            *(__half2*)&g_Chalf[(size_t)(row + 8) * NC + col] =
                __floats2half2_rn(acc[mi][ni][2] + b0, acc[mi][ni][3] + b1);
        }
}

// ---------------- fused hash + stage2: 4 tokens (160 head rows) per block ----------------
#define HW_LD 136
#define FA_ROWS 160
#define FA_SZ (FA_ROWS * HW_LD * 2)          // 43520
#define FW_SZ (128 * HW_LD * 2)              // 34816
#define FSMEM (FA_SZ + 2 * FW_SZ)            // 113152
// smem map: [0, FA_SZ)                A tile (Chalf rows, 4 tokens)
//           [FA_SZ, FA_SZ+2*FW_SZ)    Whi | Wlo  -> overlaid by codes[160][HW_LD] after MMA

__global__ void __launch_bounds__(256) fused_hash_stage2(float* __restrict__ out) {
    extern __shared__ __align__(16) char fsm[];
    __half* sA  = (__half*)fsm;                       // [160][HW_LD]
    __half* sWh = (__half*)(fsm + FA_SZ);             // [128][HW_LD]
    __half* sWl = (__half*)(fsm + FA_SZ + FW_SZ);
    __half* sCo = (__half*)(fsm + FA_SZ);             // codes overlay [160][HW_LD]

    const int ti = threadIdx.x;
    const int lane = ti & 31;
    const int warp = ti >> 5;
    const int wm = warp >> 2;   // 2 warps along M, 80 rows each
    const int wn = warp & 3;    // 4 warps along N, 32 cols each
    const size_t row0 = (size_t)blockIdx.x * FA_ROWS;
    const float inv_sqrt_d = 0.08838834764831845f;

    // ---- load A (160 rows x 128 halfs = 16 chunks/row = 2560 chunks) ----
#pragma unroll
    for (int i = 0; i < 10; i++) {
        int c = ti + 256 * i;
        int r = c >> 4, cc = c & 15;
        cp16(sA + r * HW_LD + cc * 8, g_Chalf + (row0 + r) * RBIT + cc * 8);
    }
    // ---- W: 128 rows x 16 chunks = 2048 chunks each ----
#pragma unroll
    for (int i = 0; i < 8; i++) {
        int c = ti + 256 * i;
        int r = c >> 4, cc = c & 15;
        cp16(sWh + r * HW_LD + cc * 8, g_Whi + r * RBIT + cc * 8);
        cp16(sWl + r * HW_LD + cc * 8, g_Wlo + r * RBIT + cc * 8);
    }
    asm volatile("cp.async.commit_group;\n" ::: "memory");
    asm volatile("cp.async.wait_group 0;\n" ::: "memory");
    __syncthreads();

    // ---- MMA: D[160,128] = A @ (Whi + Wlo) ----
    float acc[5][4][4];
#pragma unroll
    for (int mi = 0; mi < 5; mi++)
#pragma unroll
        for (int ni = 0; ni < 4; ni++)
#pragma unroll
            for (int r = 0; r < 4; r++) acc[mi][ni][r] = 0.f;

#pragma unroll
    for (int kk = 0; kk < 8; kk++) {
        uint32_t a[5][4], bh[4][2], bl[4][2];
#pragma unroll
        for (int mi = 0; mi < 5; mi++) {
            int row = wm * 80 + mi * 16 + (lane & 15);
            int col = kk * 16 + (lane >> 4) * 8;
            ldm_x4(a[mi], sA + row * HW_LD + col);
        }
#pragma unroll
        for (int nj = 0; nj < 2; nj++) {
            int row = kk * 16 + (lane & 15);
            int col = wn * 32 + nj * 16 + (lane >> 4) * 8;
            ldm_x4_t(&bh[2 * nj][0], sWh + row * HW_LD + col);
            ldm_x4_t(&bl[2 * nj][0], sWl + row * HW_LD + col);
        }
#pragma unroll
        for (int mi = 0; mi < 5; mi++)
#pragma unroll
            for (int ni = 0; ni < 4; ni++) {
                mma_f16(acc[mi][ni], a[mi], bh[ni]);
                mma_f16(acc[mi][ni], a[mi], bl[ni]);
            }
    }

    __syncthreads();   // all warps done reading W smem before codes overlay

    // ---- tanh -> codes smem (overlaying W region) ----
#pragma unroll
    for (int mi = 0; mi < 5; mi++)
#pragma unroll
        for (int ni = 0; ni < 4; ni++) {
            int row = wm * 80 + mi * 16 + (lane >> 2);
            int col = wn * 32 + ni * 8 + (lane & 3) * 2;
            *(__half2*)&sCo[row * HW_LD + col] =
                __floats2half2_rn(ftanh(acc[mi][ni][0]), ftanh(acc[mi][ni][1]));
            *(__half2*)&sCo[(row + 8) * HW_LD + col] =
                __floats2half2_rn(ftanh(acc[mi][ni][2]), ftanh(acc[mi][ni][3]));
        }
    __syncthreads();   // codes visible to all warps

    // ---- reductions: warp -> (token = warp>>1, heads (warp&1)*16 .. +15) ----
    const int twp  = warp >> 1;            // token within block 0..3
    const int hb   = (warp & 1) * 16;      // head base
    const int trow = twp * 40;             // token's row base in sA / sCo
    const size_t tok = (size_t)blockIdx.x * 4 + twp;

    // k vectors, k codes, k norms for kv = hb/4 .. hb/4+3
    const int kvb = hb >> 2;
    float kvr[4][4], kcr[4][4], knorm[4];
#pragma unroll
    for (int j = 0; j < 4; j++) {
        int kv = kvb + j;
        h4f(sA  + (trow + NH + kv) * HW_LD + lane * 4, kvr[j]);
        h4f(sCo + (trow + NH + kv) * HW_LD + lane * 4, kcr[j]);
        float s = kvr[j][0] * kvr[j][0] + kvr[j][1] * kvr[j][1] +
                  kvr[j][2] * kvr[j][2] + kvr[j][3] * kvr[j][3];
        knorm[j] = wsum(s);
    }

#pragma unroll 4
    for (int i = 0; i < 16; i++) {
        const int h = hb + i;
        const int j = i >> 2;              // kv index within this warp's 4
        float q[4], qc[4];
        h4f(sA  + (trow + h) * HW_LD + lane * 4, q);
        h4f(sCo + (trow + h) * HW_LD + lane * 4, qc);
        float dot = q[0] * kvr[j][0] + q[1] * kvr[j][1] +
                    q[2] * kvr[j][2] + q[3] * kvr[j][3];
        float qn  = q[0] * q[0] + q[1] * q[1] + q[2] * q[2] + q[3] * q[3];
        float hm  = fabsf(qc[0] - kcr[j][0]) + fabsf(qc[1] - kcr[j][1]) +
                    fabsf(qc[2] - kcr[j][2]) + fabsf(qc[3] - kcr[j][3]);
        dot = wsum(dot);
        qn  = wsum(qn);
        hm  = wsum(hm);
        if (lane == 0) {
            out[tok * NH + h] = dot * inv_sqrt_d;
            out[(size_t)B_TOK * NH + tok * NH + h] =
                (1.f - hm * (1.f / 128.f)) * sqrtf(qn * knorm[j]) * inv_sqrt_d;
        }
    }
}

// ---------------- launch ----------------
extern "C" void kernel_launch(void* const* d_in, const int* in_sizes, int n_in,
                              void* d_out, int out_size) {
    const float* hidden = (const float*)d_in[0];
    const float* proj_w = (const float*)d_in[1];
    const float* proj_b = (const float*)d_in[2];
    const float* hash_w = (const float*)d_in[3];
    float* out = (float*)d_out;

    cudaFuncSetAttribute(gemm_f16_kernel,
                         cudaFuncAttributeMaxDynamicSharedMemorySize, SMEM_BYTES);
    cudaFuncSetAttribute(fused_hash_stage2,
                         cudaFuncAttributeMaxDynamicSharedMemorySize, FSMEM);

    convert_all<<<WBLK + ABLK + BBLK, 256>>>(hidden, proj_w, hash_w);
    gemm_f16_kernel<<<dim3(NC / BN, B_TOK / BM), NT, SMEM_BYTES>>>(proj_b);
    fused_hash_stage2<<<B_TOK / 4, 256, FSMEM>>>(out);
}

// round 17
// speedup vs baseline: 3.5919x; 1.0228x over previous
#include <cuda_runtime.h>
#include <cuda_fp16.h>
#include <cstdint>

// ---------------- problem constants ----------------
#define B_TOK 8192
#define HID   4096
#define NH    32
#define NKV   8
#define HD    128
#define RBIT  128
#define QKV_C 6144
#define NC    5120   // (NH+NKV)*HD  -- v slice of proj_w unused
#define NHEADS 40    // 32 q + 8 k head-vectors per token

// ---------------- device scratch ----------------
__device__ __half g_A16[(size_t)B_TOK * HID];
__device__ __half g_B16[(size_t)HID * NC];          // [K][N]
__device__ __half g_Chalf[(size_t)B_TOK * NC];      // fp16 C (+bias)
__device__ __half g_Whi[RBIT * RBIT];               // hash_w fp16 [d][bit]

// ---------------- fused convert kernel: W | A | B ----------------
#define WBLK 64
#define ABLK 2048
#define BBLK 1280
__global__ void __launch_bounds__(256) convert_all(const float* __restrict__ x,
                                                   const float* __restrict__ w,
                                                   const float* __restrict__ hw) {
    const int b = blockIdx.x;
    const int t = threadIdx.x;
    if (b < WBLK) {                       // hash_w -> fp16 (16384 elems)
        int i = b * 256 + t;
        g_Whi[i] = __float2half_rn(hw[i]);
    } else if (b < WBLK + ABLK) {         // hidden -> fp16
        size_t base = (size_t)(b - WBLK) * 256 + t;
        __half2* dst = (__half2*)g_A16;
#pragma unroll 4
        for (int it = 0; it < 16; it++) {
            size_t i = base + (size_t)it * (ABLK * 256);
            float4 v = ((const float4*)x)[i];
            dst[2 * i]     = __floats2half2_rn(v.x, v.y);
            dst[2 * i + 1] = __floats2half2_rn(v.z, v.w);
        }
    } else {                              // proj_w[:, :NC] -> fp16
        size_t base = (size_t)(b - WBLK - ABLK) * 256 + t;
        __half2* dst = (__half2*)g_B16;
#pragma unroll 4
        for (int it = 0; it < 16; it++) {
            size_t i = base + (size_t)it * (BBLK * 256);
            size_t e = i * 4;
            size_t k = e / NC;
            size_t c = e - k * NC;
            float4 v = *(const float4*)(w + k * QKV_C + c);
            dst[2 * i]     = __floats2half2_rn(v.x, v.y);
            dst[2 * i + 1] = __floats2half2_rn(v.z, v.w);
        }
    }
}

// ---------------- GEMM helpers ----------------
__device__ __forceinline__ void cp16(void* smem, const void* gmem) {
    uint32_t s = (uint32_t)__cvta_generic_to_shared(smem);
    asm volatile("cp.async.cg.shared.global [%0], [%1], 16;\n" :: "r"(s), "l"(gmem) : "memory");
}
__device__ __forceinline__ void ldm_x4(uint32_t* r, const void* p) {
    uint32_t a = (uint32_t)__cvta_generic_to_shared(p);
    asm volatile("ldmatrix.sync.aligned.m8n8.x4.shared.b16 {%0,%1,%2,%3}, [%4];\n"
        : "=r"(r[0]), "=r"(r[1]), "=r"(r[2]), "=r"(r[3]) : "r"(a));
}
__device__ __forceinline__ void ldm_x4_t(uint32_t* r, const void* p) {
    uint32_t a = (uint32_t)__cvta_generic_to_shared(p);
    asm volatile("ldmatrix.sync.aligned.m8n8.x4.trans.shared.b16 {%0,%1,%2,%3}, [%4];\n"
        : "=r"(r[0]), "=r"(r[1]), "=r"(r[2]), "=r"(r[3]) : "r"(a));
}
__device__ __forceinline__ void mma_f16(float* d, const uint32_t* a, const uint32_t* b) {
    asm volatile("mma.sync.aligned.m16n8k16.row.col.f32.f16.f16.f32 "
        "{%0,%1,%2,%3}, {%4,%5,%6,%7}, {%8,%9}, {%0,%1,%2,%3};\n"
        : "+f"(d[0]), "+f"(d[1]), "+f"(d[2]), "+f"(d[3])
        : "r"(a[0]), "r"(a[1]), "r"(a[2]), "r"(a[3]), "r"(b[0]), "r"(b[1]));
}
__device__ __forceinline__ float ftanh(float x) {
    float e = __expf(2.f * x);
    return 1.f - 2.f / (e + 1.f);
}
__device__ __forceinline__ float wsum(float v) {
#pragma unroll
    for (int o = 16; o > 0; o >>= 1) v += __shfl_xor_sync(0xffffffffu, v, o);
    return v;
}
__device__ __forceinline__ void h4f(const __half* p, float* f) {
    uint2 r = *(const uint2*)p;
    __half2 a = *(__half2*)&r.x, b = *(__half2*)&r.y;
    float2 fa = __half22float2(a), fb = __half22float2(b);
    f[0] = fa.x; f[1] = fa.y; f[2] = fb.x; f[3] = fb.y;
}

// ---------------- GEMM: Chalf[8192,5120] = A16 * B16 + bias ----------------
#define BM 128
#define BN 128
#define BK 64
#define NT 128
#define STAGES 3
#define LDA_H 72            // 64 + 8 pad
#define LDB_H 136           // 128 + 8 pad
#define A_BYTES (BM * LDA_H * 2)            // 18432
#define B_BYTES (BK * LDB_H * 2)            // 17408
#define STAGE_BYTES (A_BYTES + B_BYTES)     // 35840
#define SMEM_BYTES (STAGES * STAGE_BYTES)   // 107520 -> 2 CTAs/SM

extern __shared__ __align__(16) char smem_raw[];

__global__ void __launch_bounds__(NT, 2) gemm_f16_kernel(const float* __restrict__ bias) {
    const int ti   = threadIdx.x;
    const int lane = ti & 31;
    const int warp = ti >> 5;
    const int wm = warp >> 1;   // 2 warps along M, 64 rows each
    const int wn = warp & 1;    // 2 warps along N, 64 cols each
    const int bn0 = blockIdx.x * BN;
    const int bm0 = blockIdx.y * BM;

    __shared__ float s_bias[BN];
    for (int i = ti; i < BN; i += NT) s_bias[i] = bias[bn0 + i];

    float acc[4][8][4];
#pragma unroll
    for (int mi = 0; mi < 4; mi++)
#pragma unroll
        for (int ni = 0; ni < 8; ni++)
#pragma unroll
            for (int r = 0; r < 4; r++) acc[mi][ni][r] = 0.f;

    auto load_stage = [&](int st, int kt) {
        char* base = smem_raw + st * STAGE_BYTES;
        char* sA   = base;
        char* sB   = base + A_BYTES;
#pragma unroll
        for (int i = 0; i < 8; i++) {
            int c = ti + NT * i;
            int r = c >> 3, cc = c & 7;
            size_t g = (size_t)(bm0 + r) * HID + (size_t)kt * BK + cc * 8;
            cp16(sA + r * (LDA_H * 2) + cc * 16, g_A16 + g);
        }
#pragma unroll
        for (int i = 0; i < 8; i++) {
            int c = ti + NT * i;
            int r = c >> 4, cc = c & 15;
            size_t g = (size_t)(kt * BK + r) * NC + bn0 + cc * 8;
            cp16(sB + r * (LDB_H * 2) + cc * 16, g_B16 + g);
        }
        asm volatile("cp.async.commit_group;\n" ::: "memory");
    };

    uint32_t afr[2][4][4], bfr[2][8][2];

    auto load_frag = [&](int bi, char* sA, char* sB, int kk) {
#pragma unroll
        for (int mi = 0; mi < 4; mi++) {
            int row = wm * 64 + mi * 16 + (lane & 15);
            int col = kk * 16 + (lane >> 4) * 8;
            ldm_x4(afr[bi][mi], sA + row * (LDA_H * 2) + col * 2);
        }
#pragma unroll
        for (int nj = 0; nj < 4; nj++) {
            int row = kk * 16 + (lane & 15);
            int col = wn * 64 + nj * 16 + (lane >> 4) * 8;
            ldm_x4_t(&bfr[bi][2 * nj][0], sB + row * (LDB_H * 2) + col * 2);
        }
    };

    const int KT = HID / BK;   // 64
    load_stage(0, 0);
    load_stage(1, 1);
    asm volatile("cp.async.wait_group 1;\n" ::: "memory");
    __syncthreads();
    load_frag(0, smem_raw, smem_raw + A_BYTES, 0);

    for (int kt = 0; kt < KT; kt++) {
        char* base = smem_raw + (kt % STAGES) * STAGE_BYTES;
        char* sA   = base;
        char* sB   = base + A_BYTES;

#pragma unroll
        for (int kk = 0; kk < 4; kk++) {
            const int cur = kk & 1;
            if (kk < 3) load_frag(cur ^ 1, sA, sB, kk + 1);
#pragma unroll
            for (int mi = 0; mi < 4; mi++)
#pragma unroll
                for (int ni = 0; ni < 8; ni++)
                    mma_f16(acc[mi][ni], afr[cur][mi], bfr[cur][ni]);
        }

        if (kt + 1 < KT) {
            if (kt + 2 < KT) load_stage((kt + 2) % STAGES, kt + 2);
            else asm volatile("cp.async.commit_group;\n" ::: "memory");
            asm volatile("cp.async.wait_group 1;\n" ::: "memory");
            __syncthreads();
            char* nb = smem_raw + ((kt + 1) % STAGES) * STAGE_BYTES;
            load_frag(0, nb, nb + A_BYTES, 0);
        }
    }

#pragma unroll
    for (int mi = 0; mi < 4; mi++)
#pragma unroll
        for (int ni = 0; ni < 8; ni++) {
            int row = bm0 + wm * 64 + mi * 16 + (lane >> 2);
            int col = bn0 + wn * 64 + ni * 8 + (lane & 3) * 2;
            float b0 = s_bias[col - bn0], b1 = s_bias[col - bn0 + 1];
            *(__half2*)&g_Chalf[(size_t)row * NC + col] =
                __floats2half2_rn(acc[mi][ni][0] + b0, acc[mi][ni][1] + b1);
            *(__half2*)&g_Chalf[(size_t)(row + 8) * NC + col] =
                __floats2half2_rn(acc[mi][ni][2] + b0, acc[mi][ni][3] + b1);
        }
}

// ---------------- fused hash + stage2: 4 tokens (160 head rows) per block ----------------
#define HW_LD 136
#define FA_ROWS 160
#define FA_SZ (FA_ROWS * HW_LD * 2)          // 43520
#define FW_SZ (128 * HW_LD * 2)              // 34816
#define FSMEM (FA_SZ + 2 * FW_SZ)            // 113152
// smem map: [0, FA_SZ)                A tile (Chalf rows, 4 tokens)
//           [FA_SZ, FA_SZ+FW_SZ)      W (fp16 single)
//           [FA_SZ, FA_SZ+2*FW_SZ)    codes overlay [160][HW_LD] after MMA
//           (overlay starts at W base; W region + scratch region = 69.6KB > 43.5KB codes)

__global__ void __launch_bounds__(256) fused_hash_stage2(float* __restrict__ out) {
    extern __shared__ __align__(16) char fsm[];
    __half* sA  = (__half*)fsm;                       // [160][HW_LD]
    __half* sW  = (__half*)(fsm + FA_SZ);             // [128][HW_LD]
    __half* sCo = (__half*)(fsm + FA_SZ);             // codes overlay [160][HW_LD]

    const int ti = threadIdx.x;
    const int lane = ti & 31;
    const int warp = ti >> 5;
    const int wm = warp >> 2;   // 2 warps along M, 80 rows each
    const int wn = warp & 3;    // 4 warps along N, 32 cols each
    const size_t row0 = (size_t)blockIdx.x * FA_ROWS;
    const float inv_sqrt_d = 0.08838834764831845f;

    // ---- load A (160 rows x 16 chunks = 2560 chunks) ----
#pragma unroll
    for (int i = 0; i < 10; i++) {
        int c = ti + 256 * i;
        int r = c >> 4, cc = c & 15;
        cp16(sA + r * HW_LD + cc * 8, g_Chalf + (row0 + r) * RBIT + cc * 8);
    }
    // ---- W: 128 rows x 16 chunks = 2048 chunks ----
#pragma unroll
    for (int i = 0; i < 8; i++) {
        int c = ti + 256 * i;
        int r = c >> 4, cc = c & 15;
        cp16(sW + r * HW_LD + cc * 8, g_Whi + r * RBIT + cc * 8);
    }
    asm volatile("cp.async.commit_group;\n" ::: "memory");
    asm volatile("cp.async.wait_group 0;\n" ::: "memory");
    __syncthreads();

    // ---- MMA: D[160,128] = A @ W ----
    float acc[5][4][4];
#pragma unroll
    for (int mi = 0; mi < 5; mi++)
#pragma unroll
        for (int ni = 0; ni < 4; ni++)
#pragma unroll
            for (int r = 0; r < 4; r++) acc[mi][ni][r] = 0.f;

#pragma unroll
    for (int kk = 0; kk < 8; kk++) {
        uint32_t a[5][4], bh[4][2];
#pragma unroll
        for (int mi = 0; mi < 5; mi++) {
            int row = wm * 80 + mi * 16 + (lane & 15);
            int col = kk * 16 + (lane >> 4) * 8;
            ldm_x4(a[mi], sA + row * HW_LD + col);
        }
#pragma unroll
        for (int nj = 0; nj < 2; nj++) {
            int row = kk * 16 + (lane & 15);
            int col = wn * 32 + nj * 16 + (lane >> 4) * 8;
            ldm_x4_t(&bh[2 * nj][0], sW + row * HW_LD + col);
        }
#pragma unroll
        for (int mi = 0; mi < 5; mi++)
#pragma unroll
            for (int ni = 0; ni < 4; ni++)
                mma_f16(acc[mi][ni], a[mi], bh[ni]);
    }

    __syncthreads();   // all warps done reading W smem before codes overlay

    // ---- tanh -> codes smem (overlaying W region) ----
#pragma unroll
    for (int mi = 0; mi < 5; mi++)
#pragma unroll
        for (int ni = 0; ni < 4; ni++) {
            int row = wm * 80 + mi * 16 + (lane >> 2);
            int col = wn * 32 + ni * 8 + (lane & 3) * 2;
            *(__half2*)&sCo[row * HW_LD + col] =
                __floats2half2_rn(ftanh(acc[mi][ni][0]), ftanh(acc[mi][ni][1]));
            *(__half2*)&sCo[(row + 8) * HW_LD + col] =
                __floats2half2_rn(ftanh(acc[mi][ni][2]), ftanh(acc[mi][ni][3]));
        }
    __syncthreads();   // codes visible to all warps

    // ---- reductions: warp -> (token = warp>>1, heads (warp&1)*16 .. +15) ----
    const int twp  = warp >> 1;            // token within block 0..3
    const int hb   = (warp & 1) * 16;      // head base
    const int trow = twp * 40;             // token's row base in sA / sCo
    const size_t tok = (size_t)blockIdx.x * 4 + twp;

    const int kvb = hb >> 2;
    float kvr[4][4], kcr[4][4], knorm[4];
#pragma unroll
    for (int j = 0; j < 4; j++) {
        int kv = kvb + j;
        h4f(sA  + (trow + NH + kv) * HW_LD + lane * 4, kvr[j]);
        h4f(sCo + (trow + NH + kv) * HW_LD + lane * 4, kcr[j]);
        float s = kvr[j][0] * kvr[j][0] + kvr[j][1] * kvr[j][1] +
                  kvr[j][2] * kvr[j][2] + kvr[j][3] * kvr[j][3];
        knorm[j] = wsum(s);
    }

#pragma unroll 4
    for (int i = 0; i < 16; i++) {
        const int h = hb + i;
        const int j = i >> 2;              // kv index within this warp's 4
        float q[4], qc[4];
        h4f(sA  + (trow + h) * HW_LD + lane * 4, q);
        h4f(sCo + (trow + h) * HW_LD + lane * 4, qc);
        float dot = q[0] * kvr[j][0] + q[1] * kvr[j][1] +
                    q[2] * kvr[j][2] + q[3] * kvr[j][3];
        float qn  = q[0] * q[0] + q[1] * q[1] + q[2] * q[2] + q[3] * q[3];
        float hm  = fabsf(qc[0] - kcr[j][0]) + fabsf(qc[1] - kcr[j][1]) +
                    fabsf(qc[2] - kcr[j][2]) + fabsf(qc[3] - kcr[j][3]);
        dot = wsum(dot);
        qn  = wsum(qn);
        hm  = wsum(hm);
        if (lane == 0) {
            out[tok * NH + h] = dot * inv_sqrt_d;
            out[(size_t)B_TOK * NH + tok * NH + h] =
                (1.f - hm * (1.f / 128.f)) * sqrtf(qn * knorm[j]) * inv_sqrt_d;
        }
    }
}

// ---------------- launch ----------------
extern "C" void kernel_launch(void* const* d_in, const int* in_sizes, int n_in,
                              void* d_out, int out_size) {
    const float* hidden = (const float*)d_in[0];
    const float* proj_w = (const float*)d_in[1];
    const float* proj_b = (const float*)d_in[2];
    const float* hash_w = (const float*)d_in[3];
    float* out = (float*)d_out;

    cudaFuncSetAttribute(gemm_f16_kernel,
                         cudaFuncAttributeMaxDynamicSharedMemorySize, SMEM_BYTES);
    cudaFuncSetAttribute(fused_hash_stage2,
                         cudaFuncAttributeMaxDynamicSharedMemorySize, FSMEM);

    convert_all<<<WBLK + ABLK + BBLK, 256>>>(hidden, proj_w, hash_w);
    gemm_f16_kernel<<<dim3(NC / BN, B_TOK / BM), NT, SMEM_BYTES>>>(proj_b);
    fused_hash_stage2<<<B_TOK / 4, 256, FSMEM>>>(out);
}